// round 5
// baseline (speedup 1.0000x reference)
#include <cuda_runtime.h>
#include <cuda_bf16.h>
#include <cstdint>
#include <math.h>

// ---------------- problem constants ----------------
#define BB 4
#define LL 2048
#define DD 2048
#define RR 2048
#define DHH 512
#define MM (BB * LL)          // 8192
#define NCH 16
#define CHL (LL / NCH)        // 128

// ---------------- GEMM tiling ----------------
// CTA tile 256x128, 8 warps (4x2), warp tile 64x64, BK=32 bf16 (64B rows)
#define TBM 256
#define TBN 128
#define TBK 32
#define A_TILE 16384          // 256*64B
#define B_TILE 8192           // 128*64B
#define STAGE_BYTES (2 * A_TILE + 2 * B_TILE)   // Ahi, Alo, Bhi, Blo = 49152
#define NSTAGE 3
#define SMEM_TOTAL (NSTAGE * STAGE_BYTES)       // 147456

// ---------------- device scratch ----------------
__device__ __nv_bfloat16 g_xhi[(size_t)MM * DD], g_xlo[(size_t)MM * DD];
__device__ __nv_bfloat16 g_wuhi[(size_t)RR * DD], g_wulo[(size_t)RR * DD];
__device__ __nv_bfloat16 g_wvhi[(size_t)RR * DD], g_wvlo[(size_t)RR * DD];
__device__ __nv_bfloat16 g_wg1hi[(size_t)DHH * DD], g_wg1lo[(size_t)DHH * DD];
__device__ __nv_bfloat16 g_wg2hi[(size_t)RR * DHH], g_wg2lo[(size_t)RR * DHH];
__device__ __nv_bfloat16 g_hhi[(size_t)MM * DHH], g_hlo[(size_t)MM * DHH];
__device__ __nv_bfloat16 g_ghi[(size_t)MM * RR], g_glo[(size_t)MM * RR];
__device__ float g_u[(size_t)MM * RR];
__device__ float g_v[(size_t)MM * RR];
__device__ float g_part[(size_t)BB * NCH * RR];

// ---------------- PTX helpers (arch-agnostic only) ----------------
__device__ __forceinline__ uint32_t smem_u32(const void* p) {
    uint32_t a;
    asm("{ .reg .u64 t; cvta.to.shared.u64 t, %1; cvt.u32.u64 %0, t; }" : "=r"(a) : "l"(p));
    return a;
}
__device__ __forceinline__ void cp16(uint32_t dst, const void* src) {
    asm volatile("cp.async.cg.shared.global [%0], [%1], 16;" :: "r"(dst), "l"(src));
}
#define CP_COMMIT() asm volatile("cp.async.commit_group;" ::: "memory")
#define CP_WAIT(n)  asm volatile("cp.async.wait_group %0;" :: "n"(n) : "memory")

#define LDSM4(r, addr) \
    asm volatile("ldmatrix.sync.aligned.m8n8.x4.shared.b16 {%0,%1,%2,%3}, [%4];" \
        : "=r"((r)[0]), "=r"((r)[1]), "=r"((r)[2]), "=r"((r)[3]) : "r"(addr))

__device__ __forceinline__ void mma16816(float* c, const uint32_t* a, uint32_t b0, uint32_t b1) {
    asm volatile(
        "mma.sync.aligned.m16n8k16.row.col.f32.bf16.bf16.f32 "
        "{%0,%1,%2,%3}, {%4,%5,%6,%7}, {%8,%9}, {%0,%1,%2,%3};"
        : "+f"(c[0]), "+f"(c[1]), "+f"(c[2]), "+f"(c[3])
        : "r"(a[0]), "r"(a[1]), "r"(a[2]), "r"(a[3]), "r"(b0), "r"(b1));
}

// swizzled smem offset for (row, 16B-chunk c) in a 64B-row tile.
// f(r) distinguishes rows 8 apart (ldmatrix phase partners) AND rows 2 apart,
// so every ldmatrix.x4 phase hits 4 distinct 16B bank groups:
//   groups = 4*(r&1) + (c ^ f(r)),  f(r)^f(r+8)=2, f(r)^f(r+2)... c-bit variation
__device__ __forceinline__ uint32_t swz(int r, int c) {
    int f = ((r >> 1) & 1) | (((r >> 3) & 1) << 1);
    return (uint32_t)(r * 64 + ((c ^ f) << 4));
}

// load one chunk's 4 tiles into a stage
__device__ __forceinline__ void load_ab(uint32_t st,
                                        const __nv_bfloat16* __restrict__ Ahi,
                                        const __nv_bfloat16* __restrict__ Alo,
                                        const __nv_bfloat16* __restrict__ Bhi,
                                        const __nv_bfloat16* __restrict__ Blo,
                                        int K, int row0, int col0, int k0, int tid) {
#pragma unroll
    for (int i = 0; i < 4; i++) {                 // A: 256 rows x 4 chunks
        int id = tid + i * 256;
        int r = id >> 2, c = id & 3;
        uint32_t dst = st + swz(r, c);
        size_t srcoff = (size_t)(row0 + r) * K + k0 + c * 8;
        cp16(dst,          Ahi + srcoff);
        cp16(dst + A_TILE, Alo + srcoff);
    }
#pragma unroll
    for (int i = 0; i < 2; i++) {                 // B: 128 rows x 4 chunks
        int id = tid + i * 256;
        int r = id >> 2, c = id & 3;
        uint32_t dst = st + 2 * A_TILE + swz(r, c);
        size_t srcoff = (size_t)(col0 + r) * K + k0 + c * 8;
        cp16(dst,          Bhi + srcoff);
        cp16(dst + B_TILE, Blo + srcoff);
    }
}

// ---------------------------------------------------------------------------
// bf16-split warp-MMA GEMM: C[m,n] = sum_k A[m,k]*B[n,k]
// EPI 0: C = z + bias
// EPI 1: relu(z + bias) -> bf16 split (Ohi, Olo)
// EPI 2: g = sigmoid(z + bias); C *= g; C2 *= g
// EPI 3: C += z
// ---------------------------------------------------------------------------
template <int EPI>
__global__ __launch_bounds__(256)
void bsgemm(const __nv_bfloat16* __restrict__ Ahi, const __nv_bfloat16* __restrict__ Alo,
            const __nv_bfloat16* __restrict__ Bhi, const __nv_bfloat16* __restrict__ Blo,
            const float* __restrict__ bias,
            float* __restrict__ C, float* __restrict__ C2,
            __nv_bfloat16* __restrict__ Ohi, __nv_bfloat16* __restrict__ Olo,
            int M, int N, int K) {
    extern __shared__ __align__(128) char smem[];
    const uint32_t sb = smem_u32(smem);
    const int tid  = threadIdx.x;
    const int wid  = tid >> 5;
    const int lane = tid & 31;
    const int wm = wid >> 1;          // 0..3 (m)
    const int wn = wid & 1;           // 0..1 (n)
    const int row0 = blockIdx.y * TBM;
    const int col0 = blockIdx.x * TBN;
    const int nchunks = K / TBK;

    // ldmatrix lane mapping
    const int lr = lane & 7;
    const int j  = lane >> 3;
    const int arow  = ((j & 1) << 3) + lr;   // A: row within 16-row frag
    const int acsel = j >> 1;                // A: chunk select (0/1)
    const int brow  = ((j >> 1) << 3) + lr;  // B: row within 16-row pair
    const int bcsel = j & 1;

    float acc[4][8][4];
#pragma unroll
    for (int mi = 0; mi < 4; mi++)
#pragma unroll
        for (int nj = 0; nj < 8; nj++)
#pragma unroll
            for (int q = 0; q < 4; q++) acc[mi][nj][q] = 0.0f;

    // prologue: chunks 0,1
#pragma unroll
    for (int p = 0; p < 2; p++) {
        load_ab(sb + p * STAGE_BYTES, Ahi, Alo, Bhi, Blo, K, row0, col0, p * TBK, tid);
        CP_COMMIT();
    }

    for (int c = 0; c < nchunks; c++) {
        if (c + 1 < nchunks) CP_WAIT(1); else CP_WAIT(0);
        __syncthreads();

        const int nxt = c + 2;
        if (nxt < nchunks) {
            load_ab(sb + (nxt % NSTAGE) * STAGE_BYTES, Ahi, Alo, Bhi, Blo,
                    K, row0, col0, nxt * TBK, tid);
            CP_COMMIT();
        }

        const uint32_t sA = sb + (c % NSTAGE) * STAGE_BYTES;
        const uint32_t sB = sA + 2 * A_TILE;

#pragma unroll
        for (int s = 0; s < 2; s++) {
            uint32_t ah[4][4], bh[4][4], fx[4][4];
            uint32_t adA[4], adB[4];
#pragma unroll
            for (int mi = 0; mi < 4; mi++) {
                int r = wm * 64 + mi * 16 + arow;
                adA[mi] = sA + swz(r, 2 * s + acsel);
                LDSM4(ah[mi], adA[mi]);
            }
#pragma unroll
            for (int p = 0; p < 4; p++) {
                int r = wn * 64 + p * 16 + brow;
                adB[p] = sB + swz(r, 2 * s + bcsel);
                LDSM4(bh[p], adB[p]);
            }
            // pass 1: Ahi x Bhi
#pragma unroll
            for (int mi = 0; mi < 4; mi++)
#pragma unroll
                for (int nj = 0; nj < 8; nj++)
                    mma16816(acc[mi][nj], ah[mi], bh[nj >> 1][(nj & 1) * 2], bh[nj >> 1][(nj & 1) * 2 + 1]);
            // pass 2: Alo x Bhi
#pragma unroll
            for (int mi = 0; mi < 4; mi++) LDSM4(fx[mi], adA[mi] + A_TILE);
#pragma unroll
            for (int mi = 0; mi < 4; mi++)
#pragma unroll
                for (int nj = 0; nj < 8; nj++)
                    mma16816(acc[mi][nj], fx[mi], bh[nj >> 1][(nj & 1) * 2], bh[nj >> 1][(nj & 1) * 2 + 1]);
            // pass 3: Ahi x Blo
#pragma unroll
            for (int p = 0; p < 4; p++) LDSM4(fx[p], adB[p] + B_TILE);
#pragma unroll
            for (int mi = 0; mi < 4; mi++)
#pragma unroll
                for (int nj = 0; nj < 8; nj++)
                    mma16816(acc[mi][nj], ah[mi], fx[nj >> 1][(nj & 1) * 2], fx[nj >> 1][(nj & 1) * 2 + 1]);
        }
    }

    // -------- epilogue --------
    const int g = lane >> 2, t = lane & 3;
#pragma unroll
    for (int mi = 0; mi < 4; mi++) {
#pragma unroll
        for (int nj = 0; nj < 8; nj++) {
            int row = row0 + wm * 64 + mi * 16 + g;
            int col = col0 + wn * 64 + nj * 8 + 2 * t;
            size_t i0 = (size_t)row * N + col;
            size_t i1 = (size_t)(row + 8) * N + col;
            float* z = acc[mi][nj];
            if (EPI == 0) {
                float b0 = bias[col], b1 = bias[col + 1];
                *(float2*)(C + i0) = make_float2(z[0] + b0, z[1] + b1);
                *(float2*)(C + i1) = make_float2(z[2] + b0, z[3] + b1);
            } else if (EPI == 1) {
                float b0 = bias[col], b1 = bias[col + 1];
                float v0 = fmaxf(z[0] + b0, 0.0f), v1 = fmaxf(z[1] + b1, 0.0f);
                float v2 = fmaxf(z[2] + b0, 0.0f), v3 = fmaxf(z[3] + b1, 0.0f);
                __nv_bfloat16 h0 = __float2bfloat16(v0), h1 = __float2bfloat16(v1);
                __nv_bfloat16 h2 = __float2bfloat16(v2), h3 = __float2bfloat16(v3);
                *(__nv_bfloat162*)(Ohi + i0) = __halves2bfloat162(h0, h1);
                *(__nv_bfloat162*)(Ohi + i1) = __halves2bfloat162(h2, h3);
                *(__nv_bfloat162*)(Olo + i0) = __halves2bfloat162(
                    __float2bfloat16(v0 - __bfloat162float(h0)), __float2bfloat16(v1 - __bfloat162float(h1)));
                *(__nv_bfloat162*)(Olo + i1) = __halves2bfloat162(
                    __float2bfloat16(v2 - __bfloat162float(h2)), __float2bfloat16(v3 - __bfloat162float(h3)));
            } else if (EPI == 2) {
                float b0 = bias[col], b1 = bias[col + 1];
                float g0 = 1.0f / (1.0f + __expf(-(z[0] + b0)));
                float g1 = 1.0f / (1.0f + __expf(-(z[1] + b1)));
                float g2 = 1.0f / (1.0f + __expf(-(z[2] + b0)));
                float g3 = 1.0f / (1.0f + __expf(-(z[3] + b1)));
                float2 u0 = *(float2*)(C + i0), u1 = *(float2*)(C + i1);
                float2 v0 = *(float2*)(C2 + i0), v1 = *(float2*)(C2 + i1);
                u0.x *= g0; u0.y *= g1; u1.x *= g2; u1.y *= g3;
                v0.x *= g0; v0.y *= g1; v1.x *= g2; v1.y *= g3;
                *(float2*)(C + i0) = u0; *(float2*)(C + i1) = u1;
                *(float2*)(C2 + i0) = v0; *(float2*)(C2 + i1) = v1;
            } else {  // EPI == 3
                float2 o0 = *(float2*)(C + i0), o1 = *(float2*)(C + i1);
                o0.x += z[0]; o0.y += z[1]; o1.x += z[2]; o1.y += z[3];
                *(float2*)(C + i0) = o0; *(float2*)(C + i1) = o1;
            }
        }
    }
}

// ---------------------------------------------------------------------------
// elementwise kernels
// ---------------------------------------------------------------------------
__global__ void split_kernel(const float* __restrict__ s, __nv_bfloat16* __restrict__ hi,
                             __nv_bfloat16* __restrict__ lo, size_t n) {
    size_t i = ((size_t)blockIdx.x * blockDim.x + threadIdx.x) * 4;
    if (i >= n) return;
    float4 v = *(const float4*)(s + i);
    __nv_bfloat16 h0 = __float2bfloat16(v.x), h1 = __float2bfloat16(v.y);
    __nv_bfloat16 h2 = __float2bfloat16(v.z), h3 = __float2bfloat16(v.w);
    *(__nv_bfloat162*)(hi + i)     = __halves2bfloat162(h0, h1);
    *(__nv_bfloat162*)(hi + i + 2) = __halves2bfloat162(h2, h3);
    *(__nv_bfloat162*)(lo + i)     = __halves2bfloat162(
        __float2bfloat16(v.x - __bfloat162float(h0)), __float2bfloat16(v.y - __bfloat162float(h1)));
    *(__nv_bfloat162*)(lo + i + 2) = __halves2bfloat162(
        __float2bfloat16(v.z - __bfloat162float(h2)), __float2bfloat16(v.w - __bfloat162float(h3)));
}

__global__ void conv_kernel(const float* __restrict__ x, const float* __restrict__ w,
                            const float* __restrict__ cb, float* __restrict__ out) {
    size_t idx = (size_t)blockIdx.x * blockDim.x + threadIdx.x;
    if (idx >= (size_t)MM * DD) return;
    int d = (int)(idx % DD);
    int l = (int)((idx / DD) % LL);
    float w0 = w[d * 3 + 0], w1 = w[d * 3 + 1], w2 = w[d * 3 + 2];
    float acc = cb[d] + w1 * x[idx];
    if (l > 0)      acc += w0 * x[idx - DD];
    if (l < LL - 1) acc += w2 * x[idx + DD];
    out[idx] = acc;
}

__global__ void scanA_kernel(const float* __restrict__ u, float* __restrict__ part) {
    int tid = blockIdx.x * blockDim.x + threadIdx.x;
    if (tid >= BB * NCH * RR) return;
    int r = tid % RR;
    int c = (tid / RR) % NCH;
    int b = tid / (RR * NCH);
    size_t base = ((size_t)b * LL + c * CHL) * RR + r;
    float s = 0.0f;
    for (int l = 0; l < CHL; l++) s += u[base + (size_t)l * RR];
    part[((size_t)b * NCH + c) * RR + r] = s;
}

__global__ void scanB_kernel(float* __restrict__ part) {
    int tid = blockIdx.x * blockDim.x + threadIdx.x;
    if (tid >= BB * RR) return;
    int r = tid % RR;
    int b = tid / RR;
    float run = 0.0f;
    for (int c = 0; c < NCH; c++) {
        size_t idx = ((size_t)b * NCH + c) * RR + r;
        float t = part[idx];
        part[idx] = run;
        run += t;
    }
}

__global__ void scanC_kernel(const float* __restrict__ u, const float* __restrict__ v,
                             const float* __restrict__ part,
                             __nv_bfloat16* __restrict__ ghi, __nv_bfloat16* __restrict__ glo) {
    int tid = blockIdx.x * blockDim.x + threadIdx.x;
    if (tid >= BB * NCH * RR) return;
    int r = tid % RR;
    int c = (tid / RR) % NCH;
    int b = tid / (RR * NCH);
    float acc = part[((size_t)b * NCH + c) * RR + r];
    size_t base = ((size_t)b * LL + c * CHL) * RR + r;
    for (int l = 0; l < CHL; l++) {
        size_t idx = base + (size_t)l * RR;
        acc += u[idx];
        float go = acc * v[idx];
        __nv_bfloat16 h = __float2bfloat16(go);
        ghi[idx] = h;
        glo[idx] = __float2bfloat16(go - __bfloat162float(h));
    }
}

// ---------------------------------------------------------------------------
extern "C" void kernel_launch(void* const* d_in, const int* in_sizes, int n_in,
                              void* d_out, int out_size) {
    const float* x      = (const float*)d_in[0];
    const float* Wu     = (const float*)d_in[1];
    const float* bu     = (const float*)d_in[2];
    const float* Wv     = (const float*)d_in[3];
    const float* bv     = (const float*)d_in[4];
    const float* Wg1    = (const float*)d_in[5];
    const float* bg1    = (const float*)d_in[6];
    const float* Wg2    = (const float*)d_in[7];
    const float* bg2    = (const float*)d_in[8];
    const float* conv_w = (const float*)d_in[9];
    const float* conv_b = (const float*)d_in[10];
    float* out = (float*)d_out;

    __nv_bfloat16 *xhi, *xlo, *wuhi, *wulo, *wvhi, *wvlo, *wg1hi, *wg1lo,
                  *wg2hi, *wg2lo, *hhi, *hlo, *ghi, *glo;
    float *pu, *pv, *ppart;
    cudaGetSymbolAddress((void**)&xhi, g_xhi);     cudaGetSymbolAddress((void**)&xlo, g_xlo);
    cudaGetSymbolAddress((void**)&wuhi, g_wuhi);   cudaGetSymbolAddress((void**)&wulo, g_wulo);
    cudaGetSymbolAddress((void**)&wvhi, g_wvhi);   cudaGetSymbolAddress((void**)&wvlo, g_wvlo);
    cudaGetSymbolAddress((void**)&wg1hi, g_wg1hi); cudaGetSymbolAddress((void**)&wg1lo, g_wg1lo);
    cudaGetSymbolAddress((void**)&wg2hi, g_wg2hi); cudaGetSymbolAddress((void**)&wg2lo, g_wg2lo);
    cudaGetSymbolAddress((void**)&hhi, g_hhi);     cudaGetSymbolAddress((void**)&hlo, g_hlo);
    cudaGetSymbolAddress((void**)&ghi, g_ghi);     cudaGetSymbolAddress((void**)&glo, g_glo);
    cudaGetSymbolAddress((void**)&pu, g_u);        cudaGetSymbolAddress((void**)&pv, g_v);
    cudaGetSymbolAddress((void**)&ppart, g_part);

    cudaFuncSetAttribute(bsgemm<0>, cudaFuncAttributeMaxDynamicSharedMemorySize, SMEM_TOTAL);
    cudaFuncSetAttribute(bsgemm<1>, cudaFuncAttributeMaxDynamicSharedMemorySize, SMEM_TOTAL);
    cudaFuncSetAttribute(bsgemm<2>, cudaFuncAttributeMaxDynamicSharedMemorySize, SMEM_TOTAL);
    cudaFuncSetAttribute(bsgemm<3>, cudaFuncAttributeMaxDynamicSharedMemorySize, SMEM_TOTAL);

    // launches 1-5: splits (so launch #6 = big u GEMM lands in the ncu window)
    split_kernel<<<(unsigned)((size_t)MM * DD / 4 / 256), 256>>>(x, xhi, xlo, (size_t)MM * DD);
    split_kernel<<<(unsigned)((size_t)RR * DD / 4 / 256), 256>>>(Wu, wuhi, wulo, (size_t)RR * DD);
    split_kernel<<<(unsigned)((size_t)RR * DD / 4 / 256), 256>>>(Wv, wvhi, wvlo, (size_t)RR * DD);
    split_kernel<<<(unsigned)((size_t)DHH * DD / 4 / 256), 256>>>(Wg1, wg1hi, wg1lo, (size_t)DHH * DD);
    split_kernel<<<(unsigned)((size_t)RR * DHH / 4 / 256), 256>>>(Wg2, wg2hi, wg2lo, (size_t)RR * DHH);

    // launch 6: u = x Wu^T + bu   (ncu target)
    bsgemm<0><<<dim3(RR / TBN, MM / TBM), 256, SMEM_TOTAL>>>(
        xhi, xlo, wuhi, wulo, bu, pu, nullptr, nullptr, nullptr, MM, RR, DD);
    // v = x Wv^T + bv
    bsgemm<0><<<dim3(RR / TBN, MM / TBM), 256, SMEM_TOTAL>>>(
        xhi, xlo, wvhi, wvlo, bv, pv, nullptr, nullptr, nullptr, MM, RR, DD);
    // h = relu(x Wg1^T + bg1) -> bf16 split
    bsgemm<1><<<dim3(DHH / TBN, MM / TBM), 256, SMEM_TOTAL>>>(
        xhi, xlo, wg1hi, wg1lo, bg1, nullptr, nullptr, hhi, hlo, MM, DHH, DD);
    // gates = sigmoid(h Wg2^T + bg2); u *= g; v *= g
    bsgemm<2><<<dim3(RR / TBN, MM / TBM), 256, SMEM_TOTAL>>>(
        hhi, hlo, wg2hi, wg2lo, bg2, pu, pv, nullptr, nullptr, MM, RR, DHH);

    // conv -> out (T term)
    conv_kernel<<<(unsigned)(((size_t)MM * DD + 255) / 256), 256>>>(x, conv_w, conv_b, out);

    // cumsum over L; global_out = cumsum(u_gated) * v_gated -> bf16 split
    scanA_kernel<<<(BB * NCH * RR + 255) / 256, 256>>>(pu, ppart);
    scanB_kernel<<<(BB * RR + 255) / 256, 256>>>(ppart);
    scanC_kernel<<<(BB * NCH * RR + 255) / 256, 256>>>(pu, pv, ppart, ghi, glo);

    // out += global_out @ B where B[n=d][k=r] = Wu[d][r] -> the Wu buffer itself
    bsgemm<3><<<dim3(DD / TBN, MM / TBM), 256, SMEM_TOTAL>>>(
        ghi, glo, wuhi, wulo, nullptr, out, nullptr, nullptr, nullptr, MM, DD, RR);
}

// round 6
// speedup vs baseline: 1.1367x; 1.1367x over previous
#include <cuda_runtime.h>
#include <cuda_bf16.h>
#include <cstdint>
#include <math.h>

// ---------------- problem constants ----------------
#define BB 4
#define LL 2048
#define DD 2048
#define RR 2048
#define DHH 512
#define MM (BB * LL)          // 8192
#define NCH 16
#define CHL (LL / NCH)        // 128

// ---------------- GEMM tiling ----------------
// CTA tile 256x128, 8 warps (4x2), warp tile 64x64, BK=32 bf16 (64B rows)
#define TBM 256
#define TBN 128
#define TBK 32
#define A_TILE 16384          // 256*64B
#define B_TILE 8192           // 128*64B
#define STAGE_BYTES (2 * A_TILE + 2 * B_TILE)   // Ahi, Alo, Bhi, Blo = 49152
#define NSTAGE 3
#define SMEM_TOTAL (NSTAGE * STAGE_BYTES)       // 147456

// ---------------- device scratch ----------------
__device__ __nv_bfloat16 g_xhi[(size_t)MM * DD], g_xlo[(size_t)MM * DD];
__device__ __nv_bfloat16 g_wuhi[(size_t)RR * DD], g_wulo[(size_t)RR * DD];
__device__ __nv_bfloat16 g_wvhi[(size_t)RR * DD], g_wvlo[(size_t)RR * DD];
__device__ __nv_bfloat16 g_wg1hi[(size_t)DHH * DD], g_wg1lo[(size_t)DHH * DD];
__device__ __nv_bfloat16 g_wg2hi[(size_t)RR * DHH], g_wg2lo[(size_t)RR * DHH];
__device__ __nv_bfloat16 g_hhi[(size_t)MM * DHH], g_hlo[(size_t)MM * DHH];
__device__ __nv_bfloat16 g_ghi[(size_t)MM * RR], g_glo[(size_t)MM * RR];
__device__ float g_u[(size_t)MM * RR];
__device__ float g_v[(size_t)MM * RR];
__device__ float g_part[(size_t)BB * NCH * RR];

// ---------------- PTX helpers (arch-agnostic only) ----------------
__device__ __forceinline__ uint32_t smem_u32(const void* p) {
    uint32_t a;
    asm("{ .reg .u64 t; cvta.to.shared.u64 t, %1; cvt.u32.u64 %0, t; }" : "=r"(a) : "l"(p));
    return a;
}
__device__ __forceinline__ void cp16(uint32_t dst, const void* src) {
    asm volatile("cp.async.cg.shared.global [%0], [%1], 16;" :: "r"(dst), "l"(src));
}
#define CP_COMMIT() asm volatile("cp.async.commit_group;" ::: "memory")
#define CP_WAIT(n)  asm volatile("cp.async.wait_group %0;" :: "n"(n) : "memory")

#define LDSM4(r, addr) \
    asm volatile("ldmatrix.sync.aligned.m8n8.x4.shared.b16 {%0,%1,%2,%3}, [%4];" \
        : "=r"((r)[0]), "=r"((r)[1]), "=r"((r)[2]), "=r"((r)[3]) : "r"(addr))

__device__ __forceinline__ void mma16816(float* c, const uint32_t* a, uint32_t b0, uint32_t b1) {
    asm volatile(
        "mma.sync.aligned.m16n8k16.row.col.f32.bf16.bf16.f32 "
        "{%0,%1,%2,%3}, {%4,%5,%6,%7}, {%8,%9}, {%0,%1,%2,%3};"
        : "+f"(c[0]), "+f"(c[1]), "+f"(c[2]), "+f"(c[3])
        : "r"(a[0]), "r"(a[1]), "r"(a[2]), "r"(a[3]), "r"(b0), "r"(b1));
}

// swizzled smem offset for (row, 16B-chunk c) in a 64B-row tile.
// (R4 version — verified conflict-free per 8-lane ldmatrix phase:
//  bank pos = (r&1)*64 + ((c ^ ((r>>1)&3))<<4) hits 8 distinct 16B groups)
__device__ __forceinline__ uint32_t swz(int r, int c) {
    return (uint32_t)(r * 64 + ((c ^ ((r >> 1) & 3)) << 4));
}

// load one chunk's tiles into a stage (lo tiles only when SPLIT)
template <bool SPLIT>
__device__ __forceinline__ void load_ab(uint32_t st,
                                        const __nv_bfloat16* __restrict__ Ahi,
                                        const __nv_bfloat16* __restrict__ Alo,
                                        const __nv_bfloat16* __restrict__ Bhi,
                                        const __nv_bfloat16* __restrict__ Blo,
                                        int K, int row0, int col0, int k0, int tid) {
#pragma unroll
    for (int i = 0; i < 4; i++) {                 // A: 256 rows x 4 chunks
        int id = tid + i * 256;
        int r = id >> 2, c = id & 3;
        uint32_t dst = st + swz(r, c);
        size_t srcoff = (size_t)(row0 + r) * K + k0 + c * 8;
        cp16(dst, Ahi + srcoff);
        if (SPLIT) cp16(dst + A_TILE, Alo + srcoff);
    }
#pragma unroll
    for (int i = 0; i < 2; i++) {                 // B: 128 rows x 4 chunks
        int id = tid + i * 256;
        int r = id >> 2, c = id & 3;
        uint32_t dst = st + 2 * A_TILE + swz(r, c);
        size_t srcoff = (size_t)(col0 + r) * K + k0 + c * 8;
        cp16(dst, Bhi + srcoff);
        if (SPLIT) cp16(dst + B_TILE, Blo + srcoff);
    }
}

// ---------------------------------------------------------------------------
// bf16(-split) warp-MMA GEMM: C[m,n] = sum_k A[m,k]*B[n,k]
// NPASS 3: hi*hi + lo*hi + hi*lo (fp32-grade);  NPASS 1: hi*hi (plain bf16)
// EPI 0: C = z + bias
// EPI 1: relu(z + bias) -> bf16 split (Ohi, Olo)
// EPI 2: g = sigmoid(z + bias); C *= g; C2 *= g
// EPI 3: C += z
// ---------------------------------------------------------------------------
template <int EPI, int NPASS>
__global__ __launch_bounds__(256)
void bsgemm(const __nv_bfloat16* __restrict__ Ahi, const __nv_bfloat16* __restrict__ Alo,
            const __nv_bfloat16* __restrict__ Bhi, const __nv_bfloat16* __restrict__ Blo,
            const float* __restrict__ bias,
            float* __restrict__ C, float* __restrict__ C2,
            __nv_bfloat16* __restrict__ Ohi, __nv_bfloat16* __restrict__ Olo,
            int M, int N, int K) {
    extern __shared__ __align__(128) char smem[];
    const uint32_t sb = smem_u32(smem);
    const int tid  = threadIdx.x;
    const int wid  = tid >> 5;
    const int lane = tid & 31;
    const int wm = wid >> 1;          // 0..3 (m)
    const int wn = wid & 1;           // 0..1 (n)
    const int row0 = blockIdx.y * TBM;
    const int col0 = blockIdx.x * TBN;
    const int nchunks = K / TBK;
    constexpr bool SPLIT = (NPASS == 3);

    // ldmatrix lane mapping
    const int lr = lane & 7;
    const int j  = lane >> 3;
    const int arow  = ((j & 1) << 3) + lr;   // A: row within 16-row frag
    const int acsel = j >> 1;                // A: chunk select (0/1)
    const int brow  = ((j >> 1) << 3) + lr;  // B: row within 16-row pair
    const int bcsel = j & 1;

    float acc[4][8][4];
#pragma unroll
    for (int mi = 0; mi < 4; mi++)
#pragma unroll
        for (int nj = 0; nj < 8; nj++)
#pragma unroll
            for (int q = 0; q < 4; q++) acc[mi][nj][q] = 0.0f;

    // prologue: chunks 0,1
#pragma unroll
    for (int p = 0; p < 2; p++) {
        load_ab<SPLIT>(sb + p * STAGE_BYTES, Ahi, Alo, Bhi, Blo, K, row0, col0, p * TBK, tid);
        CP_COMMIT();
    }

    for (int c = 0; c < nchunks; c++) {
        if (c + 1 < nchunks) CP_WAIT(1); else CP_WAIT(0);
        __syncthreads();

        const int nxt = c + 2;
        if (nxt < nchunks) {
            load_ab<SPLIT>(sb + (nxt % NSTAGE) * STAGE_BYTES, Ahi, Alo, Bhi, Blo,
                           K, row0, col0, nxt * TBK, tid);
            CP_COMMIT();
        }

        const uint32_t sA = sb + (c % NSTAGE) * STAGE_BYTES;
        const uint32_t sB = sA + 2 * A_TILE;

#pragma unroll
        for (int s = 0; s < 2; s++) {
            uint32_t ah[4][4], bh[4][4], fx[4][4];
            uint32_t adA[4], adB[4];
#pragma unroll
            for (int mi = 0; mi < 4; mi++) {
                int r = wm * 64 + mi * 16 + arow;
                adA[mi] = sA + swz(r, 2 * s + acsel);
                LDSM4(ah[mi], adA[mi]);
            }
#pragma unroll
            for (int p = 0; p < 4; p++) {
                int r = wn * 64 + p * 16 + brow;
                adB[p] = sB + swz(r, 2 * s + bcsel);
                LDSM4(bh[p], adB[p]);
            }
            // pass 1: Ahi x Bhi
#pragma unroll
            for (int mi = 0; mi < 4; mi++)
#pragma unroll
                for (int nj = 0; nj < 8; nj++)
                    mma16816(acc[mi][nj], ah[mi], bh[nj >> 1][(nj & 1) * 2], bh[nj >> 1][(nj & 1) * 2 + 1]);
            if (NPASS == 3) {
                // pass 2: Alo x Bhi
#pragma unroll
                for (int mi = 0; mi < 4; mi++) LDSM4(fx[mi], adA[mi] + A_TILE);
#pragma unroll
                for (int mi = 0; mi < 4; mi++)
#pragma unroll
                    for (int nj = 0; nj < 8; nj++)
                        mma16816(acc[mi][nj], fx[mi], bh[nj >> 1][(nj & 1) * 2], bh[nj >> 1][(nj & 1) * 2 + 1]);
                // pass 3: Ahi x Blo
#pragma unroll
                for (int p = 0; p < 4; p++) LDSM4(fx[p], adB[p] + B_TILE);
#pragma unroll
                for (int mi = 0; mi < 4; mi++)
#pragma unroll
                    for (int nj = 0; nj < 8; nj++)
                        mma16816(acc[mi][nj], ah[mi], fx[nj >> 1][(nj & 1) * 2], fx[nj >> 1][(nj & 1) * 2 + 1]);
            }
        }
    }

    // -------- epilogue --------
    const int g = lane >> 2, t = lane & 3;
#pragma unroll
    for (int mi = 0; mi < 4; mi++) {
#pragma unroll
        for (int nj = 0; nj < 8; nj++) {
            int row = row0 + wm * 64 + mi * 16 + g;
            int col = col0 + wn * 64 + nj * 8 + 2 * t;
            size_t i0 = (size_t)row * N + col;
            size_t i1 = (size_t)(row + 8) * N + col;
            float* z = acc[mi][nj];
            if (EPI == 0) {
                float b0 = bias[col], b1 = bias[col + 1];
                *(float2*)(C + i0) = make_float2(z[0] + b0, z[1] + b1);
                *(float2*)(C + i1) = make_float2(z[2] + b0, z[3] + b1);
            } else if (EPI == 1) {
                float b0 = bias[col], b1 = bias[col + 1];
                float v0 = fmaxf(z[0] + b0, 0.0f), v1 = fmaxf(z[1] + b1, 0.0f);
                float v2 = fmaxf(z[2] + b0, 0.0f), v3 = fmaxf(z[3] + b1, 0.0f);
                __nv_bfloat16 h0 = __float2bfloat16(v0), h1 = __float2bfloat16(v1);
                __nv_bfloat16 h2 = __float2bfloat16(v2), h3 = __float2bfloat16(v3);
                *(__nv_bfloat162*)(Ohi + i0) = __halves2bfloat162(h0, h1);
                *(__nv_bfloat162*)(Ohi + i1) = __halves2bfloat162(h2, h3);
                if (Olo != nullptr) {
                    *(__nv_bfloat162*)(Olo + i0) = __halves2bfloat162(
                        __float2bfloat16(v0 - __bfloat162float(h0)), __float2bfloat16(v1 - __bfloat162float(h1)));
                    *(__nv_bfloat162*)(Olo + i1) = __halves2bfloat162(
                        __float2bfloat16(v2 - __bfloat162float(h2)), __float2bfloat16(v3 - __bfloat162float(h3)));
                }
            } else if (EPI == 2) {
                float b0 = bias[col], b1 = bias[col + 1];
                float g0 = 1.0f / (1.0f + __expf(-(z[0] + b0)));
                float g1 = 1.0f / (1.0f + __expf(-(z[1] + b1)));
                float g2 = 1.0f / (1.0f + __expf(-(z[2] + b0)));
                float g3 = 1.0f / (1.0f + __expf(-(z[3] + b1)));
                float2 u0 = *(float2*)(C + i0), u1 = *(float2*)(C + i1);
                float2 v0 = *(float2*)(C2 + i0), v1 = *(float2*)(C2 + i1);
                u0.x *= g0; u0.y *= g1; u1.x *= g2; u1.y *= g3;
                v0.x *= g0; v0.y *= g1; v1.x *= g2; v1.y *= g3;
                *(float2*)(C + i0) = u0; *(float2*)(C + i1) = u1;
                *(float2*)(C2 + i0) = v0; *(float2*)(C2 + i1) = v1;
            } else {  // EPI == 3
                float2 o0 = *(float2*)(C + i0), o1 = *(float2*)(C + i1);
                o0.x += z[0]; o0.y += z[1]; o1.x += z[2]; o1.y += z[3];
                *(float2*)(C + i0) = o0; *(float2*)(C + i1) = o1;
            }
        }
    }
}

// ---------------------------------------------------------------------------
// elementwise kernels
// ---------------------------------------------------------------------------
__global__ void split_kernel(const float* __restrict__ s, __nv_bfloat16* __restrict__ hi,
                             __nv_bfloat16* __restrict__ lo, size_t n) {
    size_t i = ((size_t)blockIdx.x * blockDim.x + threadIdx.x) * 4;
    if (i >= n) return;
    float4 v = *(const float4*)(s + i);
    __nv_bfloat16 h0 = __float2bfloat16(v.x), h1 = __float2bfloat16(v.y);
    __nv_bfloat16 h2 = __float2bfloat16(v.z), h3 = __float2bfloat16(v.w);
    *(__nv_bfloat162*)(hi + i)     = __halves2bfloat162(h0, h1);
    *(__nv_bfloat162*)(hi + i + 2) = __halves2bfloat162(h2, h3);
    if (lo != nullptr) {
        *(__nv_bfloat162*)(lo + i)     = __halves2bfloat162(
            __float2bfloat16(v.x - __bfloat162float(h0)), __float2bfloat16(v.y - __bfloat162float(h1)));
        *(__nv_bfloat162*)(lo + i + 2) = __halves2bfloat162(
            __float2bfloat16(v.z - __bfloat162float(h2)), __float2bfloat16(v.w - __bfloat162float(h3)));
    }
}

__global__ void conv_kernel(const float* __restrict__ x, const float* __restrict__ w,
                            const float* __restrict__ cb, float* __restrict__ out) {
    size_t idx = (size_t)blockIdx.x * blockDim.x + threadIdx.x;
    if (idx >= (size_t)MM * DD) return;
    int d = (int)(idx % DD);
    int l = (int)((idx / DD) % LL);
    float w0 = w[d * 3 + 0], w1 = w[d * 3 + 1], w2 = w[d * 3 + 2];
    float acc = cb[d] + w1 * x[idx];
    if (l > 0)      acc += w0 * x[idx - DD];
    if (l < LL - 1) acc += w2 * x[idx + DD];
    out[idx] = acc;
}

__global__ void scanA_kernel(const float* __restrict__ u, float* __restrict__ part) {
    int tid = blockIdx.x * blockDim.x + threadIdx.x;
    if (tid >= BB * NCH * RR) return;
    int r = tid % RR;
    int c = (tid / RR) % NCH;
    int b = tid / (RR * NCH);
    size_t base = ((size_t)b * LL + c * CHL) * RR + r;
    float s = 0.0f;
    for (int l = 0; l < CHL; l++) s += u[base + (size_t)l * RR];
    part[((size_t)b * NCH + c) * RR + r] = s;
}

__global__ void scanB_kernel(float* __restrict__ part) {
    int tid = blockIdx.x * blockDim.x + threadIdx.x;
    if (tid >= BB * RR) return;
    int r = tid % RR;
    int b = tid / RR;
    float run = 0.0f;
    for (int c = 0; c < NCH; c++) {
        size_t idx = ((size_t)b * NCH + c) * RR + r;
        float t = part[idx];
        part[idx] = run;
        run += t;
    }
}

__global__ void scanC_kernel(const float* __restrict__ u, const float* __restrict__ v,
                             const float* __restrict__ part,
                             __nv_bfloat16* __restrict__ ghi, __nv_bfloat16* __restrict__ glo) {
    int tid = blockIdx.x * blockDim.x + threadIdx.x;
    if (tid >= BB * NCH * RR) return;
    int r = tid % RR;
    int c = (tid / RR) % NCH;
    int b = tid / (RR * NCH);
    float acc = part[((size_t)b * NCH + c) * RR + r];
    size_t base = ((size_t)b * LL + c * CHL) * RR + r;
    for (int l = 0; l < CHL; l++) {
        size_t idx = base + (size_t)l * RR;
        acc += u[idx];
        float go = acc * v[idx];
        __nv_bfloat16 h = __float2bfloat16(go);
        ghi[idx] = h;
        glo[idx] = __float2bfloat16(go - __bfloat162float(h));
    }
}

// ---------------------------------------------------------------------------
extern "C" void kernel_launch(void* const* d_in, const int* in_sizes, int n_in,
                              void* d_out, int out_size) {
    const float* x      = (const float*)d_in[0];
    const float* Wu     = (const float*)d_in[1];
    const float* bu     = (const float*)d_in[2];
    const float* Wv     = (const float*)d_in[3];
    const float* bv     = (const float*)d_in[4];
    const float* Wg1    = (const float*)d_in[5];
    const float* bg1    = (const float*)d_in[6];
    const float* Wg2    = (const float*)d_in[7];
    const float* bg2    = (const float*)d_in[8];
    const float* conv_w = (const float*)d_in[9];
    const float* conv_b = (const float*)d_in[10];
    float* out = (float*)d_out;

    __nv_bfloat16 *xhi, *xlo, *wuhi, *wulo, *wvhi, *wvlo, *wg1hi,
                  *wg2hi, *hhi, *ghi, *glo;
    float *pu, *pv, *ppart;
    cudaGetSymbolAddress((void**)&xhi, g_xhi);     cudaGetSymbolAddress((void**)&xlo, g_xlo);
    cudaGetSymbolAddress((void**)&wuhi, g_wuhi);   cudaGetSymbolAddress((void**)&wulo, g_wulo);
    cudaGetSymbolAddress((void**)&wvhi, g_wvhi);   cudaGetSymbolAddress((void**)&wvlo, g_wvlo);
    cudaGetSymbolAddress((void**)&wg1hi, g_wg1hi);
    cudaGetSymbolAddress((void**)&wg2hi, g_wg2hi);
    cudaGetSymbolAddress((void**)&hhi, g_hhi);
    cudaGetSymbolAddress((void**)&ghi, g_ghi);     cudaGetSymbolAddress((void**)&glo, g_glo);
    cudaGetSymbolAddress((void**)&pu, g_u);        cudaGetSymbolAddress((void**)&pv, g_v);
    cudaGetSymbolAddress((void**)&ppart, g_part);

    cudaFuncSetAttribute(bsgemm<0,3>, cudaFuncAttributeMaxDynamicSharedMemorySize, SMEM_TOTAL);
    cudaFuncSetAttribute(bsgemm<1,1>, cudaFuncAttributeMaxDynamicSharedMemorySize, SMEM_TOTAL);
    cudaFuncSetAttribute(bsgemm<2,1>, cudaFuncAttributeMaxDynamicSharedMemorySize, SMEM_TOTAL);
    cudaFuncSetAttribute(bsgemm<3,3>, cudaFuncAttributeMaxDynamicSharedMemorySize, SMEM_TOTAL);

    // launches 1-3: splits needed by the big GEMMs
    split_kernel<<<(unsigned)((size_t)MM * DD / 4 / 256), 256>>>(x, xhi, xlo, (size_t)MM * DD);
    split_kernel<<<(unsigned)((size_t)RR * DD / 4 / 256), 256>>>(Wu, wuhi, wulo, (size_t)RR * DD);
    split_kernel<<<(unsigned)((size_t)RR * DD / 4 / 256), 256>>>(Wv, wvhi, wvlo, (size_t)RR * DD);

    // launches 4-5: big GEMMs (ncu -s 5 -c 1 lands on one of these given 1-2 harness preludes)
    bsgemm<0,3><<<dim3(RR / TBN, MM / TBM), 256, SMEM_TOTAL>>>(
        xhi, xlo, wuhi, wulo, bu, pu, nullptr, nullptr, nullptr, MM, RR, DD);
    bsgemm<0,3><<<dim3(RR / TBN, MM / TBM), 256, SMEM_TOTAL>>>(
        xhi, xlo, wvhi, wvlo, bv, pv, nullptr, nullptr, nullptr, MM, RR, DD);

    // gate path (plain bf16, single pass)
    split_kernel<<<(unsigned)((size_t)DHH * DD / 4 / 256), 256>>>(Wg1, wg1hi, nullptr, (size_t)DHH * DD);
    split_kernel<<<(unsigned)((size_t)RR * DHH / 4 / 256), 256>>>(Wg2, wg2hi, nullptr, (size_t)RR * DHH);
    // h = relu(x Wg1^T + bg1) -> bf16 (hi only)
    bsgemm<1,1><<<dim3(DHH / TBN, MM / TBM), 256, SMEM_TOTAL>>>(
        xhi, nullptr, wg1hi, nullptr, bg1, nullptr, nullptr, hhi, nullptr, MM, DHH, DD);
    // gates = sigmoid(h Wg2^T + bg2); u *= g; v *= g
    bsgemm<2,1><<<dim3(RR / TBN, MM / TBM), 256, SMEM_TOTAL>>>(
        hhi, nullptr, wg2hi, nullptr, bg2, pu, pv, nullptr, nullptr, MM, RR, DHH);

    // conv -> out (T term)
    conv_kernel<<<(unsigned)(((size_t)MM * DD + 255) / 256), 256>>>(x, conv_w, conv_b, out);

    // cumsum over L; global_out = cumsum(u_gated) * v_gated -> bf16 split
    scanA_kernel<<<(BB * NCH * RR + 255) / 256, 256>>>(pu, ppart);
    scanB_kernel<<<(BB * RR + 255) / 256, 256>>>(ppart);
    scanC_kernel<<<(BB * NCH * RR + 255) / 256, 256>>>(pu, pv, ppart, ghi, glo);

    // out += global_out @ B where B[n=d][k=r] = Wu[d][r] -> the Wu buffer itself
    bsgemm<3,3><<<dim3(DD / TBN, MM / TBM), 256, SMEM_TOTAL>>>(
        ghi, glo, wuhi, wulo, nullptr, out, nullptr, nullptr, nullptr, MM, DD, RR);
}

// round 7
// speedup vs baseline: 1.3463x; 1.1844x over previous
#include <cuda_runtime.h>
#include <cuda_bf16.h>
#include <cstdint>
#include <math.h>

// ---------------- problem constants ----------------
#define BB 4
#define LL 2048
#define DD 2048
#define RR 2048
#define DHH 512
#define MM (BB * LL)          // 8192
#define NCH 16
#define CHL (LL / NCH)        // 128

// ---------------- GEMM tiling ----------------
// CTA tile 256x128, 8 warps (4x2), warp tile 64x64, BK=64 bf16 (128B rows)
#define TBM 256
#define TBN 128
#define TBK 64
#define A_TILE 32768          // 256 rows * 128B
#define B_TILE 16384          // 128 rows * 128B
#define STAGE_BYTES (2 * A_TILE + 2 * B_TILE)   // 98304
#define NSTAGE 2
#define SMEM_TOTAL (NSTAGE * STAGE_BYTES)       // 196608

// ---------------- device scratch ----------------
__device__ __nv_bfloat16 g_xhi[(size_t)MM * DD], g_xlo[(size_t)MM * DD];
__device__ __nv_bfloat16 g_wuhi[(size_t)RR * DD], g_wulo[(size_t)RR * DD];
__device__ __nv_bfloat16 g_wvhi[(size_t)RR * DD], g_wvlo[(size_t)RR * DD];
__device__ __nv_bfloat16 g_wg1hi[(size_t)DHH * DD];
__device__ __nv_bfloat16 g_wg2hi[(size_t)RR * DHH];
__device__ __nv_bfloat16 g_hhi[(size_t)MM * DHH];
__device__ __nv_bfloat16 g_ghi[(size_t)MM * RR], g_glo[(size_t)MM * RR];
__device__ float g_u[(size_t)MM * RR];
__device__ float g_v[(size_t)MM * RR];
__device__ float g_part[(size_t)BB * NCH * RR];

// ---------------- PTX helpers (arch-agnostic only) ----------------
__device__ __forceinline__ uint32_t smem_u32(const void* p) {
    uint32_t a;
    asm("{ .reg .u64 t; cvta.to.shared.u64 t, %1; cvt.u32.u64 %0, t; }" : "=r"(a) : "l"(p));
    return a;
}
__device__ __forceinline__ void cp16(uint32_t dst, const void* src) {
    asm volatile("cp.async.cg.shared.global [%0], [%1], 16;" :: "r"(dst), "l"(src));
}
#define CP_COMMIT() asm volatile("cp.async.commit_group;" ::: "memory")
#define CP_WAIT(n)  asm volatile("cp.async.wait_group %0;" :: "n"(n) : "memory")

#define LDSM4(r, addr) \
    asm volatile("ldmatrix.sync.aligned.m8n8.x4.shared.b16 {%0,%1,%2,%3}, [%4];" \
        : "=r"((r)[0]), "=r"((r)[1]), "=r"((r)[2]), "=r"((r)[3]) : "r"(addr))

__device__ __forceinline__ void mma16816(float* c, const uint32_t* a, uint32_t b0, uint32_t b1) {
    asm volatile(
        "mma.sync.aligned.m16n8k16.row.col.f32.bf16.bf16.f32 "
        "{%0,%1,%2,%3}, {%4,%5,%6,%7}, {%8,%9}, {%0,%1,%2,%3};"
        : "+f"(c[0]), "+f"(c[1]), "+f"(c[2]), "+f"(c[3])
        : "r"(a[0]), "r"(a[1]), "r"(a[2]), "r"(a[3]), "r"(b0), "r"(b1));
}

// SW128 swizzle for 128B rows: (row, 16B-chunk c in 0..7)
// ldmatrix phase (8 lanes, rows r..r+7, same c) -> groups c^(r&7): all distinct.
__device__ __forceinline__ uint32_t swz(int r, int c) {
    return (uint32_t)(r * 128 + ((c ^ (r & 7)) << 4));
}

// load one 64-K chunk's tiles into a stage (lo planes only when SPLIT)
template <bool SPLIT>
__device__ __forceinline__ void load_ab(uint32_t st,
                                        const __nv_bfloat16* __restrict__ Ahi,
                                        const __nv_bfloat16* __restrict__ Alo,
                                        const __nv_bfloat16* __restrict__ Bhi,
                                        const __nv_bfloat16* __restrict__ Blo,
                                        int K, int row0, int col0, int k0, int tid) {
#pragma unroll
    for (int i = 0; i < 8; i++) {                 // A: 256 rows x 8 chunks of 16B
        int id = tid + i * 256;
        int r = id >> 3, c = id & 7;
        uint32_t dst = st + swz(r, c);
        size_t srcoff = (size_t)(row0 + r) * K + k0 + c * 8;
        cp16(dst, Ahi + srcoff);
        if (SPLIT) cp16(dst + A_TILE, Alo + srcoff);
    }
#pragma unroll
    for (int i = 0; i < 4; i++) {                 // B: 128 rows x 8 chunks
        int id = tid + i * 256;
        int r = id >> 3, c = id & 7;
        uint32_t dst = st + 2 * A_TILE + swz(r, c);
        size_t srcoff = (size_t)(col0 + r) * K + k0 + c * 8;
        cp16(dst, Bhi + srcoff);
        if (SPLIT) cp16(dst + B_TILE, Blo + srcoff);
    }
}

// ---------------------------------------------------------------------------
// bf16(-split) warp-MMA GEMM: C[m,n] = sum_k A[m,k]*B[n,k]
// NPASS 3: hi*hi + lo*hi + hi*lo ; NPASS 1: hi*hi
// DUAL: blockIdx.z selects (B,bias,C) pair (EPI 0 only)
// EPI 0: C = z + bias
// EPI 1: relu(z + bias) -> bf16 (Ohi)
// EPI 2: g = sigmoid(z + bias); C *= g; C2 *= g
// EPI 3: C += z
// ---------------------------------------------------------------------------
template <int EPI, int NPASS, bool DUAL>
__global__ __launch_bounds__(256)
void bsgemm(const __nv_bfloat16* __restrict__ Ahi, const __nv_bfloat16* __restrict__ Alo,
            const __nv_bfloat16* __restrict__ Bhi_, const __nv_bfloat16* __restrict__ Blo_,
            const float* __restrict__ bias_,
            float* __restrict__ C_, float* __restrict__ C2,
            __nv_bfloat16* __restrict__ Ohi,
            const __nv_bfloat16* __restrict__ Bhi2, const __nv_bfloat16* __restrict__ Blo2,
            const float* __restrict__ bias2, float* __restrict__ Cd2,
            int M, int N, int K) {
    extern __shared__ __align__(128) char smem[];
    const uint32_t sb = smem_u32(smem);
    const int tid  = threadIdx.x;
    const int wid  = tid >> 5;
    const int lane = tid & 31;
    const int wm = wid >> 1;          // 0..3 (m)
    const int wn = wid & 1;           // 0..1 (n)
    const int row0 = blockIdx.y * TBM;
    const int col0 = blockIdx.x * TBN;
    const int nchunks = K / TBK;
    constexpr bool SPLIT = (NPASS == 3);

    const __nv_bfloat16* Bhi = Bhi_;
    const __nv_bfloat16* Blo = Blo_;
    const float* bias = bias_;
    float* C = C_;
    if (DUAL && blockIdx.z == 1) { Bhi = Bhi2; Blo = Blo2; bias = bias2; C = Cd2; }

    // ldmatrix lane mapping
    const int lr = lane & 7;
    const int j  = lane >> 3;
    const int arow  = ((j & 1) << 3) + lr;   // A: row within 16-row frag
    const int acsel = j >> 1;                // A: 16B-chunk select (0/1)
    const int brow  = ((j >> 1) << 3) + lr;  // B: row within 16-row pair
    const int bcsel = j & 1;

    float acc[4][8][4];
#pragma unroll
    for (int mi = 0; mi < 4; mi++)
#pragma unroll
        for (int nj = 0; nj < 8; nj++)
#pragma unroll
            for (int q = 0; q < 4; q++) acc[mi][nj][q] = 0.0f;

    // prologue: chunk 0 into stage 0
    load_ab<SPLIT>(sb, Ahi, Alo, Bhi, Blo, K, row0, col0, 0, tid);
    CP_COMMIT();

    for (int c = 0; c < nchunks; c++) {
        CP_WAIT(0);
        __syncthreads();

        if (c + 1 < nchunks) {
            load_ab<SPLIT>(sb + ((c + 1) & 1) * STAGE_BYTES, Ahi, Alo, Bhi, Blo,
                           K, row0, col0, (c + 1) * TBK, tid);
            CP_COMMIT();
        }

        const uint32_t sA = sb + (c & 1) * STAGE_BYTES;
        const uint32_t sB = sA + 2 * A_TILE;

#pragma unroll
        for (int s = 0; s < 4; s++) {
            uint32_t ah[4][4], bh[4][4], fx[4][4];
            uint32_t adA[4], adB[4];
#pragma unroll
            for (int mi = 0; mi < 4; mi++) {
                int r = wm * 64 + mi * 16 + arow;
                adA[mi] = sA + swz(r, 2 * s + acsel);
                LDSM4(ah[mi], adA[mi]);
            }
#pragma unroll
            for (int p = 0; p < 4; p++) {
                int r = wn * 64 + p * 16 + brow;
                adB[p] = sB + swz(r, 2 * s + bcsel);
                LDSM4(bh[p], adB[p]);
            }
            // pass 1: Ahi x Bhi
#pragma unroll
            for (int mi = 0; mi < 4; mi++)
#pragma unroll
                for (int nj = 0; nj < 8; nj++)
                    mma16816(acc[mi][nj], ah[mi], bh[nj >> 1][(nj & 1) * 2], bh[nj >> 1][(nj & 1) * 2 + 1]);
            if (NPASS == 3) {
                // pass 2: Alo x Bhi
#pragma unroll
                for (int mi = 0; mi < 4; mi++) LDSM4(fx[mi], adA[mi] + A_TILE);
#pragma unroll
                for (int mi = 0; mi < 4; mi++)
#pragma unroll
                    for (int nj = 0; nj < 8; nj++)
                        mma16816(acc[mi][nj], fx[mi], bh[nj >> 1][(nj & 1) * 2], bh[nj >> 1][(nj & 1) * 2 + 1]);
                // pass 3: Ahi x Blo
#pragma unroll
                for (int p = 0; p < 4; p++) LDSM4(fx[p], adB[p] + B_TILE);
#pragma unroll
                for (int mi = 0; mi < 4; mi++)
#pragma unroll
                    for (int nj = 0; nj < 8; nj++)
                        mma16816(acc[mi][nj], ah[mi], fx[nj >> 1][(nj & 1) * 2], fx[nj >> 1][(nj & 1) * 2 + 1]);
            }
        }
    }

    // -------- epilogue --------
    const int g = lane >> 2, t = lane & 3;
#pragma unroll
    for (int mi = 0; mi < 4; mi++) {
#pragma unroll
        for (int nj = 0; nj < 8; nj++) {
            int row = row0 + wm * 64 + mi * 16 + g;
            int col = col0 + wn * 64 + nj * 8 + 2 * t;
            size_t i0 = (size_t)row * N + col;
            size_t i1 = (size_t)(row + 8) * N + col;
            float* z = acc[mi][nj];
            if (EPI == 0) {
                float b0 = bias[col], b1 = bias[col + 1];
                *(float2*)(C + i0) = make_float2(z[0] + b0, z[1] + b1);
                *(float2*)(C + i1) = make_float2(z[2] + b0, z[3] + b1);
            } else if (EPI == 1) {
                float b0 = bias[col], b1 = bias[col + 1];
                float v0 = fmaxf(z[0] + b0, 0.0f), v1 = fmaxf(z[1] + b1, 0.0f);
                float v2 = fmaxf(z[2] + b0, 0.0f), v3 = fmaxf(z[3] + b1, 0.0f);
                *(__nv_bfloat162*)(Ohi + i0) = __halves2bfloat162(__float2bfloat16(v0), __float2bfloat16(v1));
                *(__nv_bfloat162*)(Ohi + i1) = __halves2bfloat162(__float2bfloat16(v2), __float2bfloat16(v3));
            } else if (EPI == 2) {
                float b0 = bias[col], b1 = bias[col + 1];
                float g0 = 1.0f / (1.0f + __expf(-(z[0] + b0)));
                float g1 = 1.0f / (1.0f + __expf(-(z[1] + b1)));
                float g2 = 1.0f / (1.0f + __expf(-(z[2] + b0)));
                float g3 = 1.0f / (1.0f + __expf(-(z[3] + b1)));
                float2 u0 = *(float2*)(C + i0), u1 = *(float2*)(C + i1);
                float2 v0 = *(float2*)(C2 + i0), v1 = *(float2*)(C2 + i1);
                u0.x *= g0; u0.y *= g1; u1.x *= g2; u1.y *= g3;
                v0.x *= g0; v0.y *= g1; v1.x *= g2; v1.y *= g3;
                *(float2*)(C + i0) = u0; *(float2*)(C + i1) = u1;
                *(float2*)(C2 + i0) = v0; *(float2*)(C2 + i1) = v1;
            } else {  // EPI == 3
                float2 o0 = *(float2*)(C + i0), o1 = *(float2*)(C + i1);
                o0.x += z[0]; o0.y += z[1]; o1.x += z[2]; o1.y += z[3];
                *(float2*)(C + i0) = o0; *(float2*)(C + i1) = o1;
            }
        }
    }
}

// ---------------------------------------------------------------------------
// elementwise kernels
// ---------------------------------------------------------------------------
__global__ void split_kernel(const float* __restrict__ s, __nv_bfloat16* __restrict__ hi,
                             __nv_bfloat16* __restrict__ lo, size_t n) {
    size_t i = ((size_t)blockIdx.x * blockDim.x + threadIdx.x) * 4;
    if (i >= n) return;
    float4 v = *(const float4*)(s + i);
    __nv_bfloat16 h0 = __float2bfloat16(v.x), h1 = __float2bfloat16(v.y);
    __nv_bfloat16 h2 = __float2bfloat16(v.z), h3 = __float2bfloat16(v.w);
    *(__nv_bfloat162*)(hi + i)     = __halves2bfloat162(h0, h1);
    *(__nv_bfloat162*)(hi + i + 2) = __halves2bfloat162(h2, h3);
    if (lo != nullptr) {
        *(__nv_bfloat162*)(lo + i)     = __halves2bfloat162(
            __float2bfloat16(v.x - __bfloat162float(h0)), __float2bfloat16(v.y - __bfloat162float(h1)));
        *(__nv_bfloat162*)(lo + i + 2) = __halves2bfloat162(
            __float2bfloat16(v.z - __bfloat162float(h2)), __float2bfloat16(v.w - __bfloat162float(h3)));
    }
}

__global__ void conv_kernel(const float* __restrict__ x, const float* __restrict__ w,
                            const float* __restrict__ cb, float* __restrict__ out) {
    size_t idx = (size_t)blockIdx.x * blockDim.x + threadIdx.x;
    if (idx >= (size_t)MM * DD) return;
    int d = (int)(idx % DD);
    int l = (int)((idx / DD) % LL);
    float w0 = w[d * 3 + 0], w1 = w[d * 3 + 1], w2 = w[d * 3 + 2];
    float acc = cb[d] + w1 * x[idx];
    if (l > 0)      acc += w0 * x[idx - DD];
    if (l < LL - 1) acc += w2 * x[idx + DD];
    out[idx] = acc;
}

__global__ void scanA_kernel(const float* __restrict__ u, float* __restrict__ part) {
    int tid = blockIdx.x * blockDim.x + threadIdx.x;
    if (tid >= BB * NCH * RR) return;
    int r = tid % RR;
    int c = (tid / RR) % NCH;
    int b = tid / (RR * NCH);
    size_t base = ((size_t)b * LL + c * CHL) * RR + r;
    float s = 0.0f;
    for (int l = 0; l < CHL; l++) s += u[base + (size_t)l * RR];
    part[((size_t)b * NCH + c) * RR + r] = s;
}

__global__ void scanB_kernel(float* __restrict__ part) {
    int tid = blockIdx.x * blockDim.x + threadIdx.x;
    if (tid >= BB * RR) return;
    int r = tid % RR;
    int b = tid / RR;
    float run = 0.0f;
    for (int c = 0; c < NCH; c++) {
        size_t idx = ((size_t)b * NCH + c) * RR + r;
        float t = part[idx];
        part[idx] = run;
        run += t;
    }
}

__global__ void scanC_kernel(const float* __restrict__ u, const float* __restrict__ v,
                             const float* __restrict__ part,
                             __nv_bfloat16* __restrict__ ghi, __nv_bfloat16* __restrict__ glo) {
    int tid = blockIdx.x * blockDim.x + threadIdx.x;
    if (tid >= BB * NCH * RR) return;
    int r = tid % RR;
    int c = (tid / RR) % NCH;
    int b = tid / (RR * NCH);
    float acc = part[((size_t)b * NCH + c) * RR + r];
    size_t base = ((size_t)b * LL + c * CHL) * RR + r;
    for (int l = 0; l < CHL; l++) {
        size_t idx = base + (size_t)l * RR;
        acc += u[idx];
        float go = acc * v[idx];
        __nv_bfloat16 h = __float2bfloat16(go);
        ghi[idx] = h;
        glo[idx] = __float2bfloat16(go - __bfloat162float(h));
    }
}

// ---------------------------------------------------------------------------
extern "C" void kernel_launch(void* const* d_in, const int* in_sizes, int n_in,
                              void* d_out, int out_size) {
    const float* x      = (const float*)d_in[0];
    const float* Wu     = (const float*)d_in[1];
    const float* bu     = (const float*)d_in[2];
    const float* Wv     = (const float*)d_in[3];
    const float* bv     = (const float*)d_in[4];
    const float* Wg1    = (const float*)d_in[5];
    const float* bg1    = (const float*)d_in[6];
    const float* Wg2    = (const float*)d_in[7];
    const float* bg2    = (const float*)d_in[8];
    const float* conv_w = (const float*)d_in[9];
    const float* conv_b = (const float*)d_in[10];
    float* out = (float*)d_out;

    __nv_bfloat16 *xhi, *xlo, *wuhi, *wulo, *wvhi, *wvlo, *wg1hi,
                  *wg2hi, *hhi, *ghi, *glo;
    float *pu, *pv, *ppart;
    cudaGetSymbolAddress((void**)&xhi, g_xhi);     cudaGetSymbolAddress((void**)&xlo, g_xlo);
    cudaGetSymbolAddress((void**)&wuhi, g_wuhi);   cudaGetSymbolAddress((void**)&wulo, g_wulo);
    cudaGetSymbolAddress((void**)&wvhi, g_wvhi);   cudaGetSymbolAddress((void**)&wvlo, g_wvlo);
    cudaGetSymbolAddress((void**)&wg1hi, g_wg1hi);
    cudaGetSymbolAddress((void**)&wg2hi, g_wg2hi);
    cudaGetSymbolAddress((void**)&hhi, g_hhi);
    cudaGetSymbolAddress((void**)&ghi, g_ghi);     cudaGetSymbolAddress((void**)&glo, g_glo);
    cudaGetSymbolAddress((void**)&pu, g_u);        cudaGetSymbolAddress((void**)&pv, g_v);
    cudaGetSymbolAddress((void**)&ppart, g_part);

    cudaFuncSetAttribute(bsgemm<0,3,true>,  cudaFuncAttributeMaxDynamicSharedMemorySize, SMEM_TOTAL);
    cudaFuncSetAttribute(bsgemm<1,1,false>, cudaFuncAttributeMaxDynamicSharedMemorySize, SMEM_TOTAL);
    cudaFuncSetAttribute(bsgemm<2,1,false>, cudaFuncAttributeMaxDynamicSharedMemorySize, SMEM_TOTAL);
    cudaFuncSetAttribute(bsgemm<3,3,false>, cudaFuncAttributeMaxDynamicSharedMemorySize, SMEM_TOTAL);

    // splits for big GEMMs
    split_kernel<<<(unsigned)((size_t)MM * DD / 4 / 256), 256>>>(x, xhi, xlo, (size_t)MM * DD);
    split_kernel<<<(unsigned)((size_t)RR * DD / 4 / 256), 256>>>(Wu, wuhi, wulo, (size_t)RR * DD);
    split_kernel<<<(unsigned)((size_t)RR * DD / 4 / 256), 256>>>(Wv, wvhi, wvlo, (size_t)RR * DD);

    // dual u/v GEMM: z=0 -> u (Wu,bu), z=1 -> v (Wv,bv).  1024 CTAs: ~1.3% tail.
    bsgemm<0,3,true><<<dim3(RR / TBN, MM / TBM, 2), 256, SMEM_TOTAL>>>(
        xhi, xlo, wuhi, wulo, bu, pu, nullptr, nullptr,
        wvhi, wvlo, bv, pv, MM, RR, DD);

    // gate path (plain bf16, single pass)
    split_kernel<<<(unsigned)((size_t)DHH * DD / 4 / 256), 256>>>(Wg1, wg1hi, nullptr, (size_t)DHH * DD);
    split_kernel<<<(unsigned)((size_t)RR * DHH / 4 / 256), 256>>>(Wg2, wg2hi, nullptr, (size_t)RR * DHH);
    // h = relu(x Wg1^T + bg1) -> bf16
    bsgemm<1,1,false><<<dim3(DHH / TBN, MM / TBM), 256, SMEM_TOTAL>>>(
        xhi, nullptr, wg1hi, nullptr, bg1, nullptr, nullptr, hhi,
        nullptr, nullptr, nullptr, nullptr, MM, DHH, DD);
    // gates = sigmoid(h Wg2^T + bg2); u *= g; v *= g
    bsgemm<2,1,false><<<dim3(RR / TBN, MM / TBM), 256, SMEM_TOTAL>>>(
        hhi, nullptr, wg2hi, nullptr, bg2, pu, pv, nullptr,
        nullptr, nullptr, nullptr, nullptr, MM, RR, DHH);

    // conv -> out (T term)
    conv_kernel<<<(unsigned)(((size_t)MM * DD + 255) / 256), 256>>>(x, conv_w, conv_b, out);

    // cumsum over L; global_out = cumsum(u_gated) * v_gated -> bf16 split
    scanA_kernel<<<(BB * NCH * RR + 255) / 256, 256>>>(pu, ppart);
    scanB_kernel<<<(BB * RR + 255) / 256, 256>>>(ppart);
    scanC_kernel<<<(BB * NCH * RR + 255) / 256, 256>>>(pu, pv, ppart, ghi, glo);

    // out += global_out @ B where B[n=d][k=r] = Wu[d][r] -> the Wu buffer itself
    bsgemm<3,3,false><<<dim3(DD / TBN, MM / TBM), 256, SMEM_TOTAL>>>(
        ghi, glo, wuhi, wulo, nullptr, out, nullptr, nullptr,
        nullptr, nullptr, nullptr, nullptr, MM, DD, RR);
}

// round 8
// speedup vs baseline: 1.4145x; 1.0506x over previous
#include <cuda_runtime.h>
#include <cuda_bf16.h>
#include <cstdint>
#include <math.h>

// ---------------- problem constants ----------------
#define BB 4
#define LL 2048
#define DD 2048
#define RR 2048
#define DHH 512
#define MM (BB * LL)          // 8192
#define NCH 16
#define CHL (LL / NCH)        // 128

// ---------------- GEMM tiling ----------------
// CTA tile 256x128, 8 warps (4x2), warp tile 64x64, BK=64 bf16 (128B rows)
#define TBM 256
#define TBN 128
#define TBK 64
#define A_TILE 32768          // 256 rows * 128B
#define B_TILE 16384          // 128 rows * 128B
#define STAGE_BYTES (2 * A_TILE + 2 * B_TILE)   // 98304
#define NSTAGE 2
#define SMEM_TOTAL (NSTAGE * STAGE_BYTES)       // 196608

// ---------------- device scratch ----------------
__device__ __nv_bfloat16 g_xhi[(size_t)MM * DD], g_xlo[(size_t)MM * DD];
__device__ __nv_bfloat16 g_wuhi[(size_t)RR * DD], g_wulo[(size_t)RR * DD];
__device__ __nv_bfloat16 g_wvhi[(size_t)RR * DD], g_wvlo[(size_t)RR * DD];
__device__ __nv_bfloat16 g_wg1hi[(size_t)DHH * DD];
__device__ __nv_bfloat16 g_wg2hi[(size_t)RR * DHH];
__device__ __nv_bfloat16 g_hhi[(size_t)MM * DHH];
__device__ __nv_bfloat16 g_ghi[(size_t)MM * RR], g_glo[(size_t)MM * RR];
__device__ float g_u[(size_t)MM * RR];
__device__ float g_v[(size_t)MM * RR];
__device__ float g_g[(size_t)MM * RR];          // gate values (fp32)
__device__ float g_part[(size_t)BB * NCH * RR];

// ---------------- PTX helpers (arch-agnostic only) ----------------
__device__ __forceinline__ uint32_t smem_u32(const void* p) {
    uint32_t a;
    asm("{ .reg .u64 t; cvta.to.shared.u64 t, %1; cvt.u32.u64 %0, t; }" : "=r"(a) : "l"(p));
    return a;
}
__device__ __forceinline__ void cp16(uint32_t dst, const void* src) {
    asm volatile("cp.async.cg.shared.global [%0], [%1], 16;" :: "r"(dst), "l"(src));
}
#define CP_COMMIT() asm volatile("cp.async.commit_group;" ::: "memory")
#define CP_WAIT(n)  asm volatile("cp.async.wait_group %0;" :: "n"(n) : "memory")

#define LDSM4(r, addr) \
    asm volatile("ldmatrix.sync.aligned.m8n8.x4.shared.b16 {%0,%1,%2,%3}, [%4];" \
        : "=r"((r)[0]), "=r"((r)[1]), "=r"((r)[2]), "=r"((r)[3]) : "r"(addr))

__device__ __forceinline__ void mma16816(float* c, const uint32_t* a, uint32_t b0, uint32_t b1) {
    asm volatile(
        "mma.sync.aligned.m16n8k16.row.col.f32.bf16.bf16.f32 "
        "{%0,%1,%2,%3}, {%4,%5,%6,%7}, {%8,%9}, {%0,%1,%2,%3};"
        : "+f"(c[0]), "+f"(c[1]), "+f"(c[2]), "+f"(c[3])
        : "r"(a[0]), "r"(a[1]), "r"(a[2]), "r"(a[3]), "r"(b0), "r"(b1));
}

// SW128 swizzle for 128B rows: (row, 16B-chunk c in 0..7)
__device__ __forceinline__ uint32_t swz(int r, int c) {
    return (uint32_t)(r * 128 + ((c ^ (r & 7)) << 4));
}

// load one 64-K chunk's tiles into a stage (lo planes only when SPLIT)
template <bool SPLIT>
__device__ __forceinline__ void load_ab(uint32_t st,
                                        const __nv_bfloat16* __restrict__ Ahi,
                                        const __nv_bfloat16* __restrict__ Alo,
                                        const __nv_bfloat16* __restrict__ Bhi,
                                        const __nv_bfloat16* __restrict__ Blo,
                                        int K, int row0, int col0, int k0, int tid) {
#pragma unroll
    for (int i = 0; i < 8; i++) {                 // A: 256 rows x 8 chunks of 16B
        int id = tid + i * 256;
        int r = id >> 3, c = id & 7;
        uint32_t dst = st + swz(r, c);
        size_t srcoff = (size_t)(row0 + r) * K + k0 + c * 8;
        cp16(dst, Ahi + srcoff);
        if (SPLIT) cp16(dst + A_TILE, Alo + srcoff);
    }
#pragma unroll
    for (int i = 0; i < 4; i++) {                 // B: 128 rows x 8 chunks
        int id = tid + i * 256;
        int r = id >> 3, c = id & 7;
        uint32_t dst = st + 2 * A_TILE + swz(r, c);
        size_t srcoff = (size_t)(col0 + r) * K + k0 + c * 8;
        cp16(dst, Bhi + srcoff);
        if (SPLIT) cp16(dst + B_TILE, Blo + srcoff);
    }
}

// ---------------------------------------------------------------------------
// bf16(-split) warp-MMA GEMM: C[m,n] = sum_k A[m,k]*B[n,k]
// NPASS 3: hi*hi + lo*hi + hi*lo ; NPASS 1: hi*hi
// DUAL: blockIdx.z selects (B,bias,C) pair (EPI 0 only)
// EPI 0: C = z + bias
// EPI 1: relu(z + bias) -> bf16 (Ohi)
// EPI 2: g = sigmoid(z + bias); write gbuf; part[b,chunk,r] = sum_l u*g (fused scanA)
// EPI 3: C = depthwise_conv3(x) + z   (conv fused, no pre-pass)
// ---------------------------------------------------------------------------
template <int EPI, int NPASS, bool DUAL>
__global__ __launch_bounds__(256)
void bsgemm(const __nv_bfloat16* __restrict__ Ahi, const __nv_bfloat16* __restrict__ Alo,
            const __nv_bfloat16* __restrict__ Bhi_, const __nv_bfloat16* __restrict__ Blo_,
            const float* __restrict__ bias_,
            float* __restrict__ C_, float* __restrict__ C2,
            __nv_bfloat16* __restrict__ Ohi,
            const __nv_bfloat16* __restrict__ Bhi2, const __nv_bfloat16* __restrict__ Blo2,
            const float* __restrict__ bias2, float* __restrict__ Cd2,
            const float* __restrict__ cw, const float* __restrict__ cb,
            const float* __restrict__ xp,
            float* __restrict__ gbuf, float* __restrict__ part,
            int M, int N, int K) {
    extern __shared__ __align__(128) char smem[];
    const uint32_t sb = smem_u32(smem);
    const int tid  = threadIdx.x;
    const int wid  = tid >> 5;
    const int lane = tid & 31;
    const int wm = wid >> 1;          // 0..3 (m)
    const int wn = wid & 1;           // 0..1 (n)
    const int row0 = blockIdx.y * TBM;
    const int col0 = blockIdx.x * TBN;
    const int nchunks = K / TBK;
    constexpr bool SPLIT = (NPASS == 3);

    const __nv_bfloat16* Bhi = Bhi_;
    const __nv_bfloat16* Blo = Blo_;
    const float* bias = bias_;
    float* C = C_;
    if (DUAL && blockIdx.z == 1) { Bhi = Bhi2; Blo = Blo2; bias = bias2; C = Cd2; }

    // ldmatrix lane mapping
    const int lr = lane & 7;
    const int j  = lane >> 3;
    const int arow  = ((j & 1) << 3) + lr;
    const int acsel = j >> 1;
    const int brow  = ((j >> 1) << 3) + lr;
    const int bcsel = j & 1;

    float acc[4][8][4];
#pragma unroll
    for (int mi = 0; mi < 4; mi++)
#pragma unroll
        for (int nj = 0; nj < 8; nj++)
#pragma unroll
            for (int q = 0; q < 4; q++) acc[mi][nj][q] = 0.0f;

    // prologue: chunk 0 into stage 0
    load_ab<SPLIT>(sb, Ahi, Alo, Bhi, Blo, K, row0, col0, 0, tid);
    CP_COMMIT();

    for (int c = 0; c < nchunks; c++) {
        CP_WAIT(0);
        __syncthreads();

        if (c + 1 < nchunks) {
            load_ab<SPLIT>(sb + ((c + 1) & 1) * STAGE_BYTES, Ahi, Alo, Bhi, Blo,
                           K, row0, col0, (c + 1) * TBK, tid);
            CP_COMMIT();
        }

        const uint32_t sA = sb + (c & 1) * STAGE_BYTES;
        const uint32_t sB = sA + 2 * A_TILE;

#pragma unroll
        for (int s = 0; s < 4; s++) {
            uint32_t ah[4][4], bh[4][4], fx[4][4];
            uint32_t adA[4], adB[4];
#pragma unroll
            for (int mi = 0; mi < 4; mi++) {
                int r = wm * 64 + mi * 16 + arow;
                adA[mi] = sA + swz(r, 2 * s + acsel);
                LDSM4(ah[mi], adA[mi]);
            }
#pragma unroll
            for (int p = 0; p < 4; p++) {
                int r = wn * 64 + p * 16 + brow;
                adB[p] = sB + swz(r, 2 * s + bcsel);
                LDSM4(bh[p], adB[p]);
            }
#pragma unroll
            for (int mi = 0; mi < 4; mi++)
#pragma unroll
                for (int nj = 0; nj < 8; nj++)
                    mma16816(acc[mi][nj], ah[mi], bh[nj >> 1][(nj & 1) * 2], bh[nj >> 1][(nj & 1) * 2 + 1]);
            if (NPASS == 3) {
#pragma unroll
                for (int mi = 0; mi < 4; mi++) LDSM4(fx[mi], adA[mi] + A_TILE);
#pragma unroll
                for (int mi = 0; mi < 4; mi++)
#pragma unroll
                    for (int nj = 0; nj < 8; nj++)
                        mma16816(acc[mi][nj], fx[mi], bh[nj >> 1][(nj & 1) * 2], bh[nj >> 1][(nj & 1) * 2 + 1]);
#pragma unroll
                for (int p = 0; p < 4; p++) LDSM4(fx[p], adB[p] + B_TILE);
#pragma unroll
                for (int mi = 0; mi < 4; mi++)
#pragma unroll
                    for (int nj = 0; nj < 8; nj++)
                        mma16816(acc[mi][nj], ah[mi], fx[nj >> 1][(nj & 1) * 2], fx[nj >> 1][(nj & 1) * 2 + 1]);
            }
        }
    }

    // -------- epilogue --------
    const int g_ = lane >> 2, t = lane & 3;
    float psum[8][2];
    if (EPI == 2) {
#pragma unroll
        for (int nj = 0; nj < 8; nj++) { psum[nj][0] = 0.0f; psum[nj][1] = 0.0f; }
    }
#pragma unroll
    for (int mi = 0; mi < 4; mi++) {
#pragma unroll
        for (int nj = 0; nj < 8; nj++) {
            int row = row0 + wm * 64 + mi * 16 + g_;
            int col = col0 + wn * 64 + nj * 8 + 2 * t;
            size_t i0 = (size_t)row * N + col;
            size_t i1 = (size_t)(row + 8) * N + col;
            float* z = acc[mi][nj];
            if (EPI == 0) {
                float b0 = bias[col], b1 = bias[col + 1];
                *(float2*)(C + i0) = make_float2(z[0] + b0, z[1] + b1);
                *(float2*)(C + i1) = make_float2(z[2] + b0, z[3] + b1);
            } else if (EPI == 1) {
                float b0 = bias[col], b1 = bias[col + 1];
                float v0 = fmaxf(z[0] + b0, 0.0f), v1 = fmaxf(z[1] + b1, 0.0f);
                float v2 = fmaxf(z[2] + b0, 0.0f), v3 = fmaxf(z[3] + b1, 0.0f);
                *(__nv_bfloat162*)(Ohi + i0) = __halves2bfloat162(__float2bfloat16(v0), __float2bfloat16(v1));
                *(__nv_bfloat162*)(Ohi + i1) = __halves2bfloat162(__float2bfloat16(v2), __float2bfloat16(v3));
            } else if (EPI == 2) {
                float b0 = bias[col], b1 = bias[col + 1];
                float g0 = 1.0f / (1.0f + __expf(-(z[0] + b0)));
                float g1 = 1.0f / (1.0f + __expf(-(z[1] + b1)));
                float g2 = 1.0f / (1.0f + __expf(-(z[2] + b0)));
                float g3 = 1.0f / (1.0f + __expf(-(z[3] + b1)));
                float2 u0 = *(float2*)(C + i0), u1 = *(float2*)(C + i1);
                *(float2*)(gbuf + i0) = make_float2(g0, g1);
                *(float2*)(gbuf + i1) = make_float2(g2, g3);
                psum[nj][0] += u0.x * g0 + u1.x * g2;
                psum[nj][1] += u0.y * g1 + u1.y * g3;
            } else {  // EPI == 3: out = conv3(x) + z
                int l0 = row & (LL - 1);
                int l1 = l0 + 8;
                float w0a = cw[3 * col + 0], w1a = cw[3 * col + 1], w2a = cw[3 * col + 2];
                float w0b = cw[3 * col + 3], w1b = cw[3 * col + 4], w2b = cw[3 * col + 5];
                float cb0 = cb[col], cb1 = cb[col + 1];
                const float* xr0 = xp + i0;
                const float* xr1 = xp + i1;
                float2 xc0 = *(const float2*)xr0;
                float2 xc1 = *(const float2*)xr1;
                float2 xq0 = *(const float2*)(xr0 + N);   // l0 <= LL-9, always valid
                float2 xm1 = *(const float2*)(xr1 - N);   // l1 >= 8, always valid
                float2 xm0 = (l0 > 0)      ? *(const float2*)(xr0 - N) : make_float2(0.f, 0.f);
                float2 xq1 = (l1 < LL - 1) ? *(const float2*)(xr1 + N) : make_float2(0.f, 0.f);
                float o0 = cb0 + w1a * xc0.x + w2a * xq0.x + z[0] + (l0 > 0 ? w0a * xm0.x : 0.f);
                float o1 = cb1 + w1b * xc0.y + w2b * xq0.y + z[1] + (l0 > 0 ? w0b * xm0.y : 0.f);
                float o2 = cb0 + w1a * xc1.x + w0a * xm1.x + z[2] + (l1 < LL - 1 ? w2a * xq1.x : 0.f);
                float o3 = cb1 + w1b * xc1.y + w0b * xm1.y + z[3] + (l1 < LL - 1 ? w2b * xq1.y : 0.f);
                *(float2*)(C + i0) = make_float2(o0, o1);
                *(float2*)(C + i1) = make_float2(o2, o3);
            }
        }
    }

    if (EPI == 2) {
        // warp tree-reduce over the 8 g_ groups (lane bits 2..4)
#pragma unroll
        for (int nj = 0; nj < 8; nj++) {
#pragma unroll
            for (int k = 0; k < 2; k++) {
                float v = psum[nj][k];
                v += __shfl_xor_sync(0xffffffffu, v, 4);
                v += __shfl_xor_sync(0xffffffffu, v, 8);
                v += __shfl_xor_sync(0xffffffffu, v, 16);
                psum[nj][k] = v;
            }
        }
        __syncthreads();                 // smem no longer needed by mainloop
        float* red = (float*)smem;       // [4 wm][128 cols]
        if (lane < 4) {
#pragma unroll
            for (int nj = 0; nj < 8; nj++) {
                red[wm * 128 + wn * 64 + nj * 8 + 2 * lane + 0] = psum[nj][0];
                red[wm * 128 + wn * 64 + nj * 8 + 2 * lane + 1] = psum[nj][1];
            }
        }
        __syncthreads();
        {
            int ch = tid >> 7, cl = tid & 127;
            float s = red[(2 * ch) * 128 + cl] + red[(2 * ch + 1) * 128 + cl];
            int bidx = row0 >> 11;                 // /2048
            int cbase = (row0 & (LL - 1)) >> 7;    // /128
            part[((size_t)bidx * NCH + cbase + ch) * (size_t)N + col0 + cl] = s;
        }
    }
}

// ---------------------------------------------------------------------------
// elementwise kernels
// ---------------------------------------------------------------------------
__global__ void split_kernel(const float* __restrict__ s, __nv_bfloat16* __restrict__ hi,
                             __nv_bfloat16* __restrict__ lo, size_t n) {
    size_t i = ((size_t)blockIdx.x * blockDim.x + threadIdx.x) * 4;
    if (i >= n) return;
    float4 v = *(const float4*)(s + i);
    __nv_bfloat16 h0 = __float2bfloat16(v.x), h1 = __float2bfloat16(v.y);
    __nv_bfloat16 h2 = __float2bfloat16(v.z), h3 = __float2bfloat16(v.w);
    *(__nv_bfloat162*)(hi + i)     = __halves2bfloat162(h0, h1);
    *(__nv_bfloat162*)(hi + i + 2) = __halves2bfloat162(h2, h3);
    if (lo != nullptr) {
        *(__nv_bfloat162*)(lo + i)     = __halves2bfloat162(
            __float2bfloat16(v.x - __bfloat162float(h0)), __float2bfloat16(v.y - __bfloat162float(h1)));
        *(__nv_bfloat162*)(lo + i + 2) = __halves2bfloat162(
            __float2bfloat16(v.z - __bfloat162float(h2)), __float2bfloat16(v.w - __bfloat162float(h3)));
    }
}

__global__ void scanB_kernel(float* __restrict__ part) {
    int tid = blockIdx.x * blockDim.x + threadIdx.x;
    if (tid >= BB * RR) return;
    int r = tid % RR;
    int b = tid / RR;
    float run = 0.0f;
    for (int c = 0; c < NCH; c++) {
        size_t idx = ((size_t)b * NCH + c) * RR + r;
        float t = part[idx];
        part[idx] = run;
        run += t;
    }
}

// apply gates + cumsum + multiply; write global_out as bf16 hi/lo split
__global__ void scanC_kernel(const float* __restrict__ u, const float* __restrict__ v,
                             const float* __restrict__ g, const float* __restrict__ part,
                             __nv_bfloat16* __restrict__ ghi, __nv_bfloat16* __restrict__ glo) {
    int tid = blockIdx.x * blockDim.x + threadIdx.x;
    if (tid >= BB * NCH * RR) return;
    int r = tid % RR;
    int c = (tid / RR) % NCH;
    int b = tid / (RR * NCH);
    float acc = part[((size_t)b * NCH + c) * RR + r];
    size_t base = ((size_t)b * LL + c * CHL) * RR + r;
    for (int l = 0; l < CHL; l++) {
        size_t idx = base + (size_t)l * RR;
        float gg = g[idx];
        acc += u[idx] * gg;
        float go = acc * (v[idx] * gg);
        __nv_bfloat16 h = __float2bfloat16(go);
        ghi[idx] = h;
        glo[idx] = __float2bfloat16(go - __bfloat162float(h));
    }
}

// ---------------------------------------------------------------------------
extern "C" void kernel_launch(void* const* d_in, const int* in_sizes, int n_in,
                              void* d_out, int out_size) {
    const float* x      = (const float*)d_in[0];
    const float* Wu     = (const float*)d_in[1];
    const float* bu     = (const float*)d_in[2];
    const float* Wv     = (const float*)d_in[3];
    const float* bv     = (const float*)d_in[4];
    const float* Wg1    = (const float*)d_in[5];
    const float* bg1    = (const float*)d_in[6];
    const float* Wg2    = (const float*)d_in[7];
    const float* bg2    = (const float*)d_in[8];
    const float* conv_w = (const float*)d_in[9];
    const float* conv_b = (const float*)d_in[10];
    float* out = (float*)d_out;

    __nv_bfloat16 *xhi, *xlo, *wuhi, *wulo, *wvhi, *wvlo, *wg1hi,
                  *wg2hi, *hhi, *ghi, *glo;
    float *pu, *pv, *pg, *ppart;
    cudaGetSymbolAddress((void**)&xhi, g_xhi);     cudaGetSymbolAddress((void**)&xlo, g_xlo);
    cudaGetSymbolAddress((void**)&wuhi, g_wuhi);   cudaGetSymbolAddress((void**)&wulo, g_wulo);
    cudaGetSymbolAddress((void**)&wvhi, g_wvhi);   cudaGetSymbolAddress((void**)&wvlo, g_wvlo);
    cudaGetSymbolAddress((void**)&wg1hi, g_wg1hi);
    cudaGetSymbolAddress((void**)&wg2hi, g_wg2hi);
    cudaGetSymbolAddress((void**)&hhi, g_hhi);
    cudaGetSymbolAddress((void**)&ghi, g_ghi);     cudaGetSymbolAddress((void**)&glo, g_glo);
    cudaGetSymbolAddress((void**)&pu, g_u);        cudaGetSymbolAddress((void**)&pv, g_v);
    cudaGetSymbolAddress((void**)&pg, g_g);        cudaGetSymbolAddress((void**)&ppart, g_part);

    cudaFuncSetAttribute(bsgemm<0,3,true>,  cudaFuncAttributeMaxDynamicSharedMemorySize, SMEM_TOTAL);
    cudaFuncSetAttribute(bsgemm<1,1,false>, cudaFuncAttributeMaxDynamicSharedMemorySize, SMEM_TOTAL);
    cudaFuncSetAttribute(bsgemm<2,1,false>, cudaFuncAttributeMaxDynamicSharedMemorySize, SMEM_TOTAL);
    cudaFuncSetAttribute(bsgemm<3,3,false>, cudaFuncAttributeMaxDynamicSharedMemorySize, SMEM_TOTAL);

    // splits for big GEMMs (launches 1-3; keeps dual GEMM at #4 for ncu)
    split_kernel<<<(unsigned)((size_t)MM * DD / 4 / 256), 256>>>(x, xhi, xlo, (size_t)MM * DD);
    split_kernel<<<(unsigned)((size_t)RR * DD / 4 / 256), 256>>>(Wu, wuhi, wulo, (size_t)RR * DD);
    split_kernel<<<(unsigned)((size_t)RR * DD / 4 / 256), 256>>>(Wv, wvhi, wvlo, (size_t)RR * DD);

    // dual u/v GEMM: z=0 -> u (Wu,bu), z=1 -> v (Wv,bv)
    bsgemm<0,3,true><<<dim3(RR / TBN, MM / TBM, 2), 256, SMEM_TOTAL>>>(
        xhi, xlo, wuhi, wulo, bu, pu, nullptr, nullptr,
        wvhi, wvlo, bv, pv,
        nullptr, nullptr, nullptr, nullptr, nullptr, MM, RR, DD);

    // gate path (plain bf16, single pass)
    split_kernel<<<(unsigned)((size_t)DHH * DD / 4 / 256), 256>>>(Wg1, wg1hi, nullptr, (size_t)DHH * DD);
    split_kernel<<<(unsigned)((size_t)RR * DHH / 4 / 256), 256>>>(Wg2, wg2hi, nullptr, (size_t)RR * DHH);
    // h = relu(x Wg1^T + bg1) -> bf16
    bsgemm<1,1,false><<<dim3(DHH / TBN, MM / TBM), 256, SMEM_TOTAL>>>(
        xhi, nullptr, wg1hi, nullptr, bg1, nullptr, nullptr, hhi,
        nullptr, nullptr, nullptr, nullptr,
        nullptr, nullptr, nullptr, nullptr, nullptr, MM, DHH, DD);
    // gates: write g, fused chunk partial sums of u*g -> part
    bsgemm<2,1,false><<<dim3(RR / TBN, MM / TBM), 256, SMEM_TOTAL>>>(
        hhi, nullptr, wg2hi, nullptr, bg2, pu, nullptr, nullptr,
        nullptr, nullptr, nullptr, nullptr,
        nullptr, nullptr, nullptr, pg, ppart, MM, RR, DHH);

    // exclusive prefix over chunks, then apply gates + cumsum + multiply
    scanB_kernel<<<(BB * RR + 255) / 256, 256>>>(ppart);
    scanC_kernel<<<(BB * NCH * RR + 255) / 256, 256>>>(pu, pv, pg, ppart, ghi, glo);

    // out = conv3(x) + global_out @ Wu (conv fused in epilogue)
    bsgemm<3,3,false><<<dim3(DD / TBN, MM / TBM), 256, SMEM_TOTAL>>>(
        ghi, glo, wuhi, wulo, nullptr, out, nullptr, nullptr,
        nullptr, nullptr, nullptr, nullptr,
        conv_w, conv_b, x, nullptr, nullptr, MM, DD, RR);
}

// round 9
// speedup vs baseline: 1.4426x; 1.0199x over previous
#include <cuda_runtime.h>
#include <cuda_bf16.h>
#include <cstdint>
#include <math.h>

// ---------------- problem constants ----------------
#define BB 4
#define LL 2048
#define DD 2048
#define RR 2048
#define DHH 512
#define MM (BB * LL)          // 8192
#define NCH 16
#define CHL (LL / NCH)        // 128

// ---------------- GEMM tiling ----------------
// NWN = warps along n (2 or 4). Warp tile = 64 x (128/NWN).
// TBM = 64*(8/NWN) (256 or 128), TBN = 128, BK = 64 bf16 (128B rows).
#define TBN 128
#define TBK 64
#define B_TILE 16384          // 128 rows * 128B
#define NSTAGE 2
// per-NWN sizes
#define A_TILE_OF(NWN)  ((64 * (8 / (NWN))) * 128)
#define STAGE_OF(NWN)   (2 * A_TILE_OF(NWN) + 2 * B_TILE)
#define SMEM_OF(NWN)    (NSTAGE * STAGE_OF(NWN))   // NWN=2: 196608, NWN=4: 131072

// ---------------- device scratch ----------------
__device__ __nv_bfloat16 g_xhi[(size_t)MM * DD], g_xlo[(size_t)MM * DD];
__device__ __nv_bfloat16 g_wuhi[(size_t)RR * DD], g_wulo[(size_t)RR * DD];
__device__ __nv_bfloat16 g_wvhi[(size_t)RR * DD], g_wvlo[(size_t)RR * DD];
__device__ __nv_bfloat16 g_wg1hi[(size_t)DHH * DD];
__device__ __nv_bfloat16 g_wg2hi[(size_t)RR * DHH];
__device__ __nv_bfloat16 g_hhi[(size_t)MM * DHH];
__device__ __nv_bfloat16 g_ghi[(size_t)MM * RR], g_glo[(size_t)MM * RR];
__device__ float g_u[(size_t)MM * RR];
__device__ float g_v[(size_t)MM * RR];
__device__ float g_g[(size_t)MM * RR];
__device__ float g_part[(size_t)BB * NCH * RR];

// ---------------- PTX helpers (arch-agnostic only) ----------------
__device__ __forceinline__ uint32_t smem_u32(const void* p) {
    uint32_t a;
    asm("{ .reg .u64 t; cvta.to.shared.u64 t, %1; cvt.u32.u64 %0, t; }" : "=r"(a) : "l"(p));
    return a;
}
__device__ __forceinline__ void cp16(uint32_t dst, const void* src) {
    asm volatile("cp.async.cg.shared.global [%0], [%1], 16;" :: "r"(dst), "l"(src));
}
#define CP_COMMIT() asm volatile("cp.async.commit_group;" ::: "memory")
#define CP_WAIT(n)  asm volatile("cp.async.wait_group %0;" :: "n"(n) : "memory")

#define LDSM4(r, addr) \
    asm volatile("ldmatrix.sync.aligned.m8n8.x4.shared.b16 {%0,%1,%2,%3}, [%4];" \
        : "=r"((r)[0]), "=r"((r)[1]), "=r"((r)[2]), "=r"((r)[3]) : "r"(addr))

__device__ __forceinline__ void mma16816(float* c, const uint32_t* a, uint32_t b0, uint32_t b1) {
    asm volatile(
        "mma.sync.aligned.m16n8k16.row.col.f32.bf16.bf16.f32 "
        "{%0,%1,%2,%3}, {%4,%5,%6,%7}, {%8,%9}, {%0,%1,%2,%3};"
        : "+f"(c[0]), "+f"(c[1]), "+f"(c[2]), "+f"(c[3])
        : "r"(a[0]), "r"(a[1]), "r"(a[2]), "r"(a[3]), "r"(b0), "r"(b1));
}

// SW128 swizzle for 128B rows: (row, 16B-chunk c in 0..7)
__device__ __forceinline__ uint32_t swz(int r, int c) {
    return (uint32_t)(r * 128 + ((c ^ (r & 7)) << 4));
}

// load one 64-K chunk's tiles into a stage (lo planes only when SPLIT)
template <bool SPLIT, int TBM_, int A_TILE_>
__device__ __forceinline__ void load_ab(uint32_t st,
                                        const __nv_bfloat16* __restrict__ Ahi,
                                        const __nv_bfloat16* __restrict__ Alo,
                                        const __nv_bfloat16* __restrict__ Bhi,
                                        const __nv_bfloat16* __restrict__ Blo,
                                        int K, int row0, int col0, int k0, int tid) {
#pragma unroll
    for (int i = 0; i < TBM_ / 32; i++) {         // A: TBM_ rows x 8 chunks of 16B
        int id = tid + i * 256;
        int r = id >> 3, c = id & 7;
        uint32_t dst = st + swz(r, c);
        size_t srcoff = (size_t)(row0 + r) * K + k0 + c * 8;
        cp16(dst, Ahi + srcoff);
        if (SPLIT) cp16(dst + A_TILE_, Alo + srcoff);
    }
#pragma unroll
    for (int i = 0; i < 4; i++) {                 // B: 128 rows x 8 chunks
        int id = tid + i * 256;
        int r = id >> 3, c = id & 7;
        uint32_t dst = st + 2 * A_TILE_ + swz(r, c);
        size_t srcoff = (size_t)(col0 + r) * K + k0 + c * 8;
        cp16(dst, Bhi + srcoff);
        if (SPLIT) cp16(dst + B_TILE, Blo + srcoff);
    }
}

// ---------------------------------------------------------------------------
// bf16(-split) warp-MMA GEMM: C[m,n] = sum_k A[m,k]*B[n,k]
// NPASS 3: hi*hi + lo*hi + hi*lo ; NPASS 1: hi*hi
// DUAL: blockIdx.z selects (B,bias,C) pair (EPI 0 only)
// NWN: warps along n (2 -> 256x128 CTA, 4 -> 128x128 CTA)
// EPI 0: C = z + bias
// EPI 1: relu(z + bias) -> bf16 (Ohi)
// EPI 2: g = sigmoid(z + bias); write gbuf; part = chunk sums of u*g (NWN=2 only)
// EPI 3: C = depthwise_conv3(x) + z
// ---------------------------------------------------------------------------
template <int EPI, int NPASS, bool DUAL, int NWN>
__global__ __launch_bounds__(256)
void bsgemm(const __nv_bfloat16* __restrict__ Ahi, const __nv_bfloat16* __restrict__ Alo,
            const __nv_bfloat16* __restrict__ Bhi_, const __nv_bfloat16* __restrict__ Blo_,
            const float* __restrict__ bias_,
            float* __restrict__ C_, float* __restrict__ C2,
            __nv_bfloat16* __restrict__ Ohi,
            const __nv_bfloat16* __restrict__ Bhi2, const __nv_bfloat16* __restrict__ Blo2,
            const float* __restrict__ bias2, float* __restrict__ Cd2,
            const float* __restrict__ cw, const float* __restrict__ cb,
            const float* __restrict__ xp,
            float* __restrict__ gbuf, float* __restrict__ part,
            int M, int N, int K) {
    constexpr int TBM_    = 64 * (8 / NWN);
    constexpr int A_TILE_ = TBM_ * 128;
    constexpr int STAGE_  = 2 * A_TILE_ + 2 * B_TILE;
    constexpr int WNT     = 128 / NWN;    // warp n-tile
    constexpr int NJ      = WNT / 8;      // 8 or 4
    constexpr int PB      = NJ / 2;       // B frags: 4 or 2
    constexpr bool SPLIT  = (NPASS == 3);

    extern __shared__ __align__(128) char smem[];
    const uint32_t sb = smem_u32(smem);
    const int tid  = threadIdx.x;
    const int wid  = tid >> 5;
    const int lane = tid & 31;
    const int wm = wid / NWN;
    const int wn = wid % NWN;
    const int row0 = blockIdx.y * TBM_;
    const int col0 = blockIdx.x * TBN;
    const int nchunks = K / TBK;

    const __nv_bfloat16* Bhi = Bhi_;
    const __nv_bfloat16* Blo = Blo_;
    const float* bias = bias_;
    float* C = C_;
    if (DUAL && blockIdx.z == 1) { Bhi = Bhi2; Blo = Blo2; bias = bias2; C = Cd2; }

    // ldmatrix lane mapping
    const int lr = lane & 7;
    const int j  = lane >> 3;
    const int arow  = ((j & 1) << 3) + lr;
    const int acsel = j >> 1;
    const int brow  = ((j >> 1) << 3) + lr;
    const int bcsel = j & 1;

    float acc[4][NJ][4];
#pragma unroll
    for (int mi = 0; mi < 4; mi++)
#pragma unroll
        for (int nj = 0; nj < NJ; nj++)
#pragma unroll
            for (int q = 0; q < 4; q++) acc[mi][nj][q] = 0.0f;

    // prologue: chunk 0 into stage 0
    load_ab<SPLIT, TBM_, A_TILE_>(sb, Ahi, Alo, Bhi, Blo, K, row0, col0, 0, tid);
    CP_COMMIT();

    for (int c = 0; c < nchunks; c++) {
        CP_WAIT(0);
        __syncthreads();

        if (c + 1 < nchunks) {
            load_ab<SPLIT, TBM_, A_TILE_>(sb + ((c + 1) & 1) * STAGE_, Ahi, Alo, Bhi, Blo,
                                          K, row0, col0, (c + 1) * TBK, tid);
            CP_COMMIT();
        }

        const uint32_t sA = sb + (c & 1) * STAGE_;
        const uint32_t sB = sA + 2 * A_TILE_;

#pragma unroll
        for (int s = 0; s < 4; s++) {
            uint32_t ah[4][4], bh[4][4], fx[4][4];
            uint32_t adA[4], adB[4];
#pragma unroll
            for (int mi = 0; mi < 4; mi++) {
                int r = wm * 64 + mi * 16 + arow;
                adA[mi] = sA + swz(r, 2 * s + acsel);
                LDSM4(ah[mi], adA[mi]);
            }
#pragma unroll
            for (int p = 0; p < PB; p++) {
                int r = wn * WNT + p * 16 + brow;
                adB[p] = sB + swz(r, 2 * s + bcsel);
                LDSM4(bh[p], adB[p]);
            }
#pragma unroll
            for (int mi = 0; mi < 4; mi++)
#pragma unroll
                for (int nj = 0; nj < NJ; nj++)
                    mma16816(acc[mi][nj], ah[mi], bh[nj >> 1][(nj & 1) * 2], bh[nj >> 1][(nj & 1) * 2 + 1]);
            if (NPASS == 3) {
#pragma unroll
                for (int mi = 0; mi < 4; mi++) LDSM4(fx[mi], adA[mi] + A_TILE_);
#pragma unroll
                for (int mi = 0; mi < 4; mi++)
#pragma unroll
                    for (int nj = 0; nj < NJ; nj++)
                        mma16816(acc[mi][nj], fx[mi], bh[nj >> 1][(nj & 1) * 2], bh[nj >> 1][(nj & 1) * 2 + 1]);
#pragma unroll
                for (int p = 0; p < PB; p++) LDSM4(fx[p], adB[p] + B_TILE);
#pragma unroll
                for (int mi = 0; mi < 4; mi++)
#pragma unroll
                    for (int nj = 0; nj < NJ; nj++)
                        mma16816(acc[mi][nj], ah[mi], fx[nj >> 1][(nj & 1) * 2], fx[nj >> 1][(nj & 1) * 2 + 1]);
            }
        }
    }

    // -------- epilogue --------
    const int g_ = lane >> 2, t = lane & 3;
    float psum[NJ][2];
    if (EPI == 2) {
#pragma unroll
        for (int nj = 0; nj < NJ; nj++) { psum[nj][0] = 0.0f; psum[nj][1] = 0.0f; }
    }
#pragma unroll
    for (int mi = 0; mi < 4; mi++) {
#pragma unroll
        for (int nj = 0; nj < NJ; nj++) {
            int row = row0 + wm * 64 + mi * 16 + g_;
            int col = col0 + wn * WNT + nj * 8 + 2 * t;
            size_t i0 = (size_t)row * N + col;
            size_t i1 = (size_t)(row + 8) * N + col;
            float* z = acc[mi][nj];
            if (EPI == 0) {
                float b0 = bias[col], b1 = bias[col + 1];
                *(float2*)(C + i0) = make_float2(z[0] + b0, z[1] + b1);
                *(float2*)(C + i1) = make_float2(z[2] + b0, z[3] + b1);
            } else if (EPI == 1) {
                float b0 = bias[col], b1 = bias[col + 1];
                float v0 = fmaxf(z[0] + b0, 0.0f), v1 = fmaxf(z[1] + b1, 0.0f);
                float v2 = fmaxf(z[2] + b0, 0.0f), v3 = fmaxf(z[3] + b1, 0.0f);
                *(__nv_bfloat162*)(Ohi + i0) = __halves2bfloat162(__float2bfloat16(v0), __float2bfloat16(v1));
                *(__nv_bfloat162*)(Ohi + i1) = __halves2bfloat162(__float2bfloat16(v2), __float2bfloat16(v3));
            } else if (EPI == 2) {
                float b0 = bias[col], b1 = bias[col + 1];
                float g0 = 1.0f / (1.0f + __expf(-(z[0] + b0)));
                float g1 = 1.0f / (1.0f + __expf(-(z[1] + b1)));
                float g2 = 1.0f / (1.0f + __expf(-(z[2] + b0)));
                float g3 = 1.0f / (1.0f + __expf(-(z[3] + b1)));
                float2 u0 = *(float2*)(C + i0), u1 = *(float2*)(C + i1);
                *(float2*)(gbuf + i0) = make_float2(g0, g1);
                *(float2*)(gbuf + i1) = make_float2(g2, g3);
                psum[nj][0] += u0.x * g0 + u1.x * g2;
                psum[nj][1] += u0.y * g1 + u1.y * g3;
            } else {  // EPI == 3: out = conv3(x) + z
                int l0 = row & (LL - 1);
                int l1 = l0 + 8;
                float w0a = cw[3 * col + 0], w1a = cw[3 * col + 1], w2a = cw[3 * col + 2];
                float w0b = cw[3 * col + 3], w1b = cw[3 * col + 4], w2b = cw[3 * col + 5];
                float cb0 = cb[col], cb1 = cb[col + 1];
                const float* xr0 = xp + i0;
                const float* xr1 = xp + i1;
                float2 xc0 = *(const float2*)xr0;
                float2 xc1 = *(const float2*)xr1;
                float2 xq0 = *(const float2*)(xr0 + N);
                float2 xm1 = *(const float2*)(xr1 - N);
                float2 xm0 = (l0 > 0)      ? *(const float2*)(xr0 - N) : make_float2(0.f, 0.f);
                float2 xq1 = (l1 < LL - 1) ? *(const float2*)(xr1 + N) : make_float2(0.f, 0.f);
                float o0 = cb0 + w1a * xc0.x + w2a * xq0.x + z[0] + (l0 > 0 ? w0a * xm0.x : 0.f);
                float o1 = cb1 + w1b * xc0.y + w2b * xq0.y + z[1] + (l0 > 0 ? w0b * xm0.y : 0.f);
                float o2 = cb0 + w1a * xc1.x + w0a * xm1.x + z[2] + (l1 < LL - 1 ? w2a * xq1.x : 0.f);
                float o3 = cb1 + w1b * xc1.y + w0b * xm1.y + z[3] + (l1 < LL - 1 ? w2b * xq1.y : 0.f);
                *(float2*)(C + i0) = make_float2(o0, o1);
                *(float2*)(C + i1) = make_float2(o2, o3);
            }
        }
    }

    if (EPI == 2) {   // only instantiated with NWN=2 (TBM_=256)
#pragma unroll
        for (int nj = 0; nj < NJ; nj++) {
#pragma unroll
            for (int k = 0; k < 2; k++) {
                float v = psum[nj][k];
                v += __shfl_xor_sync(0xffffffffu, v, 4);
                v += __shfl_xor_sync(0xffffffffu, v, 8);
                v += __shfl_xor_sync(0xffffffffu, v, 16);
                psum[nj][k] = v;
            }
        }
        __syncthreads();
        float* red = (float*)smem;       // [4 wm][128 cols]
        if (lane < 4) {
#pragma unroll
            for (int nj = 0; nj < NJ; nj++) {
                red[wm * 128 + wn * WNT + nj * 8 + 2 * lane + 0] = psum[nj][0];
                red[wm * 128 + wn * WNT + nj * 8 + 2 * lane + 1] = psum[nj][1];
            }
        }
        __syncthreads();
        {
            int ch = tid >> 7, cl = tid & 127;
            float s = red[(2 * ch) * 128 + cl] + red[(2 * ch + 1) * 128 + cl];
            int bidx = row0 >> 11;
            int cbase = (row0 & (LL - 1)) >> 7;
            part[((size_t)bidx * NCH + cbase + ch) * (size_t)N + col0 + cl] = s;
        }
    }
}

// ---------------------------------------------------------------------------
// elementwise kernels
// ---------------------------------------------------------------------------
__device__ __forceinline__ uint32_t pack_bf(float a, float b) {
    __nv_bfloat162 h = __halves2bfloat162(__float2bfloat16(a), __float2bfloat16(b));
    return *(uint32_t*)&h;
}

__global__ void split_kernel(const float* __restrict__ s, __nv_bfloat16* __restrict__ hi,
                             __nv_bfloat16* __restrict__ lo, size_t n) {
    size_t i = ((size_t)blockIdx.x * blockDim.x + threadIdx.x) * 8;
    if (i >= n) return;
    float4 a = *(const float4*)(s + i);
    float4 b = *(const float4*)(s + i + 4);
    uint4 h;
    h.x = pack_bf(a.x, a.y); h.y = pack_bf(a.z, a.w);
    h.z = pack_bf(b.x, b.y); h.w = pack_bf(b.z, b.w);
    *(uint4*)(hi + i) = h;
    if (lo != nullptr) {
        float hx, hy;
        uint4 l;
        hx = __bfloat162float(__float2bfloat16(a.x)); hy = __bfloat162float(__float2bfloat16(a.y));
        l.x = pack_bf(a.x - hx, a.y - hy);
        hx = __bfloat162float(__float2bfloat16(a.z)); hy = __bfloat162float(__float2bfloat16(a.w));
        l.y = pack_bf(a.z - hx, a.w - hy);
        hx = __bfloat162float(__float2bfloat16(b.x)); hy = __bfloat162float(__float2bfloat16(b.y));
        l.z = pack_bf(b.x - hx, b.y - hy);
        hx = __bfloat162float(__float2bfloat16(b.z)); hy = __bfloat162float(__float2bfloat16(b.w));
        l.w = pack_bf(b.z - hx, b.w - hy);
        *(uint4*)(lo + i) = l;
    }
}

__global__ void scanB_kernel(float* __restrict__ part) {
    int tid = blockIdx.x * blockDim.x + threadIdx.x;
    if (tid >= BB * RR) return;
    int r = tid % RR;
    int b = tid / RR;
    float run = 0.0f;
    for (int c = 0; c < NCH; c++) {
        size_t idx = ((size_t)b * NCH + c) * RR + r;
        float t = part[idx];
        part[idx] = run;
        run += t;
    }
}

__global__ void scanC_kernel(const float* __restrict__ u, const float* __restrict__ v,
                             const float* __restrict__ g, const float* __restrict__ part,
                             __nv_bfloat16* __restrict__ ghi, __nv_bfloat16* __restrict__ glo) {
    int tid = blockIdx.x * blockDim.x + threadIdx.x;
    if (tid >= BB * NCH * RR) return;
    int r = tid % RR;
    int c = (tid / RR) % NCH;
    int b = tid / (RR * NCH);
    float acc = part[((size_t)b * NCH + c) * RR + r];
    size_t base = ((size_t)b * LL + c * CHL) * RR + r;
    for (int l = 0; l < CHL; l++) {
        size_t idx = base + (size_t)l * RR;
        float gg = g[idx];
        acc += u[idx] * gg;
        float go = acc * (v[idx] * gg);
        __nv_bfloat16 h = __float2bfloat16(go);
        ghi[idx] = h;
        glo[idx] = __float2bfloat16(go - __bfloat162float(h));
    }
}

// ---------------------------------------------------------------------------
extern "C" void kernel_launch(void* const* d_in, const int* in_sizes, int n_in,
                              void* d_out, int out_size) {
    const float* x      = (const float*)d_in[0];
    const float* Wu     = (const float*)d_in[1];
    const float* bu     = (const float*)d_in[2];
    const float* Wv     = (const float*)d_in[3];
    const float* bv     = (const float*)d_in[4];
    const float* Wg1    = (const float*)d_in[5];
    const float* bg1    = (const float*)d_in[6];
    const float* Wg2    = (const float*)d_in[7];
    const float* bg2    = (const float*)d_in[8];
    const float* conv_w = (const float*)d_in[9];
    const float* conv_b = (const float*)d_in[10];
    float* out = (float*)d_out;

    __nv_bfloat16 *xhi, *xlo, *wuhi, *wulo, *wvhi, *wvlo, *wg1hi,
                  *wg2hi, *hhi, *ghi, *glo;
    float *pu, *pv, *pg, *ppart;
    cudaGetSymbolAddress((void**)&xhi, g_xhi);     cudaGetSymbolAddress((void**)&xlo, g_xlo);
    cudaGetSymbolAddress((void**)&wuhi, g_wuhi);   cudaGetSymbolAddress((void**)&wulo, g_wulo);
    cudaGetSymbolAddress((void**)&wvhi, g_wvhi);   cudaGetSymbolAddress((void**)&wvlo, g_wvlo);
    cudaGetSymbolAddress((void**)&wg1hi, g_wg1hi);
    cudaGetSymbolAddress((void**)&wg2hi, g_wg2hi);
    cudaGetSymbolAddress((void**)&hhi, g_hhi);
    cudaGetSymbolAddress((void**)&ghi, g_ghi);     cudaGetSymbolAddress((void**)&glo, g_glo);
    cudaGetSymbolAddress((void**)&pu, g_u);        cudaGetSymbolAddress((void**)&pv, g_v);
    cudaGetSymbolAddress((void**)&pg, g_g);        cudaGetSymbolAddress((void**)&ppart, g_part);

    cudaFuncSetAttribute(bsgemm<0,3,true,2>,  cudaFuncAttributeMaxDynamicSharedMemorySize, SMEM_OF(2));
    cudaFuncSetAttribute(bsgemm<1,1,false,2>, cudaFuncAttributeMaxDynamicSharedMemorySize, SMEM_OF(2));
    cudaFuncSetAttribute(bsgemm<2,1,false,2>, cudaFuncAttributeMaxDynamicSharedMemorySize, SMEM_OF(2));
    cudaFuncSetAttribute(bsgemm<3,3,false,4>, cudaFuncAttributeMaxDynamicSharedMemorySize, SMEM_OF(4));

    // splits for big GEMMs (launches 1-3)
    split_kernel<<<(unsigned)((size_t)MM * DD / 8 / 256), 256>>>(x, xhi, xlo, (size_t)MM * DD);
    split_kernel<<<(unsigned)((size_t)RR * DD / 8 / 256), 256>>>(Wu, wuhi, wulo, (size_t)RR * DD);
    split_kernel<<<(unsigned)((size_t)RR * DD / 8 / 256), 256>>>(Wv, wvhi, wvlo, (size_t)RR * DD);

    // dual u/v GEMM: z=0 -> u (Wu,bu), z=1 -> v (Wv,bv)
    bsgemm<0,3,true,2><<<dim3(RR / TBN, MM / 256, 2), 256, SMEM_OF(2)>>>(
        xhi, xlo, wuhi, wulo, bu, pu, nullptr, nullptr,
        wvhi, wvlo, bv, pv,
        nullptr, nullptr, nullptr, nullptr, nullptr, MM, RR, DD);

    // gate path (plain bf16, single pass)
    split_kernel<<<(unsigned)((size_t)DHH * DD / 8 / 256), 256>>>(Wg1, wg1hi, nullptr, (size_t)DHH * DD);
    split_kernel<<<(unsigned)((size_t)RR * DHH / 8 / 256), 256>>>(Wg2, wg2hi, nullptr, (size_t)RR * DHH);
    // h = relu(x Wg1^T + bg1) -> bf16
    bsgemm<1,1,false,2><<<dim3(DHH / TBN, MM / 256), 256, SMEM_OF(2)>>>(
        xhi, nullptr, wg1hi, nullptr, bg1, nullptr, nullptr, hhi,
        nullptr, nullptr, nullptr, nullptr,
        nullptr, nullptr, nullptr, nullptr, nullptr, MM, DHH, DD);
    // gates: write g, fused chunk partial sums of u*g -> part
    bsgemm<2,1,false,2><<<dim3(RR / TBN, MM / 256), 256, SMEM_OF(2)>>>(
        hhi, nullptr, wg2hi, nullptr, bg2, pu, nullptr, nullptr,
        nullptr, nullptr, nullptr, nullptr,
        nullptr, nullptr, nullptr, pg, ppart, MM, RR, DHH);

    // exclusive prefix over chunks, then apply gates + cumsum + multiply
    scanB_kernel<<<(BB * RR + 255) / 256, 256>>>(ppart);
    scanC_kernel<<<(BB * NCH * RR + 255) / 256, 256>>>(pu, pv, pg, ppart, ghi, glo);

    // out = conv3(x) + global_out @ Wu   (NWN=4: 1024 CTAs, small tail)
    bsgemm<3,3,false,4><<<dim3(DD / TBN, MM / 128), 256, SMEM_OF(4)>>>(
        ghi, glo, wuhi, wulo, nullptr, out, nullptr, nullptr,
        nullptr, nullptr, nullptr, nullptr,
        conv_w, conv_b, x, nullptr, nullptr, MM, DD, RR);
}

// round 10
// speedup vs baseline: 1.9027x; 1.3190x over previous
#include <cuda_runtime.h>
#include <cuda_fp16.h>
#include <cstdint>
#include <math.h>

// ---------------- problem constants ----------------
#define BB 4
#define LL 2048
#define DD 2048
#define RR 2048
#define DHH 512
#define MM (BB * LL)          // 8192
#define NCH 16
#define CHL (LL / NCH)        // 128

// ---------------- GEMM tiling ----------------
// NWN = warps along n. Warp tile = 64 x (128/NWN). TBM = 64*(8/NWN).
#define TBN 128
#define TBK 64
#define B_TILE 16384          // 128 rows * 128B
#define NSTAGE 2

// ---------------- device scratch ----------------
__device__ __half g_xhi[(size_t)MM * DD], g_xlo[(size_t)MM * DD];
__device__ __half g_wuhi[(size_t)RR * DD];
__device__ __half g_wvhi[(size_t)RR * DD];
__device__ __half g_wg1hi[(size_t)DHH * DD];
__device__ __half g_wg2hi[(size_t)RR * DHH];
__device__ __half g_hhi[(size_t)MM * DHH];
__device__ __half g_ghi[(size_t)MM * RR], g_glo[(size_t)MM * RR];
__device__ float g_u[(size_t)MM * RR];
__device__ float g_v[(size_t)MM * RR];
__device__ float g_g[(size_t)MM * RR];
__device__ float g_part[(size_t)BB * NCH * RR];

// ---------------- PTX helpers (arch-agnostic only) ----------------
__device__ __forceinline__ uint32_t smem_u32(const void* p) {
    uint32_t a;
    asm("{ .reg .u64 t; cvta.to.shared.u64 t, %1; cvt.u32.u64 %0, t; }" : "=r"(a) : "l"(p));
    return a;
}
__device__ __forceinline__ void cp16(uint32_t dst, const void* src) {
    asm volatile("cp.async.cg.shared.global [%0], [%1], 16;" :: "r"(dst), "l"(src));
}
#define CP_COMMIT() asm volatile("cp.async.commit_group;" ::: "memory")
#define CP_WAIT(n)  asm volatile("cp.async.wait_group %0;" :: "n"(n) : "memory")

#define LDSM4(r, addr) \
    asm volatile("ldmatrix.sync.aligned.m8n8.x4.shared.b16 {%0,%1,%2,%3}, [%4];" \
        : "=r"((r)[0]), "=r"((r)[1]), "=r"((r)[2]), "=r"((r)[3]) : "r"(addr))

__device__ __forceinline__ void mma16816(float* c, const uint32_t* a, uint32_t b0, uint32_t b1) {
    asm volatile(
        "mma.sync.aligned.m16n8k16.row.col.f32.f16.f16.f32 "
        "{%0,%1,%2,%3}, {%4,%5,%6,%7}, {%8,%9}, {%0,%1,%2,%3};"
        : "+f"(c[0]), "+f"(c[1]), "+f"(c[2]), "+f"(c[3])
        : "r"(a[0]), "r"(a[1]), "r"(a[2]), "r"(a[3]), "r"(b0), "r"(b1));
}

// SW128 swizzle for 128B rows: (row, 16B-chunk c in 0..7)
__device__ __forceinline__ uint32_t swz(int r, int c) {
    return (uint32_t)(r * 128 + ((c ^ (r & 7)) << 4));
}

// load one 64-K chunk's tiles into a stage. Layout: [Ahi | (Alo)] [Bhi]
template <bool SPLIT, int TBM_, int A_TILE_>
__device__ __forceinline__ void load_ab(uint32_t st,
                                        const __half* __restrict__ Ahi,
                                        const __half* __restrict__ Alo,
                                        const __half* __restrict__ Bhi,
                                        int K, int row0, int col0, int k0, int tid) {
    constexpr int B_OFF = (SPLIT ? 2 : 1) * A_TILE_;
#pragma unroll
    for (int i = 0; i < TBM_ / 32; i++) {         // A: TBM_ rows x 8 chunks of 16B
        int id = tid + i * 256;
        int r = id >> 3, c = id & 7;
        uint32_t dst = st + swz(r, c);
        size_t srcoff = (size_t)(row0 + r) * K + k0 + c * 8;
        cp16(dst, Ahi + srcoff);
        if (SPLIT) cp16(dst + A_TILE_, Alo + srcoff);
    }
#pragma unroll
    for (int i = 0; i < 4; i++) {                 // B: 128 rows x 8 chunks
        int id = tid + i * 256;
        int r = id >> 3, c = id & 7;
        uint32_t dst = st + B_OFF + swz(r, c);
        size_t srcoff = (size_t)(col0 + r) * K + k0 + c * 8;
        cp16(dst, Bhi + srcoff);
    }
}

// ---------------------------------------------------------------------------
// fp16(-split) warp-MMA GEMM: C[m,n] = sum_k A[m,k]*B[n,k]
// NPASS 2: Ahi*Bhi + Alo*Bhi (A corrected, B fp16) ; NPASS 1: Ahi*Bhi
// DUAL: blockIdx.z selects (B,bias,C) (EPI 0 only)
// NWN: warps along n (2 -> 256x128 CTA, 4 -> 128x128 CTA)
// EPI 0: C = z + bias
// EPI 1: relu(z + bias) -> fp16 (Ohi)
// EPI 2: g = sigmoid(z + bias); write gbuf; part = chunk sums of u*g (NWN=2 only)
// EPI 3: C = depthwise_conv3(x) + z
// ---------------------------------------------------------------------------
template <int EPI, int NPASS, bool DUAL, int NWN>
__global__ __launch_bounds__(256)
void bsgemm(const __half* __restrict__ Ahi, const __half* __restrict__ Alo,
            const __half* __restrict__ Bhi_,
            const float* __restrict__ bias_,
            float* __restrict__ C_,
            __half* __restrict__ Ohi,
            const __half* __restrict__ Bhi2,
            const float* __restrict__ bias2, float* __restrict__ Cd2,
            const float* __restrict__ cw, const float* __restrict__ cb,
            const float* __restrict__ xp,
            float* __restrict__ gbuf, float* __restrict__ part,
            int M, int N, int K) {
    constexpr int TBM_    = 64 * (8 / NWN);
    constexpr int A_TILE_ = TBM_ * 128;
    constexpr bool SPLIT  = (NPASS == 2);
    constexpr int B_OFF   = (SPLIT ? 2 : 1) * A_TILE_;
    constexpr int STAGE_  = B_OFF + B_TILE;
    constexpr int WNT     = 128 / NWN;    // warp n-tile
    constexpr int NJ      = WNT / 8;
    constexpr int PB      = NJ / 2;

    extern __shared__ __align__(128) char smem[];
    const uint32_t sb = smem_u32(smem);
    const int tid  = threadIdx.x;
    const int wid  = tid >> 5;
    const int lane = tid & 31;
    const int wm = wid / NWN;
    const int wn = wid % NWN;
    const int row0 = blockIdx.y * TBM_;
    const int col0 = blockIdx.x * TBN;
    const int nchunks = K / TBK;

    const __half* Bhi = Bhi_;
    const float* bias = bias_;
    float* C = C_;
    if (DUAL && blockIdx.z == 1) { Bhi = Bhi2; bias = bias2; C = Cd2; }

    // ldmatrix lane mapping
    const int lr = lane & 7;
    const int j  = lane >> 3;
    const int arow  = ((j & 1) << 3) + lr;
    const int acsel = j >> 1;
    const int brow  = ((j >> 1) << 3) + lr;
    const int bcsel = j & 1;

    float acc[4][NJ][4];
#pragma unroll
    for (int mi = 0; mi < 4; mi++)
#pragma unroll
        for (int nj = 0; nj < NJ; nj++)
#pragma unroll
            for (int q = 0; q < 4; q++) acc[mi][nj][q] = 0.0f;

    // prologue: chunk 0 into stage 0
    load_ab<SPLIT, TBM_, A_TILE_>(sb, Ahi, Alo, Bhi, K, row0, col0, 0, tid);
    CP_COMMIT();

    for (int c = 0; c < nchunks; c++) {
        CP_WAIT(0);
        __syncthreads();

        if (c + 1 < nchunks) {
            load_ab<SPLIT, TBM_, A_TILE_>(sb + ((c + 1) & 1) * STAGE_, Ahi, Alo, Bhi,
                                          K, row0, col0, (c + 1) * TBK, tid);
            CP_COMMIT();
        }

        const uint32_t sA = sb + (c & 1) * STAGE_;
        const uint32_t sB = sA + B_OFF;

#pragma unroll
        for (int s = 0; s < 4; s++) {
            uint32_t ah[4][4], bh[4][4], fx[4][4];
            uint32_t adA[4];
#pragma unroll
            for (int mi = 0; mi < 4; mi++) {
                int r = wm * 64 + mi * 16 + arow;
                adA[mi] = sA + swz(r, 2 * s + acsel);
                LDSM4(ah[mi], adA[mi]);
            }
#pragma unroll
            for (int p = 0; p < PB; p++) {
                int r = wn * WNT + p * 16 + brow;
                LDSM4(bh[p], sB + swz(r, 2 * s + bcsel));
            }
            // pass 1: Ahi x Bhi
#pragma unroll
            for (int mi = 0; mi < 4; mi++)
#pragma unroll
                for (int nj = 0; nj < NJ; nj++)
                    mma16816(acc[mi][nj], ah[mi], bh[nj >> 1][(nj & 1) * 2], bh[nj >> 1][(nj & 1) * 2 + 1]);
            if (SPLIT) {
                // pass 2: Alo x Bhi
#pragma unroll
                for (int mi = 0; mi < 4; mi++) LDSM4(fx[mi], adA[mi] + A_TILE_);
#pragma unroll
                for (int mi = 0; mi < 4; mi++)
#pragma unroll
                    for (int nj = 0; nj < NJ; nj++)
                        mma16816(acc[mi][nj], fx[mi], bh[nj >> 1][(nj & 1) * 2], bh[nj >> 1][(nj & 1) * 2 + 1]);
            }
        }
    }

    // -------- epilogue --------
    const int g_ = lane >> 2, t = lane & 3;
    float psum[NJ][2];
    if (EPI == 2) {
#pragma unroll
        for (int nj = 0; nj < NJ; nj++) { psum[nj][0] = 0.0f; psum[nj][1] = 0.0f; }
    }
#pragma unroll
    for (int mi = 0; mi < 4; mi++) {
#pragma unroll
        for (int nj = 0; nj < NJ; nj++) {
            int row = row0 + wm * 64 + mi * 16 + g_;
            int col = col0 + wn * WNT + nj * 8 + 2 * t;
            size_t i0 = (size_t)row * N + col;
            size_t i1 = (size_t)(row + 8) * N + col;
            float* z = acc[mi][nj];
            if (EPI == 0) {
                float b0 = bias[col], b1 = bias[col + 1];
                *(float2*)(C + i0) = make_float2(z[0] + b0, z[1] + b1);
                *(float2*)(C + i1) = make_float2(z[2] + b0, z[3] + b1);
            } else if (EPI == 1) {
                float b0 = bias[col], b1 = bias[col + 1];
                float v0 = fmaxf(z[0] + b0, 0.0f), v1 = fmaxf(z[1] + b1, 0.0f);
                float v2 = fmaxf(z[2] + b0, 0.0f), v3 = fmaxf(z[3] + b1, 0.0f);
                *(__half2*)(Ohi + i0) = __halves2half2(__float2half(v0), __float2half(v1));
                *(__half2*)(Ohi + i1) = __halves2half2(__float2half(v2), __float2half(v3));
            } else if (EPI == 2) {
                float b0 = bias[col], b1 = bias[col + 1];
                float g0 = 1.0f / (1.0f + __expf(-(z[0] + b0)));
                float g1 = 1.0f / (1.0f + __expf(-(z[1] + b1)));
                float g2 = 1.0f / (1.0f + __expf(-(z[2] + b0)));
                float g3 = 1.0f / (1.0f + __expf(-(z[3] + b1)));
                float2 u0 = *(float2*)(C + i0), u1 = *(float2*)(C + i1);
                *(float2*)(gbuf + i0) = make_float2(g0, g1);
                *(float2*)(gbuf + i1) = make_float2(g2, g3);
                psum[nj][0] += u0.x * g0 + u1.x * g2;
                psum[nj][1] += u0.y * g1 + u1.y * g3;
            } else {  // EPI == 3: out = conv3(x) + z
                int l0 = row & (LL - 1);
                int l1 = l0 + 8;
                float w0a = cw[3 * col + 0], w1a = cw[3 * col + 1], w2a = cw[3 * col + 2];
                float w0b = cw[3 * col + 3], w1b = cw[3 * col + 4], w2b = cw[3 * col + 5];
                float cb0 = cb[col], cb1 = cb[col + 1];
                const float* xr0 = xp + i0;
                const float* xr1 = xp + i1;
                float2 xc0 = *(const float2*)xr0;
                float2 xc1 = *(const float2*)xr1;
                float2 xq0 = *(const float2*)(xr0 + N);
                float2 xm1 = *(const float2*)(xr1 - N);
                float2 xm0 = (l0 > 0)      ? *(const float2*)(xr0 - N) : make_float2(0.f, 0.f);
                float2 xq1 = (l1 < LL - 1) ? *(const float2*)(xr1 + N) : make_float2(0.f, 0.f);
                float o0 = cb0 + w1a * xc0.x + w2a * xq0.x + z[0] + (l0 > 0 ? w0a * xm0.x : 0.f);
                float o1 = cb1 + w1b * xc0.y + w2b * xq0.y + z[1] + (l0 > 0 ? w0b * xm0.y : 0.f);
                float o2 = cb0 + w1a * xc1.x + w0a * xm1.x + z[2] + (l1 < LL - 1 ? w2a * xq1.x : 0.f);
                float o3 = cb1 + w1b * xc1.y + w0b * xm1.y + z[3] + (l1 < LL - 1 ? w2b * xq1.y : 0.f);
                *(float2*)(C + i0) = make_float2(o0, o1);
                *(float2*)(C + i1) = make_float2(o2, o3);
            }
        }
    }

    if (EPI == 2) {   // only instantiated with NWN=2 (TBM_=256)
#pragma unroll
        for (int nj = 0; nj < NJ; nj++) {
#pragma unroll
            for (int k = 0; k < 2; k++) {
                float v = psum[nj][k];
                v += __shfl_xor_sync(0xffffffffu, v, 4);
                v += __shfl_xor_sync(0xffffffffu, v, 8);
                v += __shfl_xor_sync(0xffffffffu, v, 16);
                psum[nj][k] = v;
            }
        }
        __syncthreads();
        float* red = (float*)smem;       // [4 wm][128 cols]
        if (lane < 4) {
#pragma unroll
            for (int nj = 0; nj < NJ; nj++) {
                red[wm * 128 + wn * WNT + nj * 8 + 2 * lane + 0] = psum[nj][0];
                red[wm * 128 + wn * WNT + nj * 8 + 2 * lane + 1] = psum[nj][1];
            }
        }
        __syncthreads();
        {
            int ch = tid >> 7, cl = tid & 127;
            float s = red[(2 * ch) * 128 + cl] + red[(2 * ch + 1) * 128 + cl];
            int bidx = row0 >> 11;
            int cbase = (row0 & (LL - 1)) >> 7;
            part[((size_t)bidx * NCH + cbase + ch) * (size_t)N + col0 + cl] = s;
        }
    }
}

// ---------------------------------------------------------------------------
// elementwise kernels
// ---------------------------------------------------------------------------
__device__ __forceinline__ uint32_t pack_h(float a, float b) {
    __half2 h = __halves2half2(__float2half(a), __float2half(b));
    return *(uint32_t*)&h;
}

__global__ void split_kernel(const float* __restrict__ s, __half* __restrict__ hi,
                             __half* __restrict__ lo, size_t n) {
    size_t i = ((size_t)blockIdx.x * blockDim.x + threadIdx.x) * 8;
    if (i >= n) return;
    float4 a = *(const float4*)(s + i);
    float4 b = *(const float4*)(s + i + 4);
    uint4 h;
    h.x = pack_h(a.x, a.y); h.y = pack_h(a.z, a.w);
    h.z = pack_h(b.x, b.y); h.w = pack_h(b.z, b.w);
    *(uint4*)(hi + i) = h;
    if (lo != nullptr) {
        float hx, hy;
        uint4 l;
        hx = __half2float(__float2half(a.x)); hy = __half2float(__float2half(a.y));
        l.x = pack_h(a.x - hx, a.y - hy);
        hx = __half2float(__float2half(a.z)); hy = __half2float(__float2half(a.w));
        l.y = pack_h(a.z - hx, a.w - hy);
        hx = __half2float(__float2half(b.x)); hy = __half2float(__float2half(b.y));
        l.z = pack_h(b.x - hx, b.y - hy);
        hx = __half2float(__float2half(b.z)); hy = __half2float(__float2half(b.w));
        l.w = pack_h(b.z - hx, b.w - hy);
        *(uint4*)(lo + i) = l;
    }
}

__global__ void scanB_kernel(float* __restrict__ part) {
    int tid = blockIdx.x * blockDim.x + threadIdx.x;
    if (tid >= BB * RR) return;
    int r = tid % RR;
    int b = tid / RR;
    float run = 0.0f;
    for (int c = 0; c < NCH; c++) {
        size_t idx = ((size_t)b * NCH + c) * RR + r;
        float t = part[idx];
        part[idx] = run;
        run += t;
    }
}

__global__ void scanC_kernel(const float* __restrict__ u, const float* __restrict__ v,
                             const float* __restrict__ g, const float* __restrict__ part,
                             __half* __restrict__ ghi, __half* __restrict__ glo) {
    int tid = blockIdx.x * blockDim.x + threadIdx.x;
    if (tid >= BB * NCH * RR) return;
    int r = tid % RR;
    int c = (tid / RR) % NCH;
    int b = tid / (RR * NCH);
    float acc = part[((size_t)b * NCH + c) * RR + r];
    size_t base = ((size_t)b * LL + c * CHL) * RR + r;
    for (int l = 0; l < CHL; l++) {
        size_t idx = base + (size_t)l * RR;
        float gg = g[idx];
        acc += u[idx] * gg;
        float go = acc * (v[idx] * gg);
        __half h = __float2half(go);
        ghi[idx] = h;
        glo[idx] = __float2half(go - __half2float(h));
    }
}

// ---------------------------------------------------------------------------
extern "C" void kernel_launch(void* const* d_in, const int* in_sizes, int n_in,
                              void* d_out, int out_size) {
    const float* x      = (const float*)d_in[0];
    const float* Wu     = (const float*)d_in[1];
    const float* bu     = (const float*)d_in[2];
    const float* Wv     = (const float*)d_in[3];
    const float* bv     = (const float*)d_in[4];
    const float* Wg1    = (const float*)d_in[5];
    const float* bg1    = (const float*)d_in[6];
    const float* Wg2    = (const float*)d_in[7];
    const float* bg2    = (const float*)d_in[8];
    const float* conv_w = (const float*)d_in[9];
    const float* conv_b = (const float*)d_in[10];
    float* out = (float*)d_out;

    __half *xhi, *xlo, *wuhi, *wvhi, *wg1hi, *wg2hi, *hhi, *ghi, *glo;
    float *pu, *pv, *pg, *ppart;
    cudaGetSymbolAddress((void**)&xhi, g_xhi);     cudaGetSymbolAddress((void**)&xlo, g_xlo);
    cudaGetSymbolAddress((void**)&wuhi, g_wuhi);
    cudaGetSymbolAddress((void**)&wvhi, g_wvhi);
    cudaGetSymbolAddress((void**)&wg1hi, g_wg1hi);
    cudaGetSymbolAddress((void**)&wg2hi, g_wg2hi);
    cudaGetSymbolAddress((void**)&hhi, g_hhi);
    cudaGetSymbolAddress((void**)&ghi, g_ghi);     cudaGetSymbolAddress((void**)&glo, g_glo);
    cudaGetSymbolAddress((void**)&pu, g_u);        cudaGetSymbolAddress((void**)&pv, g_v);
    cudaGetSymbolAddress((void**)&pg, g_g);        cudaGetSymbolAddress((void**)&ppart, g_part);

    // smem sizes: dual(NWN=2,SPLIT)=2*(2*32768+16384)=163840
    //             h/gates(NWN=2,NPASS=1)=2*(32768+16384)=98304
    //             uv(NWN=4,SPLIT)=2*(2*16384+16384)=98304
    cudaFuncSetAttribute(bsgemm<0,2,true,2>,  cudaFuncAttributeMaxDynamicSharedMemorySize, 163840);
    cudaFuncSetAttribute(bsgemm<1,1,false,2>, cudaFuncAttributeMaxDynamicSharedMemorySize, 98304);
    cudaFuncSetAttribute(bsgemm<2,1,false,2>, cudaFuncAttributeMaxDynamicSharedMemorySize, 98304);
    cudaFuncSetAttribute(bsgemm<3,2,false,4>, cudaFuncAttributeMaxDynamicSharedMemorySize, 98304);

    // splits (launches 1-3)
    split_kernel<<<(unsigned)((size_t)MM * DD / 8 / 256), 256>>>(x, xhi, xlo, (size_t)MM * DD);
    split_kernel<<<(unsigned)((size_t)RR * DD / 8 / 256), 256>>>(Wu, wuhi, nullptr, (size_t)RR * DD);
    split_kernel<<<(unsigned)((size_t)RR * DD / 8 / 256), 256>>>(Wv, wvhi, nullptr, (size_t)RR * DD);

    // dual u/v GEMM: z=0 -> u (Wu,bu), z=1 -> v (Wv,bv)
    bsgemm<0,2,true,2><<<dim3(RR / TBN, MM / 256, 2), 256, 163840>>>(
        xhi, xlo, wuhi, bu, pu, nullptr,
        wvhi, bv, pv,
        nullptr, nullptr, nullptr, nullptr, nullptr, MM, RR, DD);

    // gate path (plain fp16, single pass)
    split_kernel<<<(unsigned)((size_t)DHH * DD / 8 / 256), 256>>>(Wg1, wg1hi, nullptr, (size_t)DHH * DD);
    split_kernel<<<(unsigned)((size_t)RR * DHH / 8 / 256), 256>>>(Wg2, wg2hi, nullptr, (size_t)RR * DHH);
    // h = relu(x Wg1^T + bg1) -> fp16
    bsgemm<1,1,false,2><<<dim3(DHH / TBN, MM / 256), 256, 98304>>>(
        xhi, nullptr, wg1hi, bg1, nullptr, hhi,
        nullptr, nullptr, nullptr,
        nullptr, nullptr, nullptr, nullptr, nullptr, MM, DHH, DD);
    // gates: write g, fused chunk partial sums of u*g -> part
    bsgemm<2,1,false,2><<<dim3(RR / TBN, MM / 256), 256, 98304>>>(
        hhi, nullptr, wg2hi, bg2, pu, nullptr,
        nullptr, nullptr, nullptr,
        nullptr, nullptr, nullptr, pg, ppart, MM, RR, DHH);

    // exclusive prefix over chunks, then apply gates + cumsum + multiply
    scanB_kernel<<<(BB * RR + 255) / 256, 256>>>(ppart);
    scanC_kernel<<<(BB * NCH * RR + 255) / 256, 256>>>(pu, pv, pg, ppart, ghi, glo);

    // out = conv3(x) + global_out @ Wu   (NWN=4: 1024 CTAs)
    bsgemm<3,2,false,4><<<dim3(DD / TBN, MM / 128), 256, 98304>>>(
        ghi, glo, wuhi, nullptr, out, nullptr,
        nullptr, nullptr, nullptr,
        conv_w, conv_b, x, nullptr, nullptr, MM, DD, RR);
}

// round 11
// speedup vs baseline: 2.0847x; 1.0956x over previous
#include <cuda_runtime.h>
#include <cuda_fp16.h>
#include <cstdint>
#include <math.h>

// ---------------- problem constants ----------------
#define BB 4
#define LL 2048
#define DD 2048
#define RR 2048
#define DHH 512
#define MM (BB * LL)          // 8192
#define NCH 16
#define CHL (LL / NCH)        // 128

// ---------------- GEMM tiling ----------------
// NWN = warps along n. Warp tile = 64 x (128/NWN). TBM = 64*(8/NWN).
#define TBN 128
#define TBK 64
#define B_TILE 16384          // 128 rows * 128B
#define NSTAGE 2

// ---------------- device scratch ----------------
__device__ __half g_xhi[(size_t)MM * DD], g_xlo[(size_t)MM * DD];
__device__ __half g_wuhi[(size_t)RR * DD];
__device__ __half g_wvhi[(size_t)RR * DD];
__device__ __half g_wg1hi[(size_t)DHH * DD];
__device__ __half g_wg2hi[(size_t)RR * DHH];
__device__ __half g_hhi[(size_t)MM * DHH];
__device__ __half g_ghi[(size_t)MM * RR], g_glo[(size_t)MM * RR];
__device__ float g_u[(size_t)MM * RR];
__device__ float g_v[(size_t)MM * RR];
__device__ float g_g[(size_t)MM * RR];
__device__ float g_part[(size_t)BB * NCH * RR];

// ---------------- PTX helpers (arch-agnostic only) ----------------
__device__ __forceinline__ uint32_t smem_u32(const void* p) {
    uint32_t a;
    asm("{ .reg .u64 t; cvta.to.shared.u64 t, %1; cvt.u32.u64 %0, t; }" : "=r"(a) : "l"(p));
    return a;
}
__device__ __forceinline__ void cp16(uint32_t dst, const void* src) {
    asm volatile("cp.async.cg.shared.global [%0], [%1], 16;" :: "r"(dst), "l"(src));
}
#define CP_COMMIT() asm volatile("cp.async.commit_group;" ::: "memory")
#define CP_WAIT(n)  asm volatile("cp.async.wait_group %0;" :: "n"(n) : "memory")

#define LDSM4(r, addr) \
    asm volatile("ldmatrix.sync.aligned.m8n8.x4.shared.b16 {%0,%1,%2,%3}, [%4];" \
        : "=r"((r)[0]), "=r"((r)[1]), "=r"((r)[2]), "=r"((r)[3]) : "r"(addr))

__device__ __forceinline__ void mma16816(float* c, const uint32_t* a, uint32_t b0, uint32_t b1) {
    asm volatile(
        "mma.sync.aligned.m16n8k16.row.col.f32.f16.f16.f32 "
        "{%0,%1,%2,%3}, {%4,%5,%6,%7}, {%8,%9}, {%0,%1,%2,%3};"
        : "+f"(c[0]), "+f"(c[1]), "+f"(c[2]), "+f"(c[3])
        : "r"(a[0]), "r"(a[1]), "r"(a[2]), "r"(a[3]), "r"(b0), "r"(b1));
}

// SW128 swizzle for 128B rows: (row, 16B-chunk c in 0..7)
__device__ __forceinline__ uint32_t swz(int r, int c) {
    return (uint32_t)(r * 128 + ((c ^ (r & 7)) << 4));
}

// load one 64-K chunk's tiles into a stage. Layout: [Ahi | (Alo)] [Bhi]
template <bool SPLIT, int TBM_, int A_TILE_>
__device__ __forceinline__ void load_ab(uint32_t st,
                                        const __half* __restrict__ Ahi,
                                        const __half* __restrict__ Alo,
                                        const __half* __restrict__ Bhi,
                                        int K, int row0, int col0, int k0, int tid) {
    constexpr int B_OFF = (SPLIT ? 2 : 1) * A_TILE_;
#pragma unroll
    for (int i = 0; i < TBM_ / 32; i++) {         // A: TBM_ rows x 8 chunks of 16B
        int id = tid + i * 256;
        int r = id >> 3, c = id & 7;
        uint32_t dst = st + swz(r, c);
        size_t srcoff = (size_t)(row0 + r) * K + k0 + c * 8;
        cp16(dst, Ahi + srcoff);
        if (SPLIT) cp16(dst + A_TILE_, Alo + srcoff);
    }
#pragma unroll
    for (int i = 0; i < 4; i++) {                 // B: 128 rows x 8 chunks
        int id = tid + i * 256;
        int r = id >> 3, c = id & 7;
        uint32_t dst = st + B_OFF + swz(r, c);
        size_t srcoff = (size_t)(col0 + r) * K + k0 + c * 8;
        cp16(dst, Bhi + srcoff);
    }
}

// ---------------------------------------------------------------------------
// fp16(-split) warp-MMA GEMM: C[m,n] = sum_k A[m,k]*B[n,k]
// NPASS 2: Ahi*Bhi + Alo*Bhi ; NPASS 1: Ahi*Bhi
// DUAL: blockIdx.z selects (B,bias,C)
// NWN: warps along n (2 -> 256x128 CTA, 4 -> 128x128 CTA)
// MINB: min blocks/SM (launch bounds; 2 => reg cap 128 for co-residency)
// EPI 0: C = z + bias
// EPI 1: relu(z + bias) -> fp16 (Ohi)
// EPI 2: g = sigmoid(z + bias); write gbuf; part = chunk sums of u*g (NWN=2 only)
// EPI 3: C = depthwise_conv3(x) + z
// ---------------------------------------------------------------------------
template <int EPI, int NPASS, bool DUAL, int NWN, int MINB>
__global__ __launch_bounds__(256, MINB)
void bsgemm(const __half* __restrict__ Ahi, const __half* __restrict__ Alo,
            const __half* __restrict__ Bhi_,
            const float* __restrict__ bias_,
            float* __restrict__ C_,
            __half* __restrict__ Ohi,
            const __half* __restrict__ Bhi2,
            const float* __restrict__ bias2, float* __restrict__ Cd2,
            const float* __restrict__ cw, const float* __restrict__ cb,
            const float* __restrict__ xp,
            float* __restrict__ gbuf, float* __restrict__ part,
            int M, int N, int K) {
    constexpr int TBM_    = 64 * (8 / NWN);
    constexpr int A_TILE_ = TBM_ * 128;
    constexpr bool SPLIT  = (NPASS == 2);
    constexpr int B_OFF   = (SPLIT ? 2 : 1) * A_TILE_;
    constexpr int STAGE_  = B_OFF + B_TILE;
    constexpr int WNT     = 128 / NWN;    // warp n-tile
    constexpr int NJ      = WNT / 8;
    constexpr int PB      = NJ / 2;

    extern __shared__ __align__(128) char smem[];
    const uint32_t sb = smem_u32(smem);
    const int tid  = threadIdx.x;
    const int wid  = tid >> 5;
    const int lane = tid & 31;
    const int wm = wid / NWN;
    const int wn = wid % NWN;
    const int row0 = blockIdx.y * TBM_;
    const int col0 = blockIdx.x * TBN;
    const int nchunks = K / TBK;

    const __half* Bhi = Bhi_;
    const float* bias = bias_;
    float* C = C_;
    if (DUAL && blockIdx.z == 1) { Bhi = Bhi2; bias = bias2; C = Cd2; }

    // ldmatrix lane mapping
    const int lr = lane & 7;
    const int j  = lane >> 3;
    const int arow  = ((j & 1) << 3) + lr;
    const int acsel = j >> 1;
    const int brow  = ((j >> 1) << 3) + lr;
    const int bcsel = j & 1;

    float acc[4][NJ][4];
#pragma unroll
    for (int mi = 0; mi < 4; mi++)
#pragma unroll
        for (int nj = 0; nj < NJ; nj++)
#pragma unroll
            for (int q = 0; q < 4; q++) acc[mi][nj][q] = 0.0f;

    // prologue: chunk 0 into stage 0
    load_ab<SPLIT, TBM_, A_TILE_>(sb, Ahi, Alo, Bhi, K, row0, col0, 0, tid);
    CP_COMMIT();

    for (int c = 0; c < nchunks; c++) {
        CP_WAIT(0);
        __syncthreads();

        if (c + 1 < nchunks) {
            load_ab<SPLIT, TBM_, A_TILE_>(sb + ((c + 1) & 1) * STAGE_, Ahi, Alo, Bhi,
                                          K, row0, col0, (c + 1) * TBK, tid);
            CP_COMMIT();
        }

        const uint32_t sA = sb + (c & 1) * STAGE_;
        const uint32_t sB = sA + B_OFF;

#pragma unroll
        for (int s = 0; s < 4; s++) {
            uint32_t ah[4][4], bh[PB][4], fx[4][4];
            uint32_t adA[4];
#pragma unroll
            for (int mi = 0; mi < 4; mi++) {
                int r = wm * 64 + mi * 16 + arow;
                adA[mi] = sA + swz(r, 2 * s + acsel);
                LDSM4(ah[mi], adA[mi]);
            }
#pragma unroll
            for (int p = 0; p < PB; p++) {
                int r = wn * WNT + p * 16 + brow;
                LDSM4(bh[p], sB + swz(r, 2 * s + bcsel));
            }
            // pass 1: Ahi x Bhi
#pragma unroll
            for (int mi = 0; mi < 4; mi++)
#pragma unroll
                for (int nj = 0; nj < NJ; nj++)
                    mma16816(acc[mi][nj], ah[mi], bh[nj >> 1][(nj & 1) * 2], bh[nj >> 1][(nj & 1) * 2 + 1]);
            if (SPLIT) {
                // pass 2: Alo x Bhi
#pragma unroll
                for (int mi = 0; mi < 4; mi++) LDSM4(fx[mi], adA[mi] + A_TILE_);
#pragma unroll
                for (int mi = 0; mi < 4; mi++)
#pragma unroll
                    for (int nj = 0; nj < NJ; nj++)
                        mma16816(acc[mi][nj], fx[mi], bh[nj >> 1][(nj & 1) * 2], bh[nj >> 1][(nj & 1) * 2 + 1]);
            }
        }
    }

    // -------- epilogue --------
    const int g_ = lane >> 2, t = lane & 3;
    float psum[NJ][2];
    if (EPI == 2) {
#pragma unroll
        for (int nj = 0; nj < NJ; nj++) { psum[nj][0] = 0.0f; psum[nj][1] = 0.0f; }
    }
#pragma unroll
    for (int mi = 0; mi < 4; mi++) {
#pragma unroll
        for (int nj = 0; nj < NJ; nj++) {
            int row = row0 + wm * 64 + mi * 16 + g_;
            int col = col0 + wn * WNT + nj * 8 + 2 * t;
            size_t i0 = (size_t)row * N + col;
            size_t i1 = (size_t)(row + 8) * N + col;
            float* z = acc[mi][nj];
            if (EPI == 0) {
                float b0 = bias[col], b1 = bias[col + 1];
                *(float2*)(C + i0) = make_float2(z[0] + b0, z[1] + b1);
                *(float2*)(C + i1) = make_float2(z[2] + b0, z[3] + b1);
            } else if (EPI == 1) {
                float b0 = bias[col], b1 = bias[col + 1];
                float v0 = fmaxf(z[0] + b0, 0.0f), v1 = fmaxf(z[1] + b1, 0.0f);
                float v2 = fmaxf(z[2] + b0, 0.0f), v3 = fmaxf(z[3] + b1, 0.0f);
                *(__half2*)(Ohi + i0) = __halves2half2(__float2half(v0), __float2half(v1));
                *(__half2*)(Ohi + i1) = __halves2half2(__float2half(v2), __float2half(v3));
            } else if (EPI == 2) {
                float b0 = bias[col], b1 = bias[col + 1];
                float g0 = 1.0f / (1.0f + __expf(-(z[0] + b0)));
                float g1 = 1.0f / (1.0f + __expf(-(z[1] + b1)));
                float g2 = 1.0f / (1.0f + __expf(-(z[2] + b0)));
                float g3 = 1.0f / (1.0f + __expf(-(z[3] + b1)));
                float2 u0 = *(float2*)(C + i0), u1 = *(float2*)(C + i1);
                *(float2*)(gbuf + i0) = make_float2(g0, g1);
                *(float2*)(gbuf + i1) = make_float2(g2, g3);
                psum[nj][0] += u0.x * g0 + u1.x * g2;
                psum[nj][1] += u0.y * g1 + u1.y * g3;
            } else {  // EPI == 3: out = conv3(x) + z
                int l0 = row & (LL - 1);
                int l1 = l0 + 8;
                float w0a = cw[3 * col + 0], w1a = cw[3 * col + 1], w2a = cw[3 * col + 2];
                float w0b = cw[3 * col + 3], w1b = cw[3 * col + 4], w2b = cw[3 * col + 5];
                float cb0 = cb[col], cb1 = cb[col + 1];
                const float* xr0 = xp + i0;
                const float* xr1 = xp + i1;
                float2 xc0 = *(const float2*)xr0;
                float2 xc1 = *(const float2*)xr1;
                float2 xq0 = *(const float2*)(xr0 + N);
                float2 xm1 = *(const float2*)(xr1 - N);
                float2 xm0 = (l0 > 0)      ? *(const float2*)(xr0 - N) : make_float2(0.f, 0.f);
                float2 xq1 = (l1 < LL - 1) ? *(const float2*)(xr1 + N) : make_float2(0.f, 0.f);
                float o0 = cb0 + w1a * xc0.x + w2a * xq0.x + z[0] + (l0 > 0 ? w0a * xm0.x : 0.f);
                float o1 = cb1 + w1b * xc0.y + w2b * xq0.y + z[1] + (l0 > 0 ? w0b * xm0.y : 0.f);
                float o2 = cb0 + w1a * xc1.x + w0a * xm1.x + z[2] + (l1 < LL - 1 ? w2a * xq1.x : 0.f);
                float o3 = cb1 + w1b * xc1.y + w0b * xm1.y + z[3] + (l1 < LL - 1 ? w2b * xq1.y : 0.f);
                *(float2*)(C + i0) = make_float2(o0, o1);
                *(float2*)(C + i1) = make_float2(o2, o3);
            }
        }
    }

    if (EPI == 2) {   // only instantiated with NWN=2 (TBM_=256)
#pragma unroll
        for (int nj = 0; nj < NJ; nj++) {
#pragma unroll
            for (int k = 0; k < 2; k++) {
                float v = psum[nj][k];
                v += __shfl_xor_sync(0xffffffffu, v, 4);
                v += __shfl_xor_sync(0xffffffffu, v, 8);
                v += __shfl_xor_sync(0xffffffffu, v, 16);
                psum[nj][k] = v;
            }
        }
        __syncthreads();
        float* red = (float*)smem;       // [4 wm][128 cols]
        if (lane < 4) {
#pragma unroll
            for (int nj = 0; nj < NJ; nj++) {
                red[wm * 128 + wn * WNT + nj * 8 + 2 * lane + 0] = psum[nj][0];
                red[wm * 128 + wn * WNT + nj * 8 + 2 * lane + 1] = psum[nj][1];
            }
        }
        __syncthreads();
        {
            int ch = tid >> 7, cl = tid & 127;
            float s = red[(2 * ch) * 128 + cl] + red[(2 * ch + 1) * 128 + cl];
            int bidx = row0 >> 11;
            int cbase = (row0 & (LL - 1)) >> 7;
            part[((size_t)bidx * NCH + cbase + ch) * (size_t)N + col0 + cl] = s;
        }
    }
}

// ---------------------------------------------------------------------------
// elementwise kernels
// ---------------------------------------------------------------------------
__device__ __forceinline__ uint32_t pack_h(float a, float b) {
    __half2 h = __halves2half2(__float2half(a), __float2half(b));
    return *(uint32_t*)&h;
}

__global__ void split_kernel(const float* __restrict__ s, __half* __restrict__ hi,
                             __half* __restrict__ lo, size_t n) {
    size_t i = ((size_t)blockIdx.x * blockDim.x + threadIdx.x) * 8;
    if (i >= n) return;
    float4 a = *(const float4*)(s + i);
    float4 b = *(const float4*)(s + i + 4);
    uint4 h;
    h.x = pack_h(a.x, a.y); h.y = pack_h(a.z, a.w);
    h.z = pack_h(b.x, b.y); h.w = pack_h(b.z, b.w);
    *(uint4*)(hi + i) = h;
    if (lo != nullptr) {
        float hx, hy;
        uint4 l;
        hx = __half2float(__float2half(a.x)); hy = __half2float(__float2half(a.y));
        l.x = pack_h(a.x - hx, a.y - hy);
        hx = __half2float(__float2half(a.z)); hy = __half2float(__float2half(a.w));
        l.y = pack_h(a.z - hx, a.w - hy);
        hx = __half2float(__float2half(b.x)); hy = __half2float(__float2half(b.y));
        l.z = pack_h(b.x - hx, b.y - hy);
        hx = __half2float(__float2half(b.z)); hy = __half2float(__float2half(b.w));
        l.w = pack_h(b.z - hx, b.w - hy);
        *(uint4*)(lo + i) = l;
    }
}

__global__ void scanB_kernel(float* __restrict__ part) {
    int tid = blockIdx.x * blockDim.x + threadIdx.x;
    if (tid >= BB * RR) return;
    int r = tid % RR;
    int b = tid / RR;
    float run = 0.0f;
    for (int c = 0; c < NCH; c++) {
        size_t idx = ((size_t)b * NCH + c) * RR + r;
        float t = part[idx];
        part[idx] = run;
        run += t;
    }
}

__global__ void scanC_kernel(const float* __restrict__ u, const float* __restrict__ v,
                             const float* __restrict__ g, const float* __restrict__ part,
                             __half* __restrict__ ghi, __half* __restrict__ glo) {
    int tid = blockIdx.x * blockDim.x + threadIdx.x;
    if (tid >= BB * NCH * RR) return;
    int r = tid % RR;
    int c = (tid / RR) % NCH;
    int b = tid / (RR * NCH);
    float acc = part[((size_t)b * NCH + c) * RR + r];
    size_t base = ((size_t)b * LL + c * CHL) * RR + r;
    for (int l = 0; l < CHL; l++) {
        size_t idx = base + (size_t)l * RR;
        float gg = g[idx];
        acc += u[idx] * gg;
        float go = acc * (v[idx] * gg);
        __half h = __float2half(go);
        ghi[idx] = h;
        glo[idx] = __float2half(go - __half2float(h));
    }
}

// ---------------------------------------------------------------------------
extern "C" void kernel_launch(void* const* d_in, const int* in_sizes, int n_in,
                              void* d_out, int out_size) {
    const float* x      = (const float*)d_in[0];
    const float* Wu     = (const float*)d_in[1];
    const float* bu     = (const float*)d_in[2];
    const float* Wv     = (const float*)d_in[3];
    const float* bv     = (const float*)d_in[4];
    const float* Wg1    = (const float*)d_in[5];
    const float* bg1    = (const float*)d_in[6];
    const float* Wg2    = (const float*)d_in[7];
    const float* bg2    = (const float*)d_in[8];
    const float* conv_w = (const float*)d_in[9];
    const float* conv_b = (const float*)d_in[10];
    float* out = (float*)d_out;

    __half *xhi, *xlo, *wuhi, *wvhi, *wg1hi, *wg2hi, *hhi, *ghi, *glo;
    float *pu, *pv, *pg, *ppart;
    cudaGetSymbolAddress((void**)&xhi, g_xhi);     cudaGetSymbolAddress((void**)&xlo, g_xlo);
    cudaGetSymbolAddress((void**)&wuhi, g_wuhi);
    cudaGetSymbolAddress((void**)&wvhi, g_wvhi);
    cudaGetSymbolAddress((void**)&wg1hi, g_wg1hi);
    cudaGetSymbolAddress((void**)&wg2hi, g_wg2hi);
    cudaGetSymbolAddress((void**)&hhi, g_hhi);
    cudaGetSymbolAddress((void**)&ghi, g_ghi);     cudaGetSymbolAddress((void**)&glo, g_glo);
    cudaGetSymbolAddress((void**)&pu, g_u);        cudaGetSymbolAddress((void**)&pv, g_v);
    cudaGetSymbolAddress((void**)&pg, g_g);        cudaGetSymbolAddress((void**)&ppart, g_part);

    // all GEMM variants now use <=98304 B of dynamic smem -> 2 CTAs/SM
    cudaFuncSetAttribute(bsgemm<0,2,true,4,2>,  cudaFuncAttributeMaxDynamicSharedMemorySize, 98304);
    cudaFuncSetAttribute(bsgemm<1,1,false,2,1>, cudaFuncAttributeMaxDynamicSharedMemorySize, 98304);
    cudaFuncSetAttribute(bsgemm<2,1,false,2,1>, cudaFuncAttributeMaxDynamicSharedMemorySize, 98304);
    cudaFuncSetAttribute(bsgemm<3,2,false,4,2>, cudaFuncAttributeMaxDynamicSharedMemorySize, 98304);

    // splits (launches 1-3)
    split_kernel<<<(unsigned)((size_t)MM * DD / 8 / 256), 256>>>(x, xhi, xlo, (size_t)MM * DD);
    split_kernel<<<(unsigned)((size_t)RR * DD / 8 / 256), 256>>>(Wu, wuhi, nullptr, (size_t)RR * DD);
    split_kernel<<<(unsigned)((size_t)RR * DD / 8 / 256), 256>>>(Wv, wvhi, nullptr, (size_t)RR * DD);

    // dual u/v GEMM: TBM=128, 2 CTAs/SM. z=0 -> u (Wu,bu), z=1 -> v (Wv,bv)
    bsgemm<0,2,true,4,2><<<dim3(RR / TBN, MM / 128, 2), 256, 98304>>>(
        xhi, xlo, wuhi, bu, pu, nullptr,
        wvhi, bv, pv,
        nullptr, nullptr, nullptr, nullptr, nullptr, MM, RR, DD);

    // gate path (plain fp16, single pass)
    split_kernel<<<(unsigned)((size_t)DHH * DD / 8 / 256), 256>>>(Wg1, wg1hi, nullptr, (size_t)DHH * DD);
    split_kernel<<<(unsigned)((size_t)RR * DHH / 8 / 256), 256>>>(Wg2, wg2hi, nullptr, (size_t)RR * DHH);
    // h = relu(x Wg1^T + bg1) -> fp16
    bsgemm<1,1,false,2,1><<<dim3(DHH / TBN, MM / 256), 256, 98304>>>(
        xhi, nullptr, wg1hi, bg1, nullptr, hhi,
        nullptr, nullptr, nullptr,
        nullptr, nullptr, nullptr, nullptr, nullptr, MM, DHH, DD);
    // gates: write g, fused chunk partial sums of u*g -> part
    bsgemm<2,1,false,2,1><<<dim3(RR / TBN, MM / 256), 256, 98304>>>(
        hhi, nullptr, wg2hi, bg2, pu, nullptr,
        nullptr, nullptr, nullptr,
        nullptr, nullptr, nullptr, pg, ppart, MM, RR, DHH);

    // exclusive prefix over chunks, then apply gates + cumsum + multiply
    scanB_kernel<<<(BB * RR + 255) / 256, 256>>>(ppart);
    scanC_kernel<<<(BB * NCH * RR + 255) / 256, 256>>>(pu, pv, pg, ppart, ghi, glo);

    // out = conv3(x) + global_out @ Wu   (TBM=128, 2 CTAs/SM)
    bsgemm<3,2,false,4,2><<<dim3(DD / TBN, MM / 128), 256, 98304>>>(
        ghi, glo, wuhi, nullptr, out, nullptr,
        nullptr, nullptr, nullptr,
        conv_w, conv_b, x, nullptr, nullptr, MM, DD, RR);
}

// round 12
// speedup vs baseline: 2.6546x; 1.2733x over previous
#include <cuda_runtime.h>
#include <cuda_fp16.h>
#include <cstdint>
#include <math.h>

// ---------------- problem constants ----------------
#define BB 4
#define LL 2048
#define DD 2048
#define RR 2048
#define DHH 512
#define MM (BB * LL)          // 8192
#define NCH 16
#define CHL (LL / NCH)        // 128

// ---------------- GEMM tiling ----------------
#define TBN 128
#define TBK 64
#define B_TILE 16384          // 128 rows * 128B

// ---------------- device scratch ----------------
__device__ __half g_xhi[(size_t)MM * DD];
__device__ __half g_wuhi[(size_t)RR * DD];
__device__ __half g_wvhi[(size_t)RR * DD];
__device__ __half g_wg1hi[(size_t)DHH * DD];
__device__ __half g_wg2hi[(size_t)RR * DHH];
__device__ __half g_hhi[(size_t)MM * DHH];
__device__ __half g_ghi[(size_t)MM * RR], g_glo[(size_t)MM * RR];
__device__ float g_u[(size_t)MM * RR];
__device__ float g_v[(size_t)MM * RR];
__device__ float g_g[(size_t)MM * RR];
__device__ float g_part[(size_t)BB * NCH * RR];

// ---------------- PTX helpers (arch-agnostic only) ----------------
__device__ __forceinline__ uint32_t smem_u32(const void* p) {
    uint32_t a;
    asm("{ .reg .u64 t; cvta.to.shared.u64 t, %1; cvt.u32.u64 %0, t; }" : "=r"(a) : "l"(p));
    return a;
}
__device__ __forceinline__ void cp16(uint32_t dst, const void* src) {
    asm volatile("cp.async.cg.shared.global [%0], [%1], 16;" :: "r"(dst), "l"(src));
}
#define CP_COMMIT() asm volatile("cp.async.commit_group;" ::: "memory")
#define CP_WAIT(n)  asm volatile("cp.async.wait_group %0;" :: "n"(n) : "memory")

#define LDSM4(r, addr) \
    asm volatile("ldmatrix.sync.aligned.m8n8.x4.shared.b16 {%0,%1,%2,%3}, [%4];" \
        : "=r"((r)[0]), "=r"((r)[1]), "=r"((r)[2]), "=r"((r)[3]) : "r"(addr))

__device__ __forceinline__ void mma16816(float* c, const uint32_t* a, uint32_t b0, uint32_t b1) {
    asm volatile(
        "mma.sync.aligned.m16n8k16.row.col.f32.f16.f16.f32 "
        "{%0,%1,%2,%3}, {%4,%5,%6,%7}, {%8,%9}, {%0,%1,%2,%3};"
        : "+f"(c[0]), "+f"(c[1]), "+f"(c[2]), "+f"(c[3])
        : "r"(a[0]), "r"(a[1]), "r"(a[2]), "r"(a[3]), "r"(b0), "r"(b1));
}

// SW128 swizzle for 128B rows: (row, 16B-chunk c in 0..7)
__device__ __forceinline__ uint32_t swz(int r, int c) {
    return (uint32_t)(r * 128 + ((c ^ (r & 7)) << 4));
}

// load one 64-K chunk's tiles into a stage. Layout: [Ahi | (Alo)] [Bhi]
template <bool SPLIT, int TBM_, int A_TILE_>
__device__ __forceinline__ void load_ab(uint32_t st,
                                        const __half* __restrict__ Ahi,
                                        const __half* __restrict__ Alo,
                                        const __half* __restrict__ Bhi,
                                        int K, int row0, int col0, int k0, int tid) {
    constexpr int B_OFF = (SPLIT ? 2 : 1) * A_TILE_;
#pragma unroll
    for (int i = 0; i < TBM_ / 32; i++) {         // A: TBM_ rows x 8 chunks of 16B
        int id = tid + i * 256;
        int r = id >> 3, c = id & 7;
        uint32_t dst = st + swz(r, c);
        size_t srcoff = (size_t)(row0 + r) * K + k0 + c * 8;
        cp16(dst, Ahi + srcoff);
        if (SPLIT) cp16(dst + A_TILE_, Alo + srcoff);
    }
#pragma unroll
    for (int i = 0; i < 4; i++) {                 // B: 128 rows x 8 chunks
        int id = tid + i * 256;
        int r = id >> 3, c = id & 7;
        uint32_t dst = st + B_OFF + swz(r, c);
        size_t srcoff = (size_t)(col0 + r) * K + k0 + c * 8;
        cp16(dst, Bhi + srcoff);
    }
}

// ---------------------------------------------------------------------------
// fp16(-split) warp-MMA GEMM: C[m,n] = sum_k A[m,k]*B[n,k]
// NPASS 2: Ahi*Bhi + Alo*Bhi ; NPASS 1: Ahi*Bhi
// DUAL: blockIdx.z selects (B,bias,C)
// NWN: warps along n (2 -> 256x128 CTA, 4 -> 128x128 CTA)
// MINB: min blocks/SM ; NST: pipeline stages (2 or 3)
// EPI 0: C = z + bias
// EPI 1: relu(z + bias) -> fp16 (Ohi)
// EPI 2: g = sigmoid(z + bias); write gbuf; part = chunk sums of u*g (NWN=2 only)
// EPI 3: C = depthwise_conv3(x) + z
// ---------------------------------------------------------------------------
template <int EPI, int NPASS, bool DUAL, int NWN, int MINB, int NST>
__global__ __launch_bounds__(256, MINB)
void bsgemm(const __half* __restrict__ Ahi, const __half* __restrict__ Alo,
            const __half* __restrict__ Bhi_,
            const float* __restrict__ bias_,
            float* __restrict__ C_,
            __half* __restrict__ Ohi,
            const __half* __restrict__ Bhi2,
            const float* __restrict__ bias2, float* __restrict__ Cd2,
            const float* __restrict__ cw, const float* __restrict__ cb,
            const float* __restrict__ xp,
            float* __restrict__ gbuf, float* __restrict__ part,
            int M, int N, int K) {
    constexpr int TBM_    = 64 * (8 / NWN);
    constexpr int A_TILE_ = TBM_ * 128;
    constexpr bool SPLIT  = (NPASS == 2);
    constexpr int B_OFF   = (SPLIT ? 2 : 1) * A_TILE_;
    constexpr int STAGE_  = B_OFF + B_TILE;
    constexpr int WNT     = 128 / NWN;    // warp n-tile
    constexpr int NJ      = WNT / 8;
    constexpr int PB      = NJ / 2;

    extern __shared__ __align__(128) char smem[];
    const uint32_t sb = smem_u32(smem);
    const int tid  = threadIdx.x;
    const int wid  = tid >> 5;
    const int lane = tid & 31;
    const int wm = wid / NWN;
    const int wn = wid % NWN;
    const int row0 = blockIdx.y * TBM_;
    const int col0 = blockIdx.x * TBN;
    const int nchunks = K / TBK;

    const __half* Bhi = Bhi_;
    const float* bias = bias_;
    float* C = C_;
    if (DUAL && blockIdx.z == 1) { Bhi = Bhi2; bias = bias2; C = Cd2; }

    // ldmatrix lane mapping
    const int lr = lane & 7;
    const int j  = lane >> 3;
    const int arow  = ((j & 1) << 3) + lr;
    const int acsel = j >> 1;
    const int brow  = ((j >> 1) << 3) + lr;
    const int bcsel = j & 1;

    float acc[4][NJ][4];
#pragma unroll
    for (int mi = 0; mi < 4; mi++)
#pragma unroll
        for (int nj = 0; nj < NJ; nj++)
#pragma unroll
            for (int q = 0; q < 4; q++) acc[mi][nj][q] = 0.0f;

    // prologue: chunks 0..NST-2
#pragma unroll
    for (int p = 0; p < NST - 1; p++) {
        load_ab<SPLIT, TBM_, A_TILE_>(sb + p * STAGE_, Ahi, Alo, Bhi, K, row0, col0, p * TBK, tid);
        CP_COMMIT();
    }

    for (int c = 0; c < nchunks; c++) {
        if (c == nchunks - 1) CP_WAIT(0); else CP_WAIT(NST - 2);
        __syncthreads();

        const int nxt = c + NST - 1;
        if (nxt < nchunks) {
            load_ab<SPLIT, TBM_, A_TILE_>(sb + (nxt % NST) * STAGE_, Ahi, Alo, Bhi,
                                          K, row0, col0, nxt * TBK, tid);
            CP_COMMIT();
        }

        const uint32_t sA = sb + (c % NST) * STAGE_;
        const uint32_t sB = sA + B_OFF;

#pragma unroll
        for (int s = 0; s < 4; s++) {
            uint32_t ah[4][4], bh[PB][4], fx[4][4];
            uint32_t adA[4];
#pragma unroll
            for (int mi = 0; mi < 4; mi++) {
                int r = wm * 64 + mi * 16 + arow;
                adA[mi] = sA + swz(r, 2 * s + acsel);
                LDSM4(ah[mi], adA[mi]);
            }
#pragma unroll
            for (int p = 0; p < PB; p++) {
                int r = wn * WNT + p * 16 + brow;
                LDSM4(bh[p], sB + swz(r, 2 * s + bcsel));
            }
            // pass 1: Ahi x Bhi
#pragma unroll
            for (int mi = 0; mi < 4; mi++)
#pragma unroll
                for (int nj = 0; nj < NJ; nj++)
                    mma16816(acc[mi][nj], ah[mi], bh[nj >> 1][(nj & 1) * 2], bh[nj >> 1][(nj & 1) * 2 + 1]);
            if (SPLIT) {
                // pass 2: Alo x Bhi
#pragma unroll
                for (int mi = 0; mi < 4; mi++) LDSM4(fx[mi], adA[mi] + A_TILE_);
#pragma unroll
                for (int mi = 0; mi < 4; mi++)
#pragma unroll
                    for (int nj = 0; nj < NJ; nj++)
                        mma16816(acc[mi][nj], fx[mi], bh[nj >> 1][(nj & 1) * 2], bh[nj >> 1][(nj & 1) * 2 + 1]);
            }
        }
    }

    // -------- epilogue --------
    const int g_ = lane >> 2, t = lane & 3;
    float psum[NJ][2];
    if (EPI == 2) {
#pragma unroll
        for (int nj = 0; nj < NJ; nj++) { psum[nj][0] = 0.0f; psum[nj][1] = 0.0f; }
    }
#pragma unroll
    for (int mi = 0; mi < 4; mi++) {
#pragma unroll
        for (int nj = 0; nj < NJ; nj++) {
            int row = row0 + wm * 64 + mi * 16 + g_;
            int col = col0 + wn * WNT + nj * 8 + 2 * t;
            size_t i0 = (size_t)row * N + col;
            size_t i1 = (size_t)(row + 8) * N + col;
            float* z = acc[mi][nj];
            if (EPI == 0) {
                float b0 = bias[col], b1 = bias[col + 1];
                *(float2*)(C + i0) = make_float2(z[0] + b0, z[1] + b1);
                *(float2*)(C + i1) = make_float2(z[2] + b0, z[3] + b1);
            } else if (EPI == 1) {
                float b0 = bias[col], b1 = bias[col + 1];
                float v0 = fmaxf(z[0] + b0, 0.0f), v1 = fmaxf(z[1] + b1, 0.0f);
                float v2 = fmaxf(z[2] + b0, 0.0f), v3 = fmaxf(z[3] + b1, 0.0f);
                *(__half2*)(Ohi + i0) = __halves2half2(__float2half(v0), __float2half(v1));
                *(__half2*)(Ohi + i1) = __halves2half2(__float2half(v2), __float2half(v3));
            } else if (EPI == 2) {
                float b0 = bias[col], b1 = bias[col + 1];
                float g0 = 1.0f / (1.0f + __expf(-(z[0] + b0)));
                float g1 = 1.0f / (1.0f + __expf(-(z[1] + b1)));
                float g2 = 1.0f / (1.0f + __expf(-(z[2] + b0)));
                float g3 = 1.0f / (1.0f + __expf(-(z[3] + b1)));
                float2 u0 = *(float2*)(C + i0), u1 = *(float2*)(C + i1);
                *(float2*)(gbuf + i0) = make_float2(g0, g1);
                *(float2*)(gbuf + i1) = make_float2(g2, g3);
                psum[nj][0] += u0.x * g0 + u1.x * g2;
                psum[nj][1] += u0.y * g1 + u1.y * g3;
            } else {  // EPI == 3: out = conv3(x) + z
                int l0 = row & (LL - 1);
                int l1 = l0 + 8;
                float w0a = cw[3 * col + 0], w1a = cw[3 * col + 1], w2a = cw[3 * col + 2];
                float w0b = cw[3 * col + 3], w1b = cw[3 * col + 4], w2b = cw[3 * col + 5];
                float cb0 = cb[col], cb1 = cb[col + 1];
                const float* xr0 = xp + i0;
                const float* xr1 = xp + i1;
                float2 xc0 = *(const float2*)xr0;
                float2 xc1 = *(const float2*)xr1;
                float2 xq0 = *(const float2*)(xr0 + N);
                float2 xm1 = *(const float2*)(xr1 - N);
                float2 xm0 = (l0 > 0)      ? *(const float2*)(xr0 - N) : make_float2(0.f, 0.f);
                float2 xq1 = (l1 < LL - 1) ? *(const float2*)(xr1 + N) : make_float2(0.f, 0.f);
                float o0 = cb0 + w1a * xc0.x + w2a * xq0.x + z[0] + (l0 > 0 ? w0a * xm0.x : 0.f);
                float o1 = cb1 + w1b * xc0.y + w2b * xq0.y + z[1] + (l0 > 0 ? w0b * xm0.y : 0.f);
                float o2 = cb0 + w1a * xc1.x + w0a * xm1.x + z[2] + (l1 < LL - 1 ? w2a * xq1.x : 0.f);
                float o3 = cb1 + w1b * xc1.y + w0b * xm1.y + z[3] + (l1 < LL - 1 ? w2b * xq1.y : 0.f);
                *(float2*)(C + i0) = make_float2(o0, o1);
                *(float2*)(C + i1) = make_float2(o2, o3);
            }
        }
    }

    if (EPI == 2) {   // only instantiated with NWN=2 (TBM_=256)
#pragma unroll
        for (int nj = 0; nj < NJ; nj++) {
#pragma unroll
            for (int k = 0; k < 2; k++) {
                float v = psum[nj][k];
                v += __shfl_xor_sync(0xffffffffu, v, 4);
                v += __shfl_xor_sync(0xffffffffu, v, 8);
                v += __shfl_xor_sync(0xffffffffu, v, 16);
                psum[nj][k] = v;
            }
        }
        __syncthreads();
        float* red = (float*)smem;       // [4 wm][128 cols]
        if (lane < 4) {
#pragma unroll
            for (int nj = 0; nj < NJ; nj++) {
                red[wm * 128 + wn * WNT + nj * 8 + 2 * lane + 0] = psum[nj][0];
                red[wm * 128 + wn * WNT + nj * 8 + 2 * lane + 1] = psum[nj][1];
            }
        }
        __syncthreads();
        {
            int ch = tid >> 7, cl = tid & 127;
            float s = red[(2 * ch) * 128 + cl] + red[(2 * ch + 1) * 128 + cl];
            int bidx = row0 >> 11;
            int cbase = (row0 & (LL - 1)) >> 7;
            part[((size_t)bidx * NCH + cbase + ch) * (size_t)N + col0 + cl] = s;
        }
    }
}

// ---------------------------------------------------------------------------
// elementwise kernels
// ---------------------------------------------------------------------------
__device__ __forceinline__ uint32_t pack_h(float a, float b) {
    __half2 h = __halves2half2(__float2half(a), __float2half(b));
    return *(uint32_t*)&h;
}

__global__ void split_kernel(const float* __restrict__ s, __half* __restrict__ hi,
                             __half* __restrict__ lo, size_t n) {
    size_t i = ((size_t)blockIdx.x * blockDim.x + threadIdx.x) * 8;
    if (i >= n) return;
    float4 a = *(const float4*)(s + i);
    float4 b = *(const float4*)(s + i + 4);
    uint4 h;
    h.x = pack_h(a.x, a.y); h.y = pack_h(a.z, a.w);
    h.z = pack_h(b.x, b.y); h.w = pack_h(b.z, b.w);
    *(uint4*)(hi + i) = h;
    if (lo != nullptr) {
        float hx, hy;
        uint4 l;
        hx = __half2float(__float2half(a.x)); hy = __half2float(__float2half(a.y));
        l.x = pack_h(a.x - hx, a.y - hy);
        hx = __half2float(__float2half(a.z)); hy = __half2float(__float2half(a.w));
        l.y = pack_h(a.z - hx, a.w - hy);
        hx = __half2float(__float2half(b.x)); hy = __half2float(__float2half(b.y));
        l.z = pack_h(b.x - hx, b.y - hy);
        hx = __half2float(__float2half(b.z)); hy = __half2float(__float2half(b.w));
        l.w = pack_h(b.z - hx, b.w - hy);
        *(uint4*)(lo + i) = l;
    }
}

__global__ void scanB_kernel(float* __restrict__ part) {
    int tid = blockIdx.x * blockDim.x + threadIdx.x;
    if (tid >= BB * RR) return;
    int r = tid % RR;
    int b = tid / RR;
    float run = 0.0f;
    for (int c = 0; c < NCH; c++) {
        size_t idx = ((size_t)b * NCH + c) * RR + r;
        float t = part[idx];
        part[idx] = run;
        run += t;
    }
}

__global__ void scanC_kernel(const float* __restrict__ u, const float* __restrict__ v,
                             const float* __restrict__ g, const float* __restrict__ part,
                             __half* __restrict__ ghi, __half* __restrict__ glo) {
    int tid = blockIdx.x * blockDim.x + threadIdx.x;
    if (tid >= BB * NCH * RR) return;
    int r = tid % RR;
    int c = (tid / RR) % NCH;
    int b = tid / (RR * NCH);
    float acc = part[((size_t)b * NCH + c) * RR + r];
    size_t base = ((size_t)b * LL + c * CHL) * RR + r;
    for (int l = 0; l < CHL; l++) {
        size_t idx = base + (size_t)l * RR;
        float gg = g[idx];
        acc += u[idx] * gg;
        float go = acc * (v[idx] * gg);
        __half h = __float2half(go);
        ghi[idx] = h;
        glo[idx] = __float2half(go - __half2float(h));
    }
}

// ---------------------------------------------------------------------------
extern "C" void kernel_launch(void* const* d_in, const int* in_sizes, int n_in,
                              void* d_out, int out_size) {
    const float* x      = (const float*)d_in[0];
    const float* Wu     = (const float*)d_in[1];
    const float* bu     = (const float*)d_in[2];
    const float* Wv     = (const float*)d_in[3];
    const float* bv     = (const float*)d_in[4];
    const float* Wg1    = (const float*)d_in[5];
    const float* bg1    = (const float*)d_in[6];
    const float* Wg2    = (const float*)d_in[7];
    const float* bg2    = (const float*)d_in[8];
    const float* conv_w = (const float*)d_in[9];
    const float* conv_b = (const float*)d_in[10];
    float* out = (float*)d_out;

    __half *xhi, *wuhi, *wvhi, *wg1hi, *wg2hi, *hhi, *ghi, *glo;
    float *pu, *pv, *pg, *ppart;
    cudaGetSymbolAddress((void**)&xhi, g_xhi);
    cudaGetSymbolAddress((void**)&wuhi, g_wuhi);
    cudaGetSymbolAddress((void**)&wvhi, g_wvhi);
    cudaGetSymbolAddress((void**)&wg1hi, g_wg1hi);
    cudaGetSymbolAddress((void**)&wg2hi, g_wg2hi);
    cudaGetSymbolAddress((void**)&hhi, g_hhi);
    cudaGetSymbolAddress((void**)&ghi, g_ghi);     cudaGetSymbolAddress((void**)&glo, g_glo);
    cudaGetSymbolAddress((void**)&pu, g_u);        cudaGetSymbolAddress((void**)&pv, g_v);
    cudaGetSymbolAddress((void**)&pg, g_g);        cudaGetSymbolAddress((void**)&ppart, g_part);

    // dual: NPASS=1, NWN=4, 3 stages -> 3*32KB = 98304/CTA, 2 CTAs/SM
    cudaFuncSetAttribute(bsgemm<0,1,true,4,2,3>,  cudaFuncAttributeMaxDynamicSharedMemorySize, 98304);
    // h / gates: NWN=2, 1-pass, 2 stages -> 2*48KB = 98304
    cudaFuncSetAttribute(bsgemm<1,1,false,2,1,2>, cudaFuncAttributeMaxDynamicSharedMemorySize, 98304);
    cudaFuncSetAttribute(bsgemm<2,1,false,2,1,2>, cudaFuncAttributeMaxDynamicSharedMemorySize, 98304);
    // uv: NPASS=2, NWN=4, 2 stages -> 2*48KB = 98304, 2 CTAs/SM
    cudaFuncSetAttribute(bsgemm<3,2,false,4,2,2>, cudaFuncAttributeMaxDynamicSharedMemorySize, 98304);

    // splits (hi-only except none need lo now; ghi/glo come from scanC)
    split_kernel<<<(unsigned)((size_t)MM * DD / 8 / 256), 256>>>(x, xhi, nullptr, (size_t)MM * DD);
    split_kernel<<<(unsigned)((size_t)RR * DD / 8 / 256), 256>>>(Wu, wuhi, nullptr, (size_t)RR * DD);
    split_kernel<<<(unsigned)((size_t)RR * DD / 8 / 256), 256>>>(Wv, wvhi, nullptr, (size_t)RR * DD);

    // dual u/v GEMM (1-pass fp16): z=0 -> u (Wu,bu), z=1 -> v (Wv,bv)
    bsgemm<0,1,true,4,2,3><<<dim3(RR / TBN, MM / 128, 2), 256, 98304>>>(
        xhi, nullptr, wuhi, bu, pu, nullptr,
        wvhi, bv, pv,
        nullptr, nullptr, nullptr, nullptr, nullptr, MM, RR, DD);

    // gate path (plain fp16, single pass)
    split_kernel<<<(unsigned)((size_t)DHH * DD / 8 / 256), 256>>>(Wg1, wg1hi, nullptr, (size_t)DHH * DD);
    split_kernel<<<(unsigned)((size_t)RR * DHH / 8 / 256), 256>>>(Wg2, wg2hi, nullptr, (size_t)RR * DHH);
    // h = relu(x Wg1^T + bg1) -> fp16
    bsgemm<1,1,false,2,1,2><<<dim3(DHH / TBN, MM / 256), 256, 98304>>>(
        xhi, nullptr, wg1hi, bg1, nullptr, hhi,
        nullptr, nullptr, nullptr,
        nullptr, nullptr, nullptr, nullptr, nullptr, MM, DHH, DD);
    // gates: write g, fused chunk partial sums of u*g -> part
    bsgemm<2,1,false,2,1,2><<<dim3(RR / TBN, MM / 256), 256, 98304>>>(
        hhi, nullptr, wg2hi, bg2, pu, nullptr,
        nullptr, nullptr, nullptr,
        nullptr, nullptr, nullptr, pg, ppart, MM, RR, DHH);

    // exclusive prefix over chunks, then apply gates + cumsum + multiply
    scanB_kernel<<<(BB * RR + 255) / 256, 256>>>(ppart);
    scanC_kernel<<<(BB * NCH * RR + 255) / 256, 256>>>(pu, pv, pg, ppart, ghi, glo);

    // out = conv3(x) + global_out @ Wu   (2-pass: A = ghi+glo)
    bsgemm<3,2,false,4,2,2><<<dim3(DD / TBN, MM / 128), 256, 98304>>>(
        ghi, glo, wuhi, nullptr, out, nullptr,
        nullptr, nullptr, nullptr,
        conv_w, conv_b, x, nullptr, nullptr, MM, DD, RR);
}

// round 13
// speedup vs baseline: 3.2357x; 1.2189x over previous
#include <cuda_runtime.h>
#include <cuda_fp16.h>
#include <cstdint>
#include <math.h>

// ---------------- problem constants ----------------
#define BB 4
#define LL 2048
#define DD 2048
#define RR 2048
#define DHH 512
#define MM (BB * LL)          // 8192
#define NCH 16
#define CHL (LL / NCH)        // 128

// ---------------- GEMM tiling ----------------
#define TBN 128
#define TBK 64
#define B_TILE 16384          // 128 rows * 128B

// ---------------- device scratch ----------------
__device__ __half g_xhi[(size_t)MM * DD];
__device__ __half g_wuhi[(size_t)RR * DD];
__device__ __half g_wvhi[(size_t)RR * DD];
__device__ __half g_wg1hi[(size_t)DHH * DD];
__device__ __half g_wg2hi[(size_t)RR * DHH];
__device__ __half g_hhi[(size_t)MM * DHH];
__device__ __half g_ghi[(size_t)MM * RR];
__device__ float g_u[(size_t)MM * RR];
__device__ float g_v[(size_t)MM * RR];
__device__ float g_g[(size_t)MM * RR];
__device__ float g_part[(size_t)BB * NCH * RR];

// ---------------- PTX helpers (arch-agnostic only) ----------------
__device__ __forceinline__ uint32_t smem_u32(const void* p) {
    uint32_t a;
    asm("{ .reg .u64 t; cvta.to.shared.u64 t, %1; cvt.u32.u64 %0, t; }" : "=r"(a) : "l"(p));
    return a;
}
__device__ __forceinline__ void cp16(uint32_t dst, const void* src) {
    asm volatile("cp.async.cg.shared.global [%0], [%1], 16;" :: "r"(dst), "l"(src));
}
#define CP_COMMIT() asm volatile("cp.async.commit_group;" ::: "memory")
#define CP_WAIT(n)  asm volatile("cp.async.wait_group %0;" :: "n"(n) : "memory")

#define LDSM4(r, addr) \
    asm volatile("ldmatrix.sync.aligned.m8n8.x4.shared.b16 {%0,%1,%2,%3}, [%4];" \
        : "=r"((r)[0]), "=r"((r)[1]), "=r"((r)[2]), "=r"((r)[3]) : "r"(addr))

__device__ __forceinline__ void mma16816(float* c, const uint32_t* a, uint32_t b0, uint32_t b1) {
    asm volatile(
        "mma.sync.aligned.m16n8k16.row.col.f32.f16.f16.f32 "
        "{%0,%1,%2,%3}, {%4,%5,%6,%7}, {%8,%9}, {%0,%1,%2,%3};"
        : "+f"(c[0]), "+f"(c[1]), "+f"(c[2]), "+f"(c[3])
        : "r"(a[0]), "r"(a[1]), "r"(a[2]), "r"(a[3]), "r"(b0), "r"(b1));
}

// SW128 swizzle for 128B rows: (row, 16B-chunk c in 0..7)
__device__ __forceinline__ uint32_t swz(int r, int c) {
    return (uint32_t)(r * 128 + ((c ^ (r & 7)) << 4));
}

// load one 64-K chunk's tiles into a stage. Layout: [Ahi] [Bhi]
template <int TBM_, int A_TILE_>
__device__ __forceinline__ void load_ab(uint32_t st,
                                        const __half* __restrict__ Ahi,
                                        const __half* __restrict__ Bhi,
                                        int K, int row0, int col0, int k0, int tid) {
#pragma unroll
    for (int i = 0; i < TBM_ / 32; i++) {         // A: TBM_ rows x 8 chunks of 16B
        int id = tid + i * 256;
        int r = id >> 3, c = id & 7;
        size_t srcoff = (size_t)(row0 + r) * K + k0 + c * 8;
        cp16(st + swz(r, c), Ahi + srcoff);
    }
#pragma unroll
    for (int i = 0; i < 4; i++) {                 // B: 128 rows x 8 chunks
        int id = tid + i * 256;
        int r = id >> 3, c = id & 7;
        size_t srcoff = (size_t)(col0 + r) * K + k0 + c * 8;
        cp16(st + A_TILE_ + swz(r, c), Bhi + srcoff);
    }
}

// ---------------------------------------------------------------------------
// fp16 warp-MMA GEMM: C[m,n] = sum_k A[m,k]*B[n,k]   (single pass)
// DUAL: blockIdx.z selects (B,bias,C)
// NWN: warps along n (2 -> 256x128 CTA, 4 -> 128x128 CTA)
// MINB: min blocks/SM ; NST: pipeline stages
// EPI 0: C = z + bias
// EPI 1: relu(z + bias) -> fp16 (Ohi)
// EPI 2: g = sigmoid(z + bias); write gbuf; part = chunk sums of u*g
// EPI 3: C = depthwise_conv3(x) + z
// ---------------------------------------------------------------------------
template <int EPI, bool DUAL, int NWN, int MINB, int NST>
__global__ __launch_bounds__(256, MINB)
void bsgemm(const __half* __restrict__ Ahi,
            const __half* __restrict__ Bhi_,
            const float* __restrict__ bias_,
            float* __restrict__ C_,
            __half* __restrict__ Ohi,
            const __half* __restrict__ Bhi2,
            const float* __restrict__ bias2, float* __restrict__ Cd2,
            const float* __restrict__ cw, const float* __restrict__ cb,
            const float* __restrict__ xp,
            float* __restrict__ gbuf, float* __restrict__ part,
            int M, int N, int K) {
    constexpr int TBM_    = 64 * (8 / NWN);
    constexpr int A_TILE_ = TBM_ * 128;
    constexpr int STAGE_  = A_TILE_ + B_TILE;
    constexpr int WNT     = 128 / NWN;    // warp n-tile
    constexpr int NJ      = WNT / 8;
    constexpr int PB      = NJ / 2;

    extern __shared__ __align__(128) char smem[];
    const uint32_t sb = smem_u32(smem);
    const int tid  = threadIdx.x;
    const int wid  = tid >> 5;
    const int lane = tid & 31;
    const int wm = wid / NWN;
    const int wn = wid % NWN;
    const int row0 = blockIdx.y * TBM_;
    const int col0 = blockIdx.x * TBN;
    const int nchunks = K / TBK;

    const __half* Bhi = Bhi_;
    const float* bias = bias_;
    float* C = C_;
    if (DUAL && blockIdx.z == 1) { Bhi = Bhi2; bias = bias2; C = Cd2; }

    // ldmatrix lane mapping
    const int lr = lane & 7;
    const int j  = lane >> 3;
    const int arow  = ((j & 1) << 3) + lr;
    const int acsel = j >> 1;
    const int brow  = ((j >> 1) << 3) + lr;
    const int bcsel = j & 1;

    float acc[4][NJ][4];
#pragma unroll
    for (int mi = 0; mi < 4; mi++)
#pragma unroll
        for (int nj = 0; nj < NJ; nj++)
#pragma unroll
            for (int q = 0; q < 4; q++) acc[mi][nj][q] = 0.0f;

    // prologue: chunks 0..NST-2
#pragma unroll
    for (int p = 0; p < NST - 1; p++) {
        load_ab<TBM_, A_TILE_>(sb + p * STAGE_, Ahi, Bhi, K, row0, col0, p * TBK, tid);
        CP_COMMIT();
    }

    for (int c = 0; c < nchunks; c++) {
        if (c == nchunks - 1) CP_WAIT(0); else CP_WAIT(NST - 2);
        __syncthreads();

        const int nxt = c + NST - 1;
        if (nxt < nchunks) {
            load_ab<TBM_, A_TILE_>(sb + (nxt % NST) * STAGE_, Ahi, Bhi,
                                   K, row0, col0, nxt * TBK, tid);
            CP_COMMIT();
        }

        const uint32_t sA = sb + (c % NST) * STAGE_;
        const uint32_t sB = sA + A_TILE_;

#pragma unroll
        for (int s = 0; s < 4; s++) {
            uint32_t ah[4][4], bh[PB][4];
#pragma unroll
            for (int mi = 0; mi < 4; mi++) {
                int r = wm * 64 + mi * 16 + arow;
                LDSM4(ah[mi], sA + swz(r, 2 * s + acsel));
            }
#pragma unroll
            for (int p = 0; p < PB; p++) {
                int r = wn * WNT + p * 16 + brow;
                LDSM4(bh[p], sB + swz(r, 2 * s + bcsel));
            }
#pragma unroll
            for (int mi = 0; mi < 4; mi++)
#pragma unroll
                for (int nj = 0; nj < NJ; nj++)
                    mma16816(acc[mi][nj], ah[mi], bh[nj >> 1][(nj & 1) * 2], bh[nj >> 1][(nj & 1) * 2 + 1]);
        }
    }

    // -------- epilogue --------
    const int g_ = lane >> 2, t = lane & 3;
    float psum[NJ][2];
    if (EPI == 2) {
#pragma unroll
        for (int nj = 0; nj < NJ; nj++) { psum[nj][0] = 0.0f; psum[nj][1] = 0.0f; }
    }
#pragma unroll
    for (int mi = 0; mi < 4; mi++) {
#pragma unroll
        for (int nj = 0; nj < NJ; nj++) {
            int row = row0 + wm * 64 + mi * 16 + g_;
            int col = col0 + wn * WNT + nj * 8 + 2 * t;
            size_t i0 = (size_t)row * N + col;
            size_t i1 = (size_t)(row + 8) * N + col;
            float* z = acc[mi][nj];
            if (EPI == 0) {
                float b0 = bias[col], b1 = bias[col + 1];
                *(float2*)(C + i0) = make_float2(z[0] + b0, z[1] + b1);
                *(float2*)(C + i1) = make_float2(z[2] + b0, z[3] + b1);
            } else if (EPI == 1) {
                float b0 = bias[col], b1 = bias[col + 1];
                float v0 = fmaxf(z[0] + b0, 0.0f), v1 = fmaxf(z[1] + b1, 0.0f);
                float v2 = fmaxf(z[2] + b0, 0.0f), v3 = fmaxf(z[3] + b1, 0.0f);
                *(__half2*)(Ohi + i0) = __halves2half2(__float2half(v0), __float2half(v1));
                *(__half2*)(Ohi + i1) = __halves2half2(__float2half(v2), __float2half(v3));
            } else if (EPI == 2) {
                float b0 = bias[col], b1 = bias[col + 1];
                float g0 = 1.0f / (1.0f + __expf(-(z[0] + b0)));
                float g1 = 1.0f / (1.0f + __expf(-(z[1] + b1)));
                float g2 = 1.0f / (1.0f + __expf(-(z[2] + b0)));
                float g3 = 1.0f / (1.0f + __expf(-(z[3] + b1)));
                float2 u0 = *(float2*)(C + i0), u1 = *(float2*)(C + i1);
                *(float2*)(gbuf + i0) = make_float2(g0, g1);
                *(float2*)(gbuf + i1) = make_float2(g2, g3);
                psum[nj][0] += u0.x * g0 + u1.x * g2;
                psum[nj][1] += u0.y * g1 + u1.y * g3;
            } else {  // EPI == 3: out = conv3(x) + z
                int l0 = row & (LL - 1);
                int l1 = l0 + 8;
                float w0a = cw[3 * col + 0], w1a = cw[3 * col + 1], w2a = cw[3 * col + 2];
                float w0b = cw[3 * col + 3], w1b = cw[3 * col + 4], w2b = cw[3 * col + 5];
                float cb0 = cb[col], cb1 = cb[col + 1];
                const float* xr0 = xp + i0;
                const float* xr1 = xp + i1;
                float2 xc0 = *(const float2*)xr0;
                float2 xc1 = *(const float2*)xr1;
                float2 xq0 = *(const float2*)(xr0 + N);
                float2 xm1 = *(const float2*)(xr1 - N);
                float2 xm0 = (l0 > 0)      ? *(const float2*)(xr0 - N) : make_float2(0.f, 0.f);
                float2 xq1 = (l1 < LL - 1) ? *(const float2*)(xr1 + N) : make_float2(0.f, 0.f);
                float o0 = cb0 + w1a * xc0.x + w2a * xq0.x + z[0] + (l0 > 0 ? w0a * xm0.x : 0.f);
                float o1 = cb1 + w1b * xc0.y + w2b * xq0.y + z[1] + (l0 > 0 ? w0b * xm0.y : 0.f);
                float o2 = cb0 + w1a * xc1.x + w0a * xm1.x + z[2] + (l1 < LL - 1 ? w2a * xq1.x : 0.f);
                float o3 = cb1 + w1b * xc1.y + w0b * xm1.y + z[3] + (l1 < LL - 1 ? w2b * xq1.y : 0.f);
                *(float2*)(C + i0) = make_float2(o0, o1);
                *(float2*)(C + i1) = make_float2(o2, o3);
            }
        }
    }

    if (EPI == 2) {
        constexpr int NWM = 8 / NWN;     // warps along m (64 rows each)
#pragma unroll
        for (int nj = 0; nj < NJ; nj++) {
#pragma unroll
            for (int k = 0; k < 2; k++) {
                float v = psum[nj][k];
                v += __shfl_xor_sync(0xffffffffu, v, 4);
                v += __shfl_xor_sync(0xffffffffu, v, 8);
                v += __shfl_xor_sync(0xffffffffu, v, 16);
                psum[nj][k] = v;
            }
        }
        __syncthreads();
        float* red = (float*)smem;       // [NWM wm][128 cols]
        if (lane < 4) {
#pragma unroll
            for (int nj = 0; nj < NJ; nj++) {
                red[wm * 128 + wn * WNT + nj * 8 + 2 * lane + 0] = psum[nj][0];
                red[wm * 128 + wn * WNT + nj * 8 + 2 * lane + 1] = psum[nj][1];
            }
        }
        __syncthreads();
        {
            int ch = tid >> 7, cl = tid & 127;   // chunk-within-CTA, column
            if (ch < TBM_ / 128) {
                float s = red[(2 * ch) * 128 + cl] + red[(2 * ch + 1) * 128 + cl];
                int bidx = row0 >> 11;
                int cbase = (row0 & (LL - 1)) >> 7;
                part[((size_t)bidx * NCH + cbase + ch) * (size_t)N + col0 + cl] = s;
            }
        }
    }
}

// ---------------------------------------------------------------------------
// elementwise kernels
// ---------------------------------------------------------------------------
__device__ __forceinline__ uint32_t pack_h(float a, float b) {
    __half2 h = __halves2half2(__float2half(a), __float2half(b));
    return *(uint32_t*)&h;
}

__global__ void split_kernel(const float* __restrict__ s, __half* __restrict__ hi, size_t n) {
    size_t i = ((size_t)blockIdx.x * blockDim.x + threadIdx.x) * 8;
    if (i >= n) return;
    float4 a = *(const float4*)(s + i);
    float4 b = *(const float4*)(s + i + 4);
    uint4 h;
    h.x = pack_h(a.x, a.y); h.y = pack_h(a.z, a.w);
    h.z = pack_h(b.x, b.y); h.w = pack_h(b.z, b.w);
    *(uint4*)(hi + i) = h;
}

__global__ void scanB_kernel(float* __restrict__ part) {
    int tid = blockIdx.x * blockDim.x + threadIdx.x;
    if (tid >= BB * RR) return;
    int r = tid % RR;
    int b = tid / RR;
    float run = 0.0f;
    for (int c = 0; c < NCH; c++) {
        size_t idx = ((size_t)b * NCH + c) * RR + r;
        float t = part[idx];
        part[idx] = run;
        run += t;
    }
}

__global__ void scanC_kernel(const float* __restrict__ u, const float* __restrict__ v,
                             const float* __restrict__ g, const float* __restrict__ part,
                             __half* __restrict__ ghi) {
    int tid = blockIdx.x * blockDim.x + threadIdx.x;
    if (tid >= BB * NCH * RR) return;
    int r = tid % RR;
    int c = (tid / RR) % NCH;
    int b = tid / (RR * NCH);
    float acc = part[((size_t)b * NCH + c) * RR + r];
    size_t base = ((size_t)b * LL + c * CHL) * RR + r;
    for (int l = 0; l < CHL; l++) {
        size_t idx = base + (size_t)l * RR;
        float gg = g[idx];
        acc += u[idx] * gg;
        ghi[idx] = __float2half(acc * (v[idx] * gg));
    }
}

// ---------------------------------------------------------------------------
extern "C" void kernel_launch(void* const* d_in, const int* in_sizes, int n_in,
                              void* d_out, int out_size) {
    const float* x      = (const float*)d_in[0];
    const float* Wu     = (const float*)d_in[1];
    const float* bu     = (const float*)d_in[2];
    const float* Wv     = (const float*)d_in[3];
    const float* bv     = (const float*)d_in[4];
    const float* Wg1    = (const float*)d_in[5];
    const float* bg1    = (const float*)d_in[6];
    const float* Wg2    = (const float*)d_in[7];
    const float* bg2    = (const float*)d_in[8];
    const float* conv_w = (const float*)d_in[9];
    const float* conv_b = (const float*)d_in[10];
    float* out = (float*)d_out;

    __half *xhi, *wuhi, *wvhi, *wg1hi, *wg2hi, *hhi, *ghi;
    float *pu, *pv, *pg, *ppart;
    cudaGetSymbolAddress((void**)&xhi, g_xhi);
    cudaGetSymbolAddress((void**)&wuhi, g_wuhi);
    cudaGetSymbolAddress((void**)&wvhi, g_wvhi);
    cudaGetSymbolAddress((void**)&wg1hi, g_wg1hi);
    cudaGetSymbolAddress((void**)&wg2hi, g_wg2hi);
    cudaGetSymbolAddress((void**)&hhi, g_hhi);
    cudaGetSymbolAddress((void**)&ghi, g_ghi);
    cudaGetSymbolAddress((void**)&pu, g_u);        cudaGetSymbolAddress((void**)&pv, g_v);
    cudaGetSymbolAddress((void**)&pg, g_g);        cudaGetSymbolAddress((void**)&ppart, g_part);

    // dual / uv: NWN=4, 3 stages -> 3*32KB = 98304/CTA, 2 CTAs/SM
    cudaFuncSetAttribute(bsgemm<0,true,4,2,3>,  cudaFuncAttributeMaxDynamicSharedMemorySize, 98304);
    // h: NWN=2 (grid 128 < 148, single wave), 2 stages -> 2*48KB
    cudaFuncSetAttribute(bsgemm<1,false,2,1,2>, cudaFuncAttributeMaxDynamicSharedMemorySize, 98304);
    // gates: NWN=4, 2 stages -> 2*32KB = 65536/CTA, 2 CTAs/SM
    cudaFuncSetAttribute(bsgemm<2,false,4,2,2>, cudaFuncAttributeMaxDynamicSharedMemorySize, 65536);
    cudaFuncSetAttribute(bsgemm<3,false,4,2,3>, cudaFuncAttributeMaxDynamicSharedMemorySize, 98304);

    // fp16 conversions
    split_kernel<<<(unsigned)((size_t)MM * DD / 8 / 256), 256>>>(x, xhi, (size_t)MM * DD);
    split_kernel<<<(unsigned)((size_t)RR * DD / 8 / 256), 256>>>(Wu, wuhi, (size_t)RR * DD);
    split_kernel<<<(unsigned)((size_t)RR * DD / 8 / 256), 256>>>(Wv, wvhi, (size_t)RR * DD);

    // dual u/v GEMM (1-pass fp16): z=0 -> u (Wu,bu), z=1 -> v (Wv,bv)
    bsgemm<0,true,4,2,3><<<dim3(RR / TBN, MM / 128, 2), 256, 98304>>>(
        xhi, wuhi, bu, pu, nullptr,
        wvhi, bv, pv,
        nullptr, nullptr, nullptr, nullptr, nullptr, MM, RR, DD);

    // gate path (plain fp16, single pass)
    split_kernel<<<(unsigned)((size_t)DHH * DD / 8 / 256), 256>>>(Wg1, wg1hi, (size_t)DHH * DD);
    split_kernel<<<(unsigned)((size_t)RR * DHH / 8 / 256), 256>>>(Wg2, wg2hi, (size_t)RR * DHH);
    // h = relu(x Wg1^T + bg1) -> fp16
    bsgemm<1,false,2,1,2><<<dim3(DHH / TBN, MM / 256), 256, 98304>>>(
        xhi, wg1hi, bg1, nullptr, hhi,
        nullptr, nullptr, nullptr,
        nullptr, nullptr, nullptr, nullptr, nullptr, MM, DHH, DD);
    // gates: write g, fused chunk partial sums of u*g -> part (NWN=4, 2 CTAs/SM)
    bsgemm<2,false,4,2,2><<<dim3(RR / TBN, MM / 128), 256, 65536>>>(
        hhi, wg2hi, bg2, pu, nullptr,
        nullptr, nullptr, nullptr,
        nullptr, nullptr, nullptr, pg, ppart, MM, RR, DHH);

    // exclusive prefix over chunks, then apply gates + cumsum + multiply -> fp16
    scanB_kernel<<<(BB * RR + 255) / 256, 256>>>(ppart);
    scanC_kernel<<<(BB * NCH * RR + 255) / 256, 256>>>(pu, pv, pg, ppart, ghi);

    // out = conv3(x) + global_out @ Wu   (1-pass fp16)
    bsgemm<3,false,4,2,3><<<dim3(DD / TBN, MM / 128), 256, 98304>>>(
        ghi, wuhi, nullptr, out, nullptr,
        nullptr, nullptr, nullptr,
        conv_w, conv_b, x, nullptr, nullptr, MM, DD, RR);
}